// round 1
// baseline (speedup 1.0000x reference)
#include <cuda_runtime.h>

// ---------------------------------------------------------------------------
// BiLevelRoutingAttention, B=1, H=W=112, DIM=QK=256, HEADS=8, NWIN=7, TOPK=4
// Window grid: 7x7 = 49 windows, each 16x16 = 256 pixels. 12544 rows total.
// qkv cols: [0,256) = q, [256,512) = k, [512,768) = v
// ---------------------------------------------------------------------------

#define P2     49
#define W2     256
#define MROWS  (P2 * W2)     // 12544
#define NQKV   768
#define KDIM   256
#define IMG    112
#define SCALE  0.0625f       // 256^-0.5

// Scratch (device globals: allowed; runtime allocation is not)
__device__ float g_qkv [MROWS * NQKV];   // window-layout qkv rows
__device__ float g_qwin[P2 * 256];
__device__ float g_kwin[P2 * 256];
__device__ float g_logit[P2 * P2];
__device__ int   g_top [P2 * 4];
__device__ float g_y   [IMG * IMG * 256]; // attn-out + lepe, image layout

// ---------------------------------------------------------------------------
// Tiled fp32 GEMM: 64x64 block tile, BK=16, 256 threads, 4x4 microtile.
// MODE 0: A = x (gathered window rows), C = g_qkv   (N = 768)
// MODE 1: A = g_y (image rows),         C = d_out   (N = 256)
// All dims divide evenly: no bounds checks.
// ---------------------------------------------------------------------------
template <int MODE>
__global__ __launch_bounds__(256) void gemm_k(const float* __restrict__ A,
                                              const float* __restrict__ B,
                                              const float* __restrict__ bias,
                                              float* __restrict__ C, int N) {
    __shared__ __align__(16) float As[16][68];   // [k][m], padded
    __shared__ __align__(16) float Bs[16][64];   // [k][n]

    const int tid = threadIdx.x;
    const int tx  = tid & 15;
    const int ty  = tid >> 4;
    const int m0  = blockIdx.y * 64;
    const int n0  = blockIdx.x * 64;

    const float* Abase = (MODE == 0) ? A : g_y;
    float*       Cbase = (MODE == 0) ? g_qkv : C;

    // A load: each thread one float4 per k-tile. row = tid>>2, k offset = (tid&3)*4
    const int arow = tid >> 2;
    const int ak4  = (tid & 3) * 4;
    const int m    = m0 + arow;
    const float* Arow;
    if (MODE == 0) {
        const int p = m >> 8, pix = m & 255;
        const int wy = p / 7, wx = p % 7;
        const int gy = wy * 16 + (pix >> 4);
        const int gx = wx * 16 + (pix & 15);
        Arow = Abase + (gy * IMG + gx) * KDIM;
    } else {
        Arow = Abase + m * KDIM;
    }

    const int brow = tid >> 4;        // 0..15
    const int bn4  = (tid & 15) * 4;  // 0..60

    float acc[4][4];
#pragma unroll
    for (int i = 0; i < 4; i++)
#pragma unroll
        for (int j = 0; j < 4; j++) acc[i][j] = 0.f;

    for (int k0 = 0; k0 < KDIM; k0 += 16) {
        const float4 av = *(const float4*)(Arow + k0 + ak4);
        const float4 bv = *(const float4*)(B + (k0 + brow) * N + n0 + bn4);
        __syncthreads();
        As[ak4 + 0][arow] = av.x;
        As[ak4 + 1][arow] = av.y;
        As[ak4 + 2][arow] = av.z;
        As[ak4 + 3][arow] = av.w;
        *(float4*)&Bs[brow][bn4] = bv;
        __syncthreads();
#pragma unroll
        for (int kk = 0; kk < 16; kk++) {
            const float4 a = *(const float4*)&As[kk][ty * 4];
            const float4 b = *(const float4*)&Bs[kk][tx * 4];
            const float ar[4] = {a.x, a.y, a.z, a.w};
            const float br[4] = {b.x, b.y, b.z, b.w};
#pragma unroll
            for (int i = 0; i < 4; i++)
#pragma unroll
                for (int j = 0; j < 4; j++) acc[i][j] += ar[i] * br[j];
        }
    }

#pragma unroll
    for (int i = 0; i < 4; i++) {
        const int mm = m0 + ty * 4 + i;
        const int nn = n0 + tx * 4;
        float4 o;
        o.x = acc[i][0] + bias[nn + 0];
        o.y = acc[i][1] + bias[nn + 1];
        o.z = acc[i][2] + bias[nn + 2];
        o.w = acc[i][3] + bias[nn + 3];
        *(float4*)(Cbase + (size_t)mm * N + nn) = o;
    }
}

// ---------------------------------------------------------------------------
// Per-window means of q and k over the 256 pixels. grid=49, block=256.
// ---------------------------------------------------------------------------
__global__ __launch_bounds__(256) void means_k() {
    const int p = blockIdx.x;
    const int c = threadIdx.x;
    const float* base = g_qkv + (size_t)p * W2 * NQKV;
    float sq = 0.f, sk = 0.f;
    for (int pix = 0; pix < W2; pix++) {
        sq += base[pix * NQKV + c];
        sk += base[pix * NQKV + 256 + c];
    }
    g_qwin[p * 256 + c] = sq * (1.f / 256.f);
    g_kwin[p * 256 + c] = sk * (1.f / 256.f);
}

// ---------------------------------------------------------------------------
// Routing logits: 49x49 dots of length 256. One thread per (p,j).
// ---------------------------------------------------------------------------
__global__ __launch_bounds__(256) void logit_k() {
    const int t = blockIdx.x * 256 + threadIdx.x;
    if (t >= P2 * P2) return;
    const int p = t / P2, j = t % P2;
    const float4* qa = (const float4*)(g_qwin + p * 256);
    const float4* ka = (const float4*)(g_kwin + j * 256);
    float s = 0.f;
#pragma unroll 8
    for (int c = 0; c < 64; c++) {
        const float4 a = qa[c], b = ka[c];
        s += a.x * b.x + a.y * b.y + a.z * b.z + a.w * b.w;
    }
    g_logit[t] = s * SCALE;
}

// Top-4 per row (stable: strict >, earlier index wins ties like lax.top_k).
__global__ void topk_k() {
    const int p = threadIdx.x;
    if (p >= P2) return;
    float bv0 = -1e30f, bv1 = -1e30f, bv2 = -1e30f, bv3 = -1e30f;
    int   bi0 = 0, bi1 = 0, bi2 = 0, bi3 = 0;
    for (int j = 0; j < P2; j++) {
        const float s = g_logit[p * P2 + j];
        if (s > bv3) {
            if (s > bv0)      { bv3=bv2;bi3=bi2; bv2=bv1;bi2=bi1; bv1=bv0;bi1=bi0; bv0=s;bi0=j; }
            else if (s > bv1) { bv3=bv2;bi3=bi2; bv2=bv1;bi2=bi1; bv1=s;bi1=j; }
            else if (s > bv2) { bv3=bv2;bi3=bi2; bv2=s;bi2=j; }
            else              { bv3=s;bi3=j; }
        }
    }
    g_top[p * 4 + 0] = bi0; g_top[p * 4 + 1] = bi1;
    g_top[p * 4 + 2] = bi2; g_top[p * 4 + 3] = bi3;
}

// ---------------------------------------------------------------------------
// Attention: one block per (window p, head h). 256 threads = 1 thread/query.
// Streams the 4 selected windows' K/V (1024 keys) in 32-key chunks through
// shared memory with online softmax. Writes directly to image layout.
// ---------------------------------------------------------------------------
__global__ __launch_bounds__(256) void attn_k() {
    const int p = blockIdx.x;
    const int h = blockIdx.y;
    const int q = threadIdx.x;

    __shared__ __align__(16) float Ks[32][32];
    __shared__ __align__(16) float Vs[32][32];
    __shared__ int sidx[4];
    if (q < 4) sidx[q] = g_top[p * 4 + q];

    // q vector (pre-scaled)
    const float* qrow = g_qkv + ((size_t)(p * W2 + q)) * NQKV + h * 32;
    float qv[32];
    const float4* q4 = (const float4*)qrow;
#pragma unroll
    for (int i = 0; i < 8; i++) {
        const float4 v = q4[i];
        qv[i * 4 + 0] = v.x * SCALE;
        qv[i * 4 + 1] = v.y * SCALE;
        qv[i * 4 + 2] = v.z * SCALE;
        qv[i * 4 + 3] = v.w * SCALE;
    }

    float mrun = -1e30f, l = 0.f;
    float acc[32];
#pragma unroll
    for (int c = 0; c < 32; c++) acc[c] = 0.f;

    __syncthreads();  // sidx visible

    const int key = q >> 3;
    const int f4  = (q & 7) * 4;

    for (int t = 0; t < 4; t++) {
        const int s = sidx[t];
        const float* kb = g_qkv + (size_t)s * W2 * NQKV + 256 + h * 32;
        const float* vb = kb + 256;
        for (int j0 = 0; j0 < 256; j0 += 32) {
            // prefetch this chunk while previous chunk finishes compute
            const float4 kk4 = *(const float4*)(kb + (j0 + key) * NQKV + f4);
            const float4 vv4 = *(const float4*)(vb + (j0 + key) * NQKV + f4);
            __syncthreads();
            *(float4*)&Ks[key][f4] = kk4;
            *(float4*)&Vs[key][f4] = vv4;
            __syncthreads();

            float sc[32];
#pragma unroll
            for (int j = 0; j < 32; j++) {
                float d = 0.f;
#pragma unroll
                for (int c = 0; c < 32; c++) d += qv[c] * Ks[j][c];
                sc[j] = d;
            }
            float cm = sc[0];
#pragma unroll
            for (int j = 1; j < 32; j++) cm = fmaxf(cm, sc[j]);
            const float mn   = fmaxf(mrun, cm);
            const float corr = __expf(mrun - mn);
            l *= corr;
#pragma unroll
            for (int c = 0; c < 32; c++) acc[c] *= corr;
#pragma unroll
            for (int j = 0; j < 32; j++) {
                const float pj = __expf(sc[j] - mn);
                l += pj;
#pragma unroll
                for (int c = 0; c < 32; c++) acc[c] += pj * Vs[j][c];
            }
            mrun = mn;
        }
    }

    const float inv = 1.f / l;
    const int wy = p / 7, wx = p % 7, iy = q >> 4, ix = q & 15;
    float* o = g_y + ((size_t)((wy * 16 + iy) * IMG + (wx * 16 + ix))) * 256 + h * 32;
#pragma unroll
    for (int c = 0; c < 32; c++) o[c] = acc[c] * inv;
}

// ---------------------------------------------------------------------------
// LePE: depthwise 3x3 SAME conv over v (read from window layout), add into g_y.
// grid = 12544 pixels, block = 256 channels.
// ---------------------------------------------------------------------------
__global__ __launch_bounds__(256) void lepe_k(const float* __restrict__ lw,
                                              const float* __restrict__ lb) {
    const int pix = blockIdx.x;
    const int c   = threadIdx.x;
    const int y = pix / IMG, x = pix % IMG;
    float sum = lb[c];
#pragma unroll
    for (int dy = -1; dy <= 1; dy++) {
        const int yy = y + dy;
        if (yy < 0 || yy >= IMG) continue;
#pragma unroll
        for (int dx = -1; dx <= 1; dx++) {
            const int xx = x + dx;
            if (xx < 0 || xx >= IMG) continue;
            const int p  = (yy >> 4) * 7 + (xx >> 4);
            const int pp = ((yy & 15) << 4) | (xx & 15);
            const float v = g_qkv[((size_t)(p * W2 + pp)) * NQKV + 512 + c];
            sum += v * lw[((dy + 1) * 3 + (dx + 1)) * 256 + c];
        }
    }
    g_y[(size_t)pix * 256 + c] += sum;
}

// ---------------------------------------------------------------------------
extern "C" void kernel_launch(void* const* d_in, const int* in_sizes, int n_in,
                              void* d_out, int out_size) {
    const float* x      = (const float*)d_in[0];
    const float* w_qkv  = (const float*)d_in[1];
    const float* b_qkv  = (const float*)d_in[2];
    const float* w_o    = (const float*)d_in[3];
    const float* b_o    = (const float*)d_in[4];
    const float* lepe_w = (const float*)d_in[5];
    const float* lepe_b = (const float*)d_in[6];
    float* out = (float*)d_out;

    (void)in_sizes; (void)n_in; (void)out_size;

    // 1) qkv = window_partition(x) @ w_qkv + b_qkv   -> g_qkv
    gemm_k<0><<<dim3(NQKV / 64, MROWS / 64), 256>>>(x, w_qkv, b_qkv, nullptr, NQKV);
    // 2) per-window q/k means
    means_k<<<P2, 256>>>();
    // 3) routing logits + top-4
    logit_k<<<(P2 * P2 + 255) / 256, 256>>>();
    topk_k<<<1, 64>>>();
    // 4) attention -> g_y (image layout)
    attn_k<<<dim3(P2, 8), 256>>>();
    // 5) lepe conv added into g_y
    lepe_k<<<IMG * IMG, 256>>>(lepe_w, lepe_b);
    // 6) (attn + lepe) @ w_o + b_o -> out
    gemm_k<1><<<dim3(KDIM / 64, MROWS / 64), 256>>>(nullptr, w_o, b_o, out, KDIM);
}

// round 3
// speedup vs baseline: 1.1411x; 1.1411x over previous
#include <cuda_runtime.h>
#include <cuda_bf16.h>
#include <cstdint>

// ---------------------------------------------------------------------------
// BiLevelRoutingAttention, B=1, H=W=112, DIM=QK=256, HEADS=8, NWIN=7, TOPK=4
// 49 windows x 256 pixels = 12544 rows. qkv cols: [0,256)=q [256,512)=k [512,768)=v
// Dense GEMMs: mma.sync bf16 with hi/lo split folded into K (K_eff = 768).
// ---------------------------------------------------------------------------

#define P2     49
#define W2     256
#define MROWS  12544
#define NQKV   768
#define KDIM   256
#define KEFF   768          // 3 x 256 (hi|hi|lo vs hi|lo|hi)
#define IMG    112
#define SCALE  0.0625f

// Scratch
__device__ float g_qkv [MROWS * NQKV];
__device__ float g_qwin[P2 * 256];
__device__ float g_kwin[P2 * 256];
__device__ float g_logit[P2 * P2];
__device__ int   g_top [P2 * 4];
__device__ float g_y   [MROWS * 256];              // attn out, image-row order
__device__ __nv_bfloat16 g_Ap[MROWS * KEFF];       // x gathered, split-packed
__device__ __nv_bfloat16 g_Yp[MROWS * KEFF];       // attn+lepe, split-packed
__device__ __nv_bfloat16 g_Bq[NQKV * KEFF];        // w_qkv^T split-packed
__device__ __nv_bfloat16 g_Bo[KDIM * KEFF];        // w_o^T split-packed

__device__ __forceinline__ uint32_t smem_u32(const void* p) {
    uint32_t a;
    asm("{ .reg .u64 t; cvta.to.shared.u64 t, %1; cvt.u32.u64 %0, t; }" : "=r"(a) : "l"(p));
    return a;
}

// ---------------------------------------------------------------------------
// Prep: weights -> transposed, bf16 hi/lo split-packed rows of KEFF
// layout per row n: [0,256)=hi  [256,512)=lo  [512,768)=hi
// ---------------------------------------------------------------------------
__global__ __launch_bounds__(256) void prep_w(const float* __restrict__ wq,
                                              const float* __restrict__ wo) {
    const int t = blockIdx.x * 256 + threadIdx.x;   // n*256 + k
    const int n = t >> 8, k = t & 255;
    if (t < NQKV * KDIM) {
        const float v = wq[k * NQKV + n];
        const __nv_bfloat16 h = __float2bfloat16(v);
        const __nv_bfloat16 l = __float2bfloat16(v - __bfloat162float(h));
        g_Bq[n * KEFF + k]       = h;
        g_Bq[n * KEFF + 256 + k] = l;
        g_Bq[n * KEFF + 512 + k] = h;
    }
    if (t < KDIM * KDIM) {
        const float v = wo[k * KDIM + n];
        const __nv_bfloat16 h = __float2bfloat16(v);
        const __nv_bfloat16 l = __float2bfloat16(v - __bfloat162float(h));
        g_Bo[n * KEFF + k]       = h;
        g_Bo[n * KEFF + 256 + k] = l;
        g_Bo[n * KEFF + 512 + k] = h;
    }
}

// Prep: gather x window-row order, split-pack: [0,256)=hi [256,512)=hi [512,768)=lo
__global__ __launch_bounds__(256) void prep_a(const float* __restrict__ x) {
    const int m = blockIdx.x, c = threadIdx.x;
    const int p = m >> 8, pix = m & 255;
    const int gy = (p / 7) * 16 + (pix >> 4);
    const int gx = (p % 7) * 16 + (pix & 15);
    const float v = x[(gy * IMG + gx) * KDIM + c];
    const __nv_bfloat16 h = __float2bfloat16(v);
    const __nv_bfloat16 l = __float2bfloat16(v - __bfloat162float(h));
    g_Ap[m * KEFF + c]       = h;
    g_Ap[m * KEFF + 256 + c] = h;
    g_Ap[m * KEFF + 512 + c] = l;
}

// ---------------------------------------------------------------------------
// mma.sync bf16 GEMM: C[M x N] = A'[M x 768] * B'^T + bias
// Tile: BM=128, BN=128, BK=64. 8 warps (4m x 2n), warp tile 32x64.
// SMEM rows of 64 bf16 = 128B, SW128 swizzle (chunk ^ (row&7)).
// MODE 0: A=g_Ap B=g_Bq C=g_qkv (N=768)   MODE 1: A=g_Yp B=g_Bo C=out (N=256)
// ---------------------------------------------------------------------------
__device__ __forceinline__ void ldsm_x4(uint32_t& r0, uint32_t& r1, uint32_t& r2, uint32_t& r3, uint32_t a) {
    asm volatile("ldmatrix.sync.aligned.m8n8.x4.shared.b16 {%0,%1,%2,%3}, [%4];"
                 : "=r"(r0), "=r"(r1), "=r"(r2), "=r"(r3) : "r"(a));
}
__device__ __forceinline__ void mma16816(float* c, const uint32_t* a, const uint32_t* b) {
    asm volatile(
        "mma.sync.aligned.m16n8k16.row.col.f32.bf16.bf16.f32 "
        "{%0,%1,%2,%3}, {%4,%5,%6,%7}, {%8,%9}, {%0,%1,%2,%3};"
        : "+f"(c[0]), "+f"(c[1]), "+f"(c[2]), "+f"(c[3])
        : "r"(a[0]), "r"(a[1]), "r"(a[2]), "r"(a[3]), "r"(b[0]), "r"(b[1]));
}

template <int MODE>
__global__ __launch_bounds__(256) void gemm_mma(const float* __restrict__ bias,
                                                float* __restrict__ Cout) {
    constexpr int N = (MODE == 0) ? NQKV : KDIM;
    __shared__ __align__(128) __nv_bfloat16 As[128 * 64];
    __shared__ __align__(128) __nv_bfloat16 Bs[128 * 64];

    const __nv_bfloat16* A = (MODE == 0) ? g_Ap : g_Yp;
    const __nv_bfloat16* B = (MODE == 0) ? g_Bq : g_Bo;
    float* C = (MODE == 0) ? g_qkv : Cout;

    const int tid  = threadIdx.x;
    const int wid  = tid >> 5;
    const int lane = tid & 31;
    const int m0   = blockIdx.y * 128;
    const int n0   = blockIdx.x * 128;
    const int mw   = (wid >> 1) * 32;   // warp m offset in tile
    const int nw   = (wid & 1) * 64;    // warp n offset in tile

    const uint32_t sA = smem_u32(As), sB = smem_u32(Bs);

    // global->smem: 4 uint4 each for A and B per iter. idx: row = idx>>3, chunk = idx&7
    const int lrow = tid >> 1;                 // wrong granularity fix below
    (void)lrow;
    uint4 pa[4], pb[4];
    int grow[4], gchk[4];
#pragma unroll
    for (int i = 0; i < 4; i++) {
        const int idx = tid + 256 * i;         // 0..1023
        grow[i] = idx >> 3;                    // 0..127
        gchk[i] = idx & 7;                     // 0..7
    }

    // prefetch iter 0
#pragma unroll
    for (int i = 0; i < 4; i++) {
        pa[i] = *(const uint4*)(A + (size_t)(m0 + grow[i]) * KEFF + gchk[i] * 8);
        pb[i] = *(const uint4*)(B + (size_t)(n0 + grow[i]) * KEFF + gchk[i] * 8);
    }

    float acc[2][8][4];
#pragma unroll
    for (int mt = 0; mt < 2; mt++)
#pragma unroll
        for (int nt = 0; nt < 8; nt++)
#pragma unroll
            for (int j = 0; j < 4; j++) acc[mt][nt][j] = 0.f;

    for (int kt = 0; kt < KEFF / 64; kt++) {
#pragma unroll
        for (int i = 0; i < 4; i++) {
            const int so = grow[i] * 128 + ((gchk[i] ^ (grow[i] & 7)) * 16);
            *(uint4*)((char*)As + so) = pa[i];
            *(uint4*)((char*)Bs + so) = pb[i];
        }
        __syncthreads();
        if (kt + 1 < KEFF / 64) {
            const int k0 = (kt + 1) * 64;
#pragma unroll
            for (int i = 0; i < 4; i++) {
                pa[i] = *(const uint4*)(A + (size_t)(m0 + grow[i]) * KEFF + k0 + gchk[i] * 8);
                pb[i] = *(const uint4*)(B + (size_t)(n0 + grow[i]) * KEFF + k0 + gchk[i] * 8);
            }
        }

#pragma unroll
        for (int ks = 0; ks < 4; ks++) {
            // A frags: 2 m16-tiles
            uint32_t aF[2][4];
#pragma unroll
            for (int mt = 0; mt < 2; mt++) {
                const int row = mw + mt * 16 + (lane & 15);
                const int chk = ks * 2 + (lane >> 4);
                ldsm_x4(aF[mt][0], aF[mt][1], aF[mt][2], aF[mt][3],
                        sA + row * 128 + ((chk ^ (row & 7)) * 16));
            }
            // B frags: 4 x4-loads covering 8 n8-tiles
            uint32_t bF[8][2];
#pragma unroll
            for (int np = 0; np < 4; np++) {
                const int row = nw + np * 16 + (lane & 7) + ((lane >> 4) << 3);
                const int chk = ks * 2 + ((lane >> 3) & 1);
                uint32_t r0, r1, r2, r3;
                ldsm_x4(r0, r1, r2, r3, sB + row * 128 + ((chk ^ (row & 7)) * 16));
                bF[np * 2][0] = r0; bF[np * 2][1] = r1;
                bF[np * 2 + 1][0] = r2; bF[np * 2 + 1][1] = r3;
            }
#pragma unroll
            for (int mt = 0; mt < 2; mt++)
#pragma unroll
                for (int nt = 0; nt < 8; nt++)
                    mma16816(acc[mt][nt], aF[mt], bF[nt]);
        }
        __syncthreads();
    }

    // epilogue
    const int r0 = lane >> 2, c0 = (lane & 3) * 2;
#pragma unroll
    for (int mt = 0; mt < 2; mt++) {
#pragma unroll
        for (int nt = 0; nt < 8; nt++) {
            const int col = n0 + nw + nt * 8 + c0;
            const float bx = bias[col], by = bias[col + 1];
            const int rowa = m0 + mw + mt * 16 + r0;
            float2 v0 = {acc[mt][nt][0] + bx, acc[mt][nt][1] + by};
            float2 v1 = {acc[mt][nt][2] + bx, acc[mt][nt][3] + by};
            *(float2*)(C + (size_t)rowa * N + col)       = v0;
            *(float2*)(C + (size_t)(rowa + 8) * N + col) = v1;
        }
    }
}

// ---------------------------------------------------------------------------
// Per-window means of q and k
// ---------------------------------------------------------------------------
__global__ __launch_bounds__(256) void means_k() {
    const int p = blockIdx.x, c = threadIdx.x;
    const float* base = g_qkv + (size_t)p * W2 * NQKV;
    float sq = 0.f, sk = 0.f;
    for (int pix = 0; pix < W2; pix++) {
        sq += base[pix * NQKV + c];
        sk += base[pix * NQKV + 256 + c];
    }
    g_qwin[p * 256 + c] = sq * (1.f / 256.f);
    g_kwin[p * 256 + c] = sk * (1.f / 256.f);
}

__global__ __launch_bounds__(256) void logit_k() {
    const int t = blockIdx.x * 256 + threadIdx.x;
    if (t >= P2 * P2) return;
    const int p = t / P2, j = t % P2;
    const float4* qa = (const float4*)(g_qwin + p * 256);
    const float4* ka = (const float4*)(g_kwin + j * 256);
    float s = 0.f;
#pragma unroll 8
    for (int c = 0; c < 64; c++) {
        const float4 a = qa[c], b = ka[c];
        s += a.x * b.x + a.y * b.y + a.z * b.z + a.w * b.w;
    }
    g_logit[t] = s * SCALE;
}

__global__ void topk_k() {
    const int p = threadIdx.x;
    if (p >= P2) return;
    float bv0 = -1e30f, bv1 = -1e30f, bv2 = -1e30f, bv3 = -1e30f;
    int   bi0 = 0, bi1 = 0, bi2 = 0, bi3 = 0;
    for (int j = 0; j < P2; j++) {
        const float s = g_logit[p * P2 + j];
        if (s > bv3) {
            if (s > bv0)      { bv3=bv2;bi3=bi2; bv2=bv1;bi2=bi1; bv1=bv0;bi1=bi0; bv0=s;bi0=j; }
            else if (s > bv1) { bv3=bv2;bi3=bi2; bv2=bv1;bi2=bi1; bv1=s;bi1=j; }
            else if (s > bv2) { bv3=bv2;bi3=bi2; bv2=s;bi2=j; }
            else              { bv3=s;bi3=j; }
        }
    }
    g_top[p * 4 + 0] = bi0; g_top[p * 4 + 1] = bi1;
    g_top[p * 4 + 2] = bi2; g_top[p * 4 + 3] = bi3;
}

// ---------------------------------------------------------------------------
// Attention: one block per (window, head), 256 threads = 1 thread/query. fp32.
// ---------------------------------------------------------------------------
__global__ __launch_bounds__(256) void attn_k() {
    const int p = blockIdx.x;
    const int h = blockIdx.y;
    const int q = threadIdx.x;

    __shared__ __align__(16) float Ks[32][32];
    __shared__ __align__(16) float Vs[32][32];
    __shared__ int sidx[4];
    if (q < 4) sidx[q] = g_top[p * 4 + q];

    const float* qrow = g_qkv + ((size_t)(p * W2 + q)) * NQKV + h * 32;
    float qv[32];
    const float4* q4 = (const float4*)qrow;
#pragma unroll
    for (int i = 0; i < 8; i++) {
        const float4 v = q4[i];
        qv[i * 4 + 0] = v.x * SCALE;
        qv[i * 4 + 1] = v.y * SCALE;
        qv[i * 4 + 2] = v.z * SCALE;
        qv[i * 4 + 3] = v.w * SCALE;
    }

    float mrun = -1e30f, l = 0.f;
    float acc[32];
#pragma unroll
    for (int c = 0; c < 32; c++) acc[c] = 0.f;

    __syncthreads();

    const int key = q >> 3;
    const int f4  = (q & 7) * 4;

    for (int t = 0; t < 4; t++) {
        const int s = sidx[t];
        const float* kb = g_qkv + (size_t)s * W2 * NQKV + 256 + h * 32;
        const float* vb = kb + 256;
        for (int j0 = 0; j0 < 256; j0 += 32) {
            const float4 kk4 = *(const float4*)(kb + (j0 + key) * NQKV + f4);
            const float4 vv4 = *(const float4*)(vb + (j0 + key) * NQKV + f4);
            __syncthreads();
            *(float4*)&Ks[key][f4] = kk4;
            *(float4*)&Vs[key][f4] = vv4;
            __syncthreads();

            float sc[32];
#pragma unroll
            for (int j = 0; j < 32; j++) {
                float d = 0.f;
#pragma unroll
                for (int c = 0; c < 32; c++) d += qv[c] * Ks[j][c];
                sc[j] = d;
            }
            float cm = sc[0];
#pragma unroll
            for (int j = 1; j < 32; j++) cm = fmaxf(cm, sc[j]);
            const float mn   = fmaxf(mrun, cm);
            const float corr = __expf(mrun - mn);
            l *= corr;
#pragma unroll
            for (int c = 0; c < 32; c++) acc[c] *= corr;
#pragma unroll
            for (int j = 0; j < 32; j++) {
                const float pj = __expf(sc[j] - mn);
                l += pj;
#pragma unroll
                for (int c = 0; c < 32; c++) acc[c] += pj * Vs[j][c];
            }
            mrun = mn;
        }
    }

    const float inv = 1.f / l;
    const int wy = p / 7, wx = p % 7, iy = q >> 4, ix = q & 15;
    float* o = g_y + ((size_t)((wy * 16 + iy) * IMG + (wx * 16 + ix))) * 256 + h * 32;
#pragma unroll
    for (int c = 0; c < 32; c++) o[c] = acc[c] * inv;
}

// ---------------------------------------------------------------------------
// LePE depthwise 3x3 + add attention output; emit split-packed rows for out-gemm.
// ---------------------------------------------------------------------------
__global__ __launch_bounds__(256) void lepe_k(const float* __restrict__ lw,
                                              const float* __restrict__ lb) {
    const int pix = blockIdx.x;
    const int c   = threadIdx.x;
    const int y = pix / IMG, x = pix % IMG;
    float sum = lb[c];
#pragma unroll
    for (int dy = -1; dy <= 1; dy++) {
        const int yy = y + dy;
        if (yy < 0 || yy >= IMG) continue;
#pragma unroll
        for (int dx = -1; dx <= 1; dx++) {
            const int xx = x + dx;
            if (xx < 0 || xx >= IMG) continue;
            const int p  = (yy >> 4) * 7 + (xx >> 4);
            const int pp = ((yy & 15) << 4) | (xx & 15);
            const float v = g_qkv[((size_t)(p * W2 + pp)) * NQKV + 512 + c];
            sum += v * lw[((dy + 1) * 3 + (dx + 1)) * 256 + c];
        }
    }
    const float tot = g_y[(size_t)pix * 256 + c] + sum;
    const __nv_bfloat16 h = __float2bfloat16(tot);
    const __nv_bfloat16 l = __float2bfloat16(tot - __bfloat162float(h));
    g_Yp[(size_t)pix * KEFF + c]       = h;
    g_Yp[(size_t)pix * KEFF + 256 + c] = h;
    g_Yp[(size_t)pix * KEFF + 512 + c] = l;
}

// ---------------------------------------------------------------------------
extern "C" void kernel_launch(void* const* d_in, const int* in_sizes, int n_in,
                              void* d_out, int out_size) {
    const float* x      = (const float*)d_in[0];
    const float* w_qkv  = (const float*)d_in[1];
    const float* b_qkv  = (const float*)d_in[2];
    const float* w_o    = (const float*)d_in[3];
    const float* b_o    = (const float*)d_in[4];
    const float* lepe_w = (const float*)d_in[5];
    const float* lepe_b = (const float*)d_in[6];
    float* out = (float*)d_out;
    (void)in_sizes; (void)n_in; (void)out_size;

    prep_w<<<(NQKV * KDIM + 255) / 256, 256>>>(w_qkv, w_o);
    prep_a<<<MROWS, 256>>>(x);
    gemm_mma<0><<<dim3(NQKV / 128, MROWS / 128), 256>>>(b_qkv, nullptr);
    means_k<<<P2, 256>>>();
    logit_k<<<(P2 * P2 + 255) / 256, 256>>>();
    topk_k<<<1, 64>>>();
    attn_k<<<dim3(P2, 8), 256>>>();
    lepe_k<<<IMG * IMG, 256>>>(lepe_w, lepe_b);
    gemm_mma<1><<<dim3(KDIM / 128, MROWS / 128), 256>>>(b_o, out);
}

// round 4
// speedup vs baseline: 2.1422x; 1.8773x over previous
#include <cuda_runtime.h>
#include <cuda_bf16.h>
#include <cstdint>

// ---------------------------------------------------------------------------
// BiLevelRoutingAttention, B=1, H=W=112, DIM=QK=256, HEADS=8, NWIN=7, TOPK=4
// GEMMs + attention on mma.sync bf16 with hi/lo split (fp32-grade accuracy).
// ---------------------------------------------------------------------------

#define P2     49
#define W2     256
#define MROWS  12544
#define NQKV   768
#define KDIM   256
#define KEFF   768
#define IMG    112
#define SCALE  0.0625f

__device__ float g_qkv [MROWS * NQKV];
__device__ float g_qwin[P2 * 256];
__device__ float g_kwin[P2 * 256];
__device__ float g_part[8][P2][512];
__device__ float g_logit[P2 * P2];
__device__ int   g_top [P2 * 4];
__device__ float g_y   [MROWS * 256];              // attn out, image-row order
__device__ __nv_bfloat16 g_Ap[MROWS * KEFF];
__device__ __nv_bfloat16 g_Yp[MROWS * KEFF];
__device__ __nv_bfloat16 g_Bq[NQKV * KEFF];
__device__ __nv_bfloat16 g_Bo[KDIM * KEFF];
// Prepacked K/V tiles: per (win,h): 256 rows x 128B; row = [hi(32 bf16)|lo(32 bf16)],
// 16B chunks swizzled by ^(row&7).
__device__ unsigned char g_Ktb[P2 * 8 * 32768];
__device__ unsigned char g_Vtb[P2 * 8 * 32768];

__device__ __forceinline__ uint32_t smem_u32(const void* p) {
    uint32_t a;
    asm("{ .reg .u64 t; cvta.to.shared.u64 t, %1; cvt.u32.u64 %0, t; }" : "=r"(a) : "l"(p));
    return a;
}
__device__ __forceinline__ uint32_t pack_bf(__nv_bfloat16 lo, __nv_bfloat16 hi) {
    return ((uint32_t)__bfloat16_as_ushort(hi) << 16) | __bfloat16_as_ushort(lo);
}
__device__ __forceinline__ void ldsm_x4(uint32_t& r0, uint32_t& r1, uint32_t& r2, uint32_t& r3, uint32_t a) {
    asm volatile("ldmatrix.sync.aligned.m8n8.x4.shared.b16 {%0,%1,%2,%3}, [%4];"
                 : "=r"(r0), "=r"(r1), "=r"(r2), "=r"(r3) : "r"(a));
}
__device__ __forceinline__ void ldsm_x4_t(uint32_t& r0, uint32_t& r1, uint32_t& r2, uint32_t& r3, uint32_t a) {
    asm volatile("ldmatrix.sync.aligned.m8n8.x4.trans.shared.b16 {%0,%1,%2,%3}, [%4];"
                 : "=r"(r0), "=r"(r1), "=r"(r2), "=r"(r3) : "r"(a));
}
__device__ __forceinline__ void mma16816(float* c, const uint32_t* a, const uint32_t* b) {
    asm volatile(
        "mma.sync.aligned.m16n8k16.row.col.f32.bf16.bf16.f32 "
        "{%0,%1,%2,%3}, {%4,%5,%6,%7}, {%8,%9}, {%0,%1,%2,%3};"
        : "+f"(c[0]), "+f"(c[1]), "+f"(c[2]), "+f"(c[3])
        : "r"(a[0]), "r"(a[1]), "r"(a[2]), "r"(a[3]), "r"(b[0]), "r"(b[1]));
}

// ---------------------------------------------------------------------------
// Prep kernels
// ---------------------------------------------------------------------------
__global__ __launch_bounds__(256) void prep_w(const float* __restrict__ wq,
                                              const float* __restrict__ wo) {
    const int t = blockIdx.x * 256 + threadIdx.x;
    const int n = t >> 8, k = t & 255;
    if (t < NQKV * KDIM) {
        const float v = wq[k * NQKV + n];
        const __nv_bfloat16 h = __float2bfloat16(v);
        const __nv_bfloat16 l = __float2bfloat16(v - __bfloat162float(h));
        g_Bq[n * KEFF + k]       = h;
        g_Bq[n * KEFF + 256 + k] = l;
        g_Bq[n * KEFF + 512 + k] = h;
    }
    if (t < KDIM * KDIM) {
        const float v = wo[k * KDIM + n];
        const __nv_bfloat16 h = __float2bfloat16(v);
        const __nv_bfloat16 l = __float2bfloat16(v - __bfloat162float(h));
        g_Bo[n * KEFF + k]       = h;
        g_Bo[n * KEFF + 256 + k] = l;
        g_Bo[n * KEFF + 512 + k] = h;
    }
}

__global__ __launch_bounds__(256) void prep_a(const float* __restrict__ x) {
    const int m = blockIdx.x, c = threadIdx.x;
    const int p = m >> 8, pix = m & 255;
    const int gy = (p / 7) * 16 + (pix >> 4);
    const int gx = (p % 7) * 16 + (pix & 15);
    const float v = x[(gy * IMG + gx) * KDIM + c];
    const __nv_bfloat16 h = __float2bfloat16(v);
    const __nv_bfloat16 l = __float2bfloat16(v - __bfloat162float(h));
    g_Ap[m * KEFF + c]       = h;
    g_Ap[m * KEFF + 256 + c] = h;
    g_Ap[m * KEFF + 512 + c] = l;
}

// Prepack K/V hi/lo swizzled tiles. grid (49, 8), 256 threads (one row each).
__global__ __launch_bounds__(256) void prep_kv() {
    const int p = blockIdx.x, h = blockIdx.y, j = threadIdx.x;
    const float* ksrc = g_qkv + ((size_t)(p * W2 + j)) * NQKV + 256 + h * 32;
    const float* vsrc = ksrc + 256;
    const size_t base = ((size_t)(p * 8 + h)) * 32768 + (size_t)j * 128;
    uint32_t kw[32], vw[32];
#pragma unroll
    for (int w = 0; w < 16; w++) {
        float f0 = ksrc[2 * w], f1 = ksrc[2 * w + 1];
        __nv_bfloat16 h0 = __float2bfloat16(f0), h1 = __float2bfloat16(f1);
        kw[w]      = pack_bf(h0, h1);
        kw[16 + w] = pack_bf(__float2bfloat16(f0 - __bfloat162float(h0)),
                             __float2bfloat16(f1 - __bfloat162float(h1)));
        f0 = vsrc[2 * w]; f1 = vsrc[2 * w + 1];
        h0 = __float2bfloat16(f0); h1 = __float2bfloat16(f1);
        vw[w]      = pack_bf(h0, h1);
        vw[16 + w] = pack_bf(__float2bfloat16(f0 - __bfloat162float(h0)),
                             __float2bfloat16(f1 - __bfloat162float(h1)));
    }
#pragma unroll
    for (int c = 0; c < 8; c++) {
        const int off = ((c ^ (j & 7)) * 16);
        *(uint4*)(g_Ktb + base + off) = make_uint4(kw[4*c], kw[4*c+1], kw[4*c+2], kw[4*c+3]);
        *(uint4*)(g_Vtb + base + off) = make_uint4(vw[4*c], vw[4*c+1], vw[4*c+2], vw[4*c+3]);
    }
}

// ---------------------------------------------------------------------------
// Dense GEMM (validated in R3)
// ---------------------------------------------------------------------------
template <int MODE>
__global__ __launch_bounds__(256) void gemm_mma(const float* __restrict__ bias,
                                                float* __restrict__ Cout) {
    constexpr int N = (MODE == 0) ? NQKV : KDIM;
    __shared__ __align__(128) __nv_bfloat16 As[128 * 64];
    __shared__ __align__(128) __nv_bfloat16 Bs[128 * 64];

    const __nv_bfloat16* A = (MODE == 0) ? g_Ap : g_Yp;
    const __nv_bfloat16* B = (MODE == 0) ? g_Bq : g_Bo;
    float* C = (MODE == 0) ? g_qkv : Cout;

    const int tid  = threadIdx.x;
    const int wid  = tid >> 5;
    const int lane = tid & 31;
    const int m0   = blockIdx.y * 128;
    const int n0   = blockIdx.x * 128;
    const int mw   = (wid >> 1) * 32;
    const int nw   = (wid & 1) * 64;

    const uint32_t sA = smem_u32(As), sB = smem_u32(Bs);

    uint4 pa[4], pb[4];
    int grow[4], gchk[4];
#pragma unroll
    for (int i = 0; i < 4; i++) {
        const int idx = tid + 256 * i;
        grow[i] = idx >> 3;
        gchk[i] = idx & 7;
    }
#pragma unroll
    for (int i = 0; i < 4; i++) {
        pa[i] = *(const uint4*)(A + (size_t)(m0 + grow[i]) * KEFF + gchk[i] * 8);
        pb[i] = *(const uint4*)(B + (size_t)(n0 + grow[i]) * KEFF + gchk[i] * 8);
    }

    float acc[2][8][4];
#pragma unroll
    for (int mt = 0; mt < 2; mt++)
#pragma unroll
        for (int nt = 0; nt < 8; nt++)
#pragma unroll
            for (int j = 0; j < 4; j++) acc[mt][nt][j] = 0.f;

    for (int kt = 0; kt < KEFF / 64; kt++) {
#pragma unroll
        for (int i = 0; i < 4; i++) {
            const int so = grow[i] * 128 + ((gchk[i] ^ (grow[i] & 7)) * 16);
            *(uint4*)((char*)As + so) = pa[i];
            *(uint4*)((char*)Bs + so) = pb[i];
        }
        __syncthreads();
        if (kt + 1 < KEFF / 64) {
            const int k0 = (kt + 1) * 64;
#pragma unroll
            for (int i = 0; i < 4; i++) {
                pa[i] = *(const uint4*)(A + (size_t)(m0 + grow[i]) * KEFF + k0 + gchk[i] * 8);
                pb[i] = *(const uint4*)(B + (size_t)(n0 + grow[i]) * KEFF + k0 + gchk[i] * 8);
            }
        }
#pragma unroll
        for (int ks = 0; ks < 4; ks++) {
            uint32_t aF[2][4];
#pragma unroll
            for (int mt = 0; mt < 2; mt++) {
                const int row = mw + mt * 16 + (lane & 15);
                const int chk = ks * 2 + (lane >> 4);
                ldsm_x4(aF[mt][0], aF[mt][1], aF[mt][2], aF[mt][3],
                        sA + row * 128 + ((chk ^ (row & 7)) * 16));
            }
            uint32_t bF[8][2];
#pragma unroll
            for (int np = 0; np < 4; np++) {
                const int row = nw + np * 16 + (lane & 7) + ((lane >> 4) << 3);
                const int chk = ks * 2 + ((lane >> 3) & 1);
                uint32_t r0, r1, r2, r3;
                ldsm_x4(r0, r1, r2, r3, sB + row * 128 + ((chk ^ (row & 7)) * 16));
                bF[np * 2][0] = r0; bF[np * 2][1] = r1;
                bF[np * 2 + 1][0] = r2; bF[np * 2 + 1][1] = r3;
            }
#pragma unroll
            for (int mt = 0; mt < 2; mt++)
#pragma unroll
                for (int nt = 0; nt < 8; nt++)
                    mma16816(acc[mt][nt], aF[mt], bF[nt]);
        }
        __syncthreads();
    }

    const int r0 = lane >> 2, c0 = (lane & 3) * 2;
#pragma unroll
    for (int mt = 0; mt < 2; mt++) {
#pragma unroll
        for (int nt = 0; nt < 8; nt++) {
            const int col = n0 + nw + nt * 8 + c0;
            const float bx = bias[col], by = bias[col + 1];
            const int rowa = m0 + mw + mt * 16 + r0;
            float2 v0 = {acc[mt][nt][0] + bx, acc[mt][nt][1] + by};
            float2 v1 = {acc[mt][nt][2] + bx, acc[mt][nt][3] + by};
            *(float2*)(C + (size_t)rowa * N + col)       = v0;
            *(float2*)(C + (size_t)(rowa + 8) * N + col) = v1;
        }
    }
}

// ---------------------------------------------------------------------------
// Window means (2-stage), routing, top-k
// ---------------------------------------------------------------------------
__global__ __launch_bounds__(512) void means1() {
    const int p = blockIdx.x, sl = blockIdx.y, c = threadIdx.x;
    const float* b = g_qkv + ((size_t)(p * W2 + sl * 32)) * NQKV + c;
    float s = 0.f;
#pragma unroll
    for (int i = 0; i < 32; i++) s += b[(size_t)i * NQKV];
    g_part[sl][p][c] = s;
}
__global__ __launch_bounds__(512) void means2() {
    const int p = blockIdx.x, c = threadIdx.x;
    float s = 0.f;
#pragma unroll
    for (int sl = 0; sl < 8; sl++) s += g_part[sl][p][c];
    s *= (1.f / 256.f);
    if (c < 256) g_qwin[p * 256 + c] = s;
    else         g_kwin[p * 256 + (c - 256)] = s;
}

__global__ __launch_bounds__(256) void logit_k() {
    const int t = blockIdx.x * 256 + threadIdx.x;
    if (t >= P2 * P2) return;
    const int p = t / P2, j = t % P2;
    const float4* qa = (const float4*)(g_qwin + p * 256);
    const float4* ka = (const float4*)(g_kwin + j * 256);
    float s = 0.f;
#pragma unroll 8
    for (int c = 0; c < 64; c++) {
        const float4 a = qa[c], b = ka[c];
        s += a.x * b.x + a.y * b.y + a.z * b.z + a.w * b.w;
    }
    g_logit[t] = s * SCALE;
}

__global__ void topk_k() {
    const int p = threadIdx.x;
    if (p >= P2) return;
    float bv0 = -1e30f, bv1 = -1e30f, bv2 = -1e30f, bv3 = -1e30f;
    int   bi0 = 0, bi1 = 0, bi2 = 0, bi3 = 0;
    for (int j = 0; j < P2; j++) {
        const float s = g_logit[p * P2 + j];
        if (s > bv3) {
            if (s > bv0)      { bv3=bv2;bi3=bi2; bv2=bv1;bi2=bi1; bv1=bv0;bi1=bi0; bv0=s;bi0=j; }
            else if (s > bv1) { bv3=bv2;bi3=bi2; bv2=bv1;bi2=bi1; bv1=s;bi1=j; }
            else if (s > bv2) { bv3=bv2;bi3=bi2; bv2=s;bi2=j; }
            else              { bv3=s;bi3=j; }
        }
    }
    g_top[p * 4 + 0] = bi0; g_top[p * 4 + 1] = bi1;
    g_top[p * 4 + 2] = bi2; g_top[p * 4 + 3] = bi3;
}

// ---------------------------------------------------------------------------
// Attention on tensor cores. Block = (window, head), 8 warps x 32 query rows.
// Online softmax per warp-row (quad shuffles). 64-key chunks from prepacked
// swizzled K/V tiles. 3-term hi/lo split for both QK^T and P*V.
// ---------------------------------------------------------------------------
__global__ __launch_bounds__(256) void attn_mma() {
    __shared__ __align__(128) unsigned char Kt[8192];
    __shared__ __align__(128) unsigned char Vt[8192];
    __shared__ int sidx[4];
    const int p = blockIdx.x, h = blockIdx.y;
    const int tid = threadIdx.x, wid = tid >> 5, lane = tid & 31;
    if (tid < 4) sidx[tid] = g_top[p * 4 + tid];

    const uint32_t sK = smem_u32(Kt), sV = smem_u32(Vt);
    const int r  = lane >> 2;
    const int c2 = (lane & 3) * 2;

    // Q fragments (prescaled, hi/lo split)
    uint32_t qh[2][2][4], ql[2][2][4];
    {
        const float* qb = g_qkv + ((size_t)p * W2 + wid * 32) * NQKV + h * 32;
#pragma unroll
        for (int mt = 0; mt < 2; mt++)
#pragma unroll
            for (int ks = 0; ks < 2; ks++)
#pragma unroll
                for (int idx = 0; idx < 4; idx++) {
                    const int row = mt * 16 + r + (idx & 1) * 8;
                    const int col = ks * 16 + (idx >> 1) * 8 + c2;
                    const float2 v = *(const float2*)(qb + (size_t)row * NQKV + col);
                    const float f0 = v.x * SCALE, f1 = v.y * SCALE;
                    const __nv_bfloat16 h0 = __float2bfloat16(f0), h1 = __float2bfloat16(f1);
                    qh[mt][ks][idx] = pack_bf(h0, h1);
                    ql[mt][ks][idx] = pack_bf(__float2bfloat16(f0 - __bfloat162float(h0)),
                                              __float2bfloat16(f1 - __bfloat162float(h1)));
                }
    }
    __syncthreads();
    const int s0 = sidx[0], s1 = sidx[1], s2 = sidx[2], s3 = sidx[3];

    float m[2][2], l[2][2];
    float outA[2][4][4];
#pragma unroll
    for (int mt = 0; mt < 2; mt++)
#pragma unroll
        for (int hf = 0; hf < 2; hf++) { m[mt][hf] = -1e30f; l[mt][hf] = 0.f; }
#pragma unroll
    for (int mt = 0; mt < 2; mt++)
#pragma unroll
        for (int ct = 0; ct < 4; ct++)
#pragma unroll
            for (int j = 0; j < 4; j++) outA[mt][ct][j] = 0.f;

    // prefetch chunk 0
    uint4 pk0, pk1, pv0, pv1;
    {
        const size_t b = ((size_t)(s0 * 8 + h)) * 32768 + (size_t)tid * 16;
        pk0 = *(const uint4*)(g_Ktb + b);
        pk1 = *(const uint4*)(g_Ktb + b + 4096);
        pv0 = *(const uint4*)(g_Vtb + b);
        pv1 = *(const uint4*)(g_Vtb + b + 4096);
    }

#pragma unroll 1
    for (int ch = 0; ch < 16; ch++) {
        *(uint4*)(Kt + tid * 16)        = pk0;
        *(uint4*)(Kt + 4096 + tid * 16) = pk1;
        *(uint4*)(Vt + tid * 16)        = pv0;
        *(uint4*)(Vt + 4096 + tid * 16) = pv1;
        __syncthreads();
        if (ch + 1 < 16) {
            const int nc = ch + 1, t = nc >> 2;
            const int sw = (t == 0) ? s0 : (t == 1) ? s1 : (t == 2) ? s2 : s3;
            const size_t b = ((size_t)(sw * 8 + h)) * 32768 + (size_t)(nc & 3) * 8192 + (size_t)tid * 16;
            pk0 = *(const uint4*)(g_Ktb + b);
            pk1 = *(const uint4*)(g_Ktb + b + 4096);
            pv0 = *(const uint4*)(g_Vtb + b);
            pv1 = *(const uint4*)(g_Vtb + b + 4096);
        }

        // ---- QK^T: 3 passes (qhi*khi, qhi*klo, qlo*khi) ----
        float s[2][8][4];
#pragma unroll
        for (int mt = 0; mt < 2; mt++)
#pragma unroll
            for (int nt = 0; nt < 8; nt++)
#pragma unroll
                for (int j = 0; j < 4; j++) s[mt][nt][j] = 0.f;

#pragma unroll
        for (int pass = 0; pass < 3; pass++) {
            const int kb = (pass == 1) ? 4 : 0;           // khi chunks 0..3, klo 4..7
#pragma unroll
            for (int ks = 0; ks < 2; ks++) {
                uint32_t bF[8][2];
#pragma unroll
                for (int np = 0; np < 4; np++) {
                    const int row = np * 16 + (lane & 7) + ((lane >> 4) << 3);
                    const int chk = kb + ks * 2 + ((lane >> 3) & 1);
                    uint32_t r0, r1, r2, r3;
                    ldsm_x4(r0, r1, r2, r3, sK + row * 128 + ((chk ^ (row & 7)) * 16));
                    bF[np * 2][0] = r0; bF[np * 2][1] = r1;
                    bF[np * 2 + 1][0] = r2; bF[np * 2 + 1][1] = r3;
                }
#pragma unroll
                for (int mt = 0; mt < 2; mt++) {
                    const uint32_t* aF = (pass == 2) ? ql[mt][ks] : qh[mt][ks];
#pragma unroll
                    for (int nt = 0; nt < 8; nt++)
                        mma16816(s[mt][nt], aF, bF[nt]);
                }
            }
        }

        // ---- online softmax ----
#pragma unroll
        for (int mt = 0; mt < 2; mt++)
#pragma unroll
            for (int hf = 0; hf < 2; hf++) {
                float cm = -1e30f;
#pragma unroll
                for (int nt = 0; nt < 8; nt++) {
                    cm = fmaxf(cm, s[mt][nt][hf * 2]);
                    cm = fmaxf(cm, s[mt][nt][hf * 2 + 1]);
                }
                cm = fmaxf(cm, __shfl_xor_sync(0xffffffffu, cm, 1));
                cm = fmaxf(cm, __shfl_xor_sync(0xffffffffu, cm, 2));
                const float mn = fmaxf(m[mt][hf], cm);
                const float corr = __expf(m[mt][hf] - mn);
                m[mt][hf] = mn;
                l[mt][hf] *= corr;
#pragma unroll
                for (int ct = 0; ct < 4; ct++) {
                    outA[mt][ct][hf * 2]     *= corr;
                    outA[mt][ct][hf * 2 + 1] *= corr;
                }
                float ll = 0.f;
#pragma unroll
                for (int nt = 0; nt < 8; nt++) {
                    const float e0 = __expf(s[mt][nt][hf * 2]     - mn);
                    const float e1 = __expf(s[mt][nt][hf * 2 + 1] - mn);
                    s[mt][nt][hf * 2]     = e0;
                    s[mt][nt][hf * 2 + 1] = e1;
                    ll += e0 + e1;
                }
                l[mt][hf] += ll;
            }

        // ---- convert P to bf16 hi/lo, packed in place ----
#pragma unroll
        for (int mt = 0; mt < 2; mt++)
#pragma unroll
            for (int nt = 0; nt < 8; nt++) {
                const float v0 = s[mt][nt][0], v1 = s[mt][nt][1];
                const float v2 = s[mt][nt][2], v3 = s[mt][nt][3];
                const __nv_bfloat16 h0 = __float2bfloat16(v0), h1 = __float2bfloat16(v1);
                const __nv_bfloat16 h2 = __float2bfloat16(v2), h3 = __float2bfloat16(v3);
                s[mt][nt][0] = __uint_as_float(pack_bf(h0, h1));
                s[mt][nt][2] = __uint_as_float(pack_bf(h2, h3));
                s[mt][nt][1] = __uint_as_float(pack_bf(__float2bfloat16(v0 - __bfloat162float(h0)),
                                                       __float2bfloat16(v1 - __bfloat162float(h1))));
                s[mt][nt][3] = __uint_as_float(pack_bf(__float2bfloat16(v2 - __bfloat162float(h2)),
                                                       __float2bfloat16(v3 - __bfloat162float(h3))));
            }

        // ---- P*V: 3 passes (phi*vhi, phi*vlo, plo*vhi) ----
#pragma unroll
        for (int pass = 0; pass < 3; pass++) {
            const int vb = (pass == 1) ? 4 : 0;
            const int pi = (pass == 2) ? 1 : 0;           // hi regs [0],[2]; lo regs [1],[3]
#pragma unroll
            for (int ks = 0; ks < 4; ks++) {
                uint32_t bV[4][2];
#pragma unroll
                for (int cp = 0; cp < 2; cp++) {
                    const int row = ks * 16 + (lane & 15);
                    const int chk = vb + cp * 2 + (lane >> 4);
                    uint32_t r0, r1, r2, r3;
                    ldsm_x4_t(r0, r1, r2, r3, sV + row * 128 + ((chk ^ (row & 7)) * 16));
                    bV[cp * 2][0] = r0; bV[cp * 2][1] = r1;
                    bV[cp * 2 + 1][0] = r2; bV[cp * 2 + 1][1] = r3;
                }
#pragma unroll
                for (int mt = 0; mt < 2; mt++) {
                    uint32_t aP[4];
                    aP[0] = __float_as_uint(s[mt][2 * ks][pi]);
                    aP[1] = __float_as_uint(s[mt][2 * ks][pi + 2]);
                    aP[2] = __float_as_uint(s[mt][2 * ks + 1][pi]);
                    aP[3] = __float_as_uint(s[mt][2 * ks + 1][pi + 2]);
#pragma unroll
                    for (int ct = 0; ct < 4; ct++)
                        mma16816(outA[mt][ct], aP, bV[ct]);
                }
            }
        }
        __syncthreads();
    }

    // ---- epilogue: normalize, write image layout ----
    const int wy = p / 7, wx = p % 7;
#pragma unroll
    for (int mt = 0; mt < 2; mt++)
#pragma unroll
        for (int hf = 0; hf < 2; hf++) {
            float ls = l[mt][hf];
            ls += __shfl_xor_sync(0xffffffffu, ls, 1);
            ls += __shfl_xor_sync(0xffffffffu, ls, 2);
            const float inv = 1.f / ls;
            const int q = wid * 32 + mt * 16 + r + hf * 8;
            const int gy = wy * 16 + (q >> 4), gx = wx * 16 + (q & 15);
            float* o = g_y + ((size_t)(gy * IMG + gx)) * 256 + h * 32;
#pragma unroll
            for (int ct = 0; ct < 4; ct++) {
                float2 v = {outA[mt][ct][hf * 2] * inv, outA[mt][ct][hf * 2 + 1] * inv};
                *(float2*)(o + ct * 8 + c2) = v;
            }
        }
}

// ---------------------------------------------------------------------------
// LePE + add attention output; emit split-packed rows for out-gemm
// ---------------------------------------------------------------------------
__global__ __launch_bounds__(256) void lepe_k(const float* __restrict__ lw,
                                              const float* __restrict__ lb) {
    const int pix = blockIdx.x;
    const int c   = threadIdx.x;
    const int y = pix / IMG, x = pix % IMG;
    float sum = lb[c];
#pragma unroll
    for (int dy = -1; dy <= 1; dy++) {
        const int yy = y + dy;
        if (yy < 0 || yy >= IMG) continue;
#pragma unroll
        for (int dx = -1; dx <= 1; dx++) {
            const int xx = x + dx;
            if (xx < 0 || xx >= IMG) continue;
            const int p  = (yy >> 4) * 7 + (xx >> 4);
            const int pp = ((yy & 15) << 4) | (xx & 15);
            const float v = g_qkv[((size_t)(p * W2 + pp)) * NQKV + 512 + c];
            sum += v * lw[((dy + 1) * 3 + (dx + 1)) * 256 + c];
        }
    }
    const float tot = g_y[(size_t)pix * 256 + c] + sum;
    const __nv_bfloat16 h = __float2bfloat16(tot);
    const __nv_bfloat16 l = __float2bfloat16(tot - __bfloat162float(h));
    g_Yp[(size_t)pix * KEFF + c]       = h;
    g_Yp[(size_t)pix * KEFF + 256 + c] = h;
    g_Yp[(size_t)pix * KEFF + 512 + c] = l;
}

// ---------------------------------------------------------------------------
extern "C" void kernel_launch(void* const* d_in, const int* in_sizes, int n_in,
                              void* d_out, int out_size) {
    const float* x      = (const float*)d_in[0];
    const float* w_qkv  = (const float*)d_in[1];
    const float* b_qkv  = (const float*)d_in[2];
    const float* w_o    = (const float*)d_in[3];
    const float* b_o    = (const float*)d_in[4];
    const float* lepe_w = (const float*)d_in[5];
    const float* lepe_b = (const float*)d_in[6];
    float* out = (float*)d_out;
    (void)in_sizes; (void)n_in; (void)out_size;

    prep_w<<<(NQKV * KDIM + 255) / 256, 256>>>(w_qkv, w_o);
    prep_a<<<MROWS, 256>>>(x);
    gemm_mma<0><<<dim3(NQKV / 128, MROWS / 128), 256>>>(b_qkv, nullptr);
    prep_kv<<<dim3(P2, 8), 256>>>();
    means1<<<dim3(P2, 8), 512>>>();
    means2<<<P2, 512>>>();
    logit_k<<<(P2 * P2 + 255) / 256, 256>>>();
    topk_k<<<1, 64>>>();
    attn_mma<<<dim3(P2, 8), 256>>>();
    lepe_k<<<IMG * IMG, 256>>>(lepe_w, lepe_b);
    gemm_mma<1><<<dim3(KDIM / 128, MROWS / 128), 256>>>(b_o, out);
}

// round 5
// speedup vs baseline: 2.3254x; 1.0855x over previous
#include <cuda_runtime.h>
#include <cuda_bf16.h>
#include <cstdint>

// ---------------------------------------------------------------------------
// BiLevelRoutingAttention, B=1, H=W=112, DIM=QK=256, HEADS=8, NWIN=7, TOPK=4
// GEMMs + attention on mma.sync bf16 hi/lo split. qkv-GEMM epilogue fuses the
// K/V tile packing (bf16 hi/lo, swizzled) and v image-layout scatter.
// ---------------------------------------------------------------------------

#define P2     49
#define W2     256
#define MROWS  12544
#define NQKV   768
#define KDIM   256
#define KEFF   768
#define IMG    112
#define SCALE  0.0625f

__device__ float g_qkv [MROWS * 512];              // q|k only, stride 512
__device__ float g_vimg[MROWS * 256];              // v, image layout
__device__ float g_qwin[P2 * 256];
__device__ float g_kwin[P2 * 256];
__device__ float g_part[8][P2][512];
__device__ float g_logit[P2 * P2];
__device__ int   g_top [P2 * 4];
__device__ float g_y   [MROWS * 256];              // attn out, image layout
__device__ __nv_bfloat16 g_Ap[MROWS * KEFF];
__device__ __nv_bfloat16 g_Yp[MROWS * KEFF];
__device__ __nv_bfloat16 g_Bq[NQKV * KEFF];
__device__ __nv_bfloat16 g_Bo[KDIM * KEFF];
// Packed K/V tiles: per (win,h): 256 rows x 128B; row = [hi(32 bf16)|lo(32 bf16)],
// 16B chunks swizzled by ^(row&7).
__device__ unsigned char g_Ktb[P2 * 8 * 32768];
__device__ unsigned char g_Vtb[P2 * 8 * 32768];

__device__ __forceinline__ uint32_t smem_u32(const void* p) {
    uint32_t a;
    asm("{ .reg .u64 t; cvta.to.shared.u64 t, %1; cvt.u32.u64 %0, t; }" : "=r"(a) : "l"(p));
    return a;
}
__device__ __forceinline__ uint32_t pack_bf(__nv_bfloat16 lo, __nv_bfloat16 hi) {
    return ((uint32_t)__bfloat16_as_ushort(hi) << 16) | __bfloat16_as_ushort(lo);
}
__device__ __forceinline__ void ldsm_x4(uint32_t& r0, uint32_t& r1, uint32_t& r2, uint32_t& r3, uint32_t a) {
    asm volatile("ldmatrix.sync.aligned.m8n8.x4.shared.b16 {%0,%1,%2,%3}, [%4];"
                 : "=r"(r0), "=r"(r1), "=r"(r2), "=r"(r3) : "r"(a));
}
__device__ __forceinline__ void ldsm_x4_t(uint32_t& r0, uint32_t& r1, uint32_t& r2, uint32_t& r3, uint32_t a) {
    asm volatile("ldmatrix.sync.aligned.m8n8.x4.trans.shared.b16 {%0,%1,%2,%3}, [%4];"
                 : "=r"(r0), "=r"(r1), "=r"(r2), "=r"(r3) : "r"(a));
}
__device__ __forceinline__ void mma16816(float* c, const uint32_t* a, const uint32_t* b) {
    asm volatile(
        "mma.sync.aligned.m16n8k16.row.col.f32.bf16.bf16.f32 "
        "{%0,%1,%2,%3}, {%4,%5,%6,%7}, {%8,%9}, {%0,%1,%2,%3};"
        : "+f"(c[0]), "+f"(c[1]), "+f"(c[2]), "+f"(c[3])
        : "r"(a[0]), "r"(a[1]), "r"(a[2]), "r"(a[3]), "r"(b[0]), "r"(b[1]));
}

// ---------------------------------------------------------------------------
// Prep kernels
// ---------------------------------------------------------------------------
__global__ __launch_bounds__(256) void prep_w(const float* __restrict__ wq,
                                              const float* __restrict__ wo) {
    const int t = blockIdx.x * 256 + threadIdx.x;
    const int n = t >> 8, k = t & 255;
    if (t < NQKV * KDIM) {
        const float v = wq[k * NQKV + n];
        const __nv_bfloat16 h = __float2bfloat16(v);
        const __nv_bfloat16 l = __float2bfloat16(v - __bfloat162float(h));
        g_Bq[n * KEFF + k]       = h;
        g_Bq[n * KEFF + 256 + k] = l;
        g_Bq[n * KEFF + 512 + k] = h;
    }
    if (t < KDIM * KDIM) {
        const float v = wo[k * KDIM + n];
        const __nv_bfloat16 h = __float2bfloat16(v);
        const __nv_bfloat16 l = __float2bfloat16(v - __bfloat162float(h));
        g_Bo[n * KEFF + k]       = h;
        g_Bo[n * KEFF + 256 + k] = l;
        g_Bo[n * KEFF + 512 + k] = h;
    }
}

__global__ __launch_bounds__(256) void prep_a(const float* __restrict__ x) {
    const int m = blockIdx.x, c = threadIdx.x;
    const int p = m >> 8, pix = m & 255;
    const int gy = (p / 7) * 16 + (pix >> 4);
    const int gx = (p % 7) * 16 + (pix & 15);
    const float v = x[(gy * IMG + gx) * KDIM + c];
    const __nv_bfloat16 h = __float2bfloat16(v);
    const __nv_bfloat16 l = __float2bfloat16(v - __bfloat162float(h));
    g_Ap[m * KEFF + c]       = h;
    g_Ap[m * KEFF + 256 + c] = h;
    g_Ap[m * KEFF + 512 + c] = l;
}

// ---------------------------------------------------------------------------
// Dense GEMM (core validated R3/R4). MODE 0 epilogue fuses KV packing.
// ---------------------------------------------------------------------------
template <int MODE>
__global__ __launch_bounds__(256) void gemm_mma(const float* __restrict__ bias,
                                                float* __restrict__ Cout) {
    __shared__ __align__(128) __nv_bfloat16 As[128 * 64];
    __shared__ __align__(128) __nv_bfloat16 Bs[128 * 64];

    const __nv_bfloat16* A = (MODE == 0) ? g_Ap : g_Yp;
    const __nv_bfloat16* B = (MODE == 0) ? g_Bq : g_Bo;

    const int tid  = threadIdx.x;
    const int wid  = tid >> 5;
    const int lane = tid & 31;
    const int m0   = blockIdx.y * 128;
    const int n0   = blockIdx.x * 128;
    const int mw   = (wid >> 1) * 32;
    const int nw   = (wid & 1) * 64;

    const uint32_t sA = smem_u32(As), sB = smem_u32(Bs);

    uint4 pa[4], pb[4];
    int grow[4], gchk[4];
#pragma unroll
    for (int i = 0; i < 4; i++) {
        const int idx = tid + 256 * i;
        grow[i] = idx >> 3;
        gchk[i] = idx & 7;
    }
#pragma unroll
    for (int i = 0; i < 4; i++) {
        pa[i] = *(const uint4*)(A + (size_t)(m0 + grow[i]) * KEFF + gchk[i] * 8);
        pb[i] = *(const uint4*)(B + (size_t)(n0 + grow[i]) * KEFF + gchk[i] * 8);
    }

    float acc[2][8][4];
#pragma unroll
    for (int mt = 0; mt < 2; mt++)
#pragma unroll
        for (int nt = 0; nt < 8; nt++)
#pragma unroll
            for (int j = 0; j < 4; j++) acc[mt][nt][j] = 0.f;

    for (int kt = 0; kt < KEFF / 64; kt++) {
#pragma unroll
        for (int i = 0; i < 4; i++) {
            const int so = grow[i] * 128 + ((gchk[i] ^ (grow[i] & 7)) * 16);
            *(uint4*)((char*)As + so) = pa[i];
            *(uint4*)((char*)Bs + so) = pb[i];
        }
        __syncthreads();
        if (kt + 1 < KEFF / 64) {
            const int k0 = (kt + 1) * 64;
#pragma unroll
            for (int i = 0; i < 4; i++) {
                pa[i] = *(const uint4*)(A + (size_t)(m0 + grow[i]) * KEFF + k0 + gchk[i] * 8);
                pb[i] = *(const uint4*)(B + (size_t)(n0 + grow[i]) * KEFF + k0 + gchk[i] * 8);
            }
        }
#pragma unroll
        for (int ks = 0; ks < 4; ks++) {
            uint32_t aF[2][4];
#pragma unroll
            for (int mt = 0; mt < 2; mt++) {
                const int row = mw + mt * 16 + (lane & 15);
                const int chk = ks * 2 + (lane >> 4);
                ldsm_x4(aF[mt][0], aF[mt][1], aF[mt][2], aF[mt][3],
                        sA + row * 128 + ((chk ^ (row & 7)) * 16));
            }
            uint32_t bF[8][2];
#pragma unroll
            for (int np = 0; np < 4; np++) {
                const int row = nw + np * 16 + (lane & 7) + ((lane >> 4) << 3);
                const int chk = ks * 2 + ((lane >> 3) & 1);
                uint32_t r0, r1, r2, r3;
                ldsm_x4(r0, r1, r2, r3, sB + row * 128 + ((chk ^ (row & 7)) * 16));
                bF[np * 2][0] = r0; bF[np * 2][1] = r1;
                bF[np * 2 + 1][0] = r2; bF[np * 2 + 1][1] = r3;
            }
#pragma unroll
            for (int mt = 0; mt < 2; mt++)
#pragma unroll
                for (int nt = 0; nt < 8; nt++)
                    mma16816(acc[mt][nt], aF[mt], bF[nt]);
        }
        __syncthreads();
    }

    const int r0 = lane >> 2, c0 = (lane & 3) * 2;
    // kind: 0 = q cols, 1 = k cols, 2 = v cols (MODE 0 only; uniform per block)
    const int kind = (MODE == 0) ? ((n0 >= 512) ? 2 : ((n0 >= 256) ? 1 : 0)) : 0;

#pragma unroll
    for (int mt = 0; mt < 2; mt++) {
#pragma unroll
        for (int nt = 0; nt < 8; nt++) {
            const int col = n0 + nw + nt * 8 + c0;
            const float bx = bias[col], by = bias[col + 1];
            const int rowa = m0 + mw + mt * 16 + r0;
            const float vx[2] = {acc[mt][nt][0] + bx, acc[mt][nt][2] + bx};
            const float vy[2] = {acc[mt][nt][1] + by, acc[mt][nt][3] + by};
            if (MODE == 1) {
                *(float2*)(Cout + (size_t)rowa * KDIM + col)       = make_float2(vx[0], vy[0]);
                *(float2*)(Cout + (size_t)(rowa + 8) * KDIM + col) = make_float2(vx[1], vy[1]);
            } else {
#pragma unroll
                for (int rr = 0; rr < 2; rr++) {
                    const int row = rowa + rr * 8;
                    if (kind < 2)
                        *(float2*)(g_qkv + (size_t)row * 512 + col) = make_float2(vx[rr], vy[rr]);
                    if (kind >= 1) {
                        const int cc = col - ((kind == 1) ? 256 : 512);
                        const int hh = cc >> 5, w = (cc & 31) >> 1;
                        const int p = row >> 8, j = row & 255;
                        unsigned char* tb = ((kind == 1) ? g_Ktb : g_Vtb)
                                          + ((size_t)(p * 8 + hh)) * 32768 + (size_t)j * 128;
                        const int sw = j & 7;
                        const int hib = (((w >> 2) ^ sw) * 16) + (w & 3) * 4;
                        const int lob = (((4 + (w >> 2)) ^ sw) * 16) + (w & 3) * 4;
                        const __nv_bfloat16 hx = __float2bfloat16(vx[rr]);
                        const __nv_bfloat16 hy = __float2bfloat16(vy[rr]);
                        *(uint32_t*)(tb + hib) = pack_bf(hx, hy);
                        *(uint32_t*)(tb + lob) = pack_bf(
                            __float2bfloat16(vx[rr] - __bfloat162float(hx)),
                            __float2bfloat16(vy[rr] - __bfloat162float(hy)));
                    }
                    if (kind == 2) {
                        const int p = row >> 8, pix = row & 255;
                        const int gy = (p / 7) * 16 + (pix >> 4);
                        const int gx = (p % 7) * 16 + (pix & 15);
                        *(float2*)(g_vimg + ((size_t)(gy * IMG + gx)) * 256 + (col - 512))
                            = make_float2(vx[rr], vy[rr]);
                    }
                }
            }
        }
    }
}

// ---------------------------------------------------------------------------
// Window means (2-stage), routing, top-k
// ---------------------------------------------------------------------------
__global__ __launch_bounds__(512) void means1() {
    const int p = blockIdx.x, sl = blockIdx.y, c = threadIdx.x;
    const float* b = g_qkv + ((size_t)(p * W2 + sl * 32)) * 512 + c;
    float s = 0.f;
#pragma unroll
    for (int i = 0; i < 32; i++) s += b[(size_t)i * 512];
    g_part[sl][p][c] = s;
}
__global__ __launch_bounds__(512) void means2() {
    const int p = blockIdx.x, c = threadIdx.x;
    float s = 0.f;
#pragma unroll
    for (int sl = 0; sl < 8; sl++) s += g_part[sl][p][c];
    s *= (1.f / 256.f);
    if (c < 256) g_qwin[p * 256 + c] = s;
    else         g_kwin[p * 256 + (c - 256)] = s;
}

__global__ __launch_bounds__(256) void logit_k() {
    const int t = blockIdx.x * 256 + threadIdx.x;
    if (t >= P2 * P2) return;
    const int p = t / P2, j = t % P2;
    const float4* qa = (const float4*)(g_qwin + p * 256);
    const float4* ka = (const float4*)(g_kwin + j * 256);
    float s = 0.f;
#pragma unroll 8
    for (int c = 0; c < 64; c++) {
        const float4 a = qa[c], b = ka[c];
        s += a.x * b.x + a.y * b.y + a.z * b.z + a.w * b.w;
    }
    g_logit[t] = s * SCALE;
}

__global__ void topk_k() {
    const int p = threadIdx.x;
    if (p >= P2) return;
    float bv0 = -1e30f, bv1 = -1e30f, bv2 = -1e30f, bv3 = -1e30f;
    int   bi0 = 0, bi1 = 0, bi2 = 0, bi3 = 0;
    for (int j = 0; j < P2; j++) {
        const float s = g_logit[p * P2 + j];
        if (s > bv3) {
            if (s > bv0)      { bv3=bv2;bi3=bi2; bv2=bv1;bi2=bi1; bv1=bv0;bi1=bi0; bv0=s;bi0=j; }
            else if (s > bv1) { bv3=bv2;bi3=bi2; bv2=bv1;bi2=bi1; bv1=s;bi1=j; }
            else if (s > bv2) { bv3=bv2;bi3=bi2; bv2=s;bi2=j; }
            else              { bv3=s;bi3=j; }
        }
    }
    g_top[p * 4 + 0] = bi0; g_top[p * 4 + 1] = bi1;
    g_top[p * 4 + 2] = bi2; g_top[p * 4 + 3] = bi3;
}

// ---------------------------------------------------------------------------
// Attention on tensor cores (validated R4). Block = (window, head).
// ---------------------------------------------------------------------------
__global__ __launch_bounds__(256) void attn_mma() {
    __shared__ __align__(128) unsigned char Kt[8192];
    __shared__ __align__(128) unsigned char Vt[8192];
    __shared__ int sidx[4];
    const int p = blockIdx.x, h = blockIdx.y;
    const int tid = threadIdx.x, wid = tid >> 5, lane = tid & 31;
    if (tid < 4) sidx[tid] = g_top[p * 4 + tid];

    const uint32_t sK = smem_u32(Kt), sV = smem_u32(Vt);
    const int r  = lane >> 2;
    const int c2 = (lane & 3) * 2;

    uint32_t qh[2][2][4], ql[2][2][4];
    {
        const float* qb = g_qkv + ((size_t)p * W2 + wid * 32) * 512 + h * 32;
#pragma unroll
        for (int mt = 0; mt < 2; mt++)
#pragma unroll
            for (int ks = 0; ks < 2; ks++)
#pragma unroll
                for (int idx = 0; idx < 4; idx++) {
                    const int row = mt * 16 + r + (idx & 1) * 8;
                    const int col = ks * 16 + (idx >> 1) * 8 + c2;
                    const float2 v = *(const float2*)(qb + (size_t)row * 512 + col);
                    const float f0 = v.x * SCALE, f1 = v.y * SCALE;
                    const __nv_bfloat16 h0 = __float2bfloat16(f0), h1 = __float2bfloat16(f1);
                    qh[mt][ks][idx] = pack_bf(h0, h1);
                    ql[mt][ks][idx] = pack_bf(__float2bfloat16(f0 - __bfloat162float(h0)),
                                              __float2bfloat16(f1 - __bfloat162float(h1)));
                }
    }
    __syncthreads();
    const int s0 = sidx[0], s1 = sidx[1], s2 = sidx[2], s3 = sidx[3];

    float m[2][2], l[2][2];
    float outA[2][4][4];
#pragma unroll
    for (int mt = 0; mt < 2; mt++)
#pragma unroll
        for (int hf = 0; hf < 2; hf++) { m[mt][hf] = -1e30f; l[mt][hf] = 0.f; }
#pragma unroll
    for (int mt = 0; mt < 2; mt++)
#pragma unroll
        for (int ct = 0; ct < 4; ct++)
#pragma unroll
            for (int j = 0; j < 4; j++) outA[mt][ct][j] = 0.f;

    uint4 pk0, pk1, pv0, pv1;
    {
        const size_t b = ((size_t)(s0 * 8 + h)) * 32768 + (size_t)tid * 16;
        pk0 = *(const uint4*)(g_Ktb + b);
        pk1 = *(const uint4*)(g_Ktb + b + 4096);
        pv0 = *(const uint4*)(g_Vtb + b);
        pv1 = *(const uint4*)(g_Vtb + b + 4096);
    }

#pragma unroll 1
    for (int ch = 0; ch < 16; ch++) {
        *(uint4*)(Kt + tid * 16)        = pk0;
        *(uint4*)(Kt + 4096 + tid * 16) = pk1;
        *(uint4*)(Vt + tid * 16)        = pv0;
        *(uint4*)(Vt + 4096 + tid * 16) = pv1;
        __syncthreads();
        if (ch + 1 < 16) {
            const int nc = ch + 1, t = nc >> 2;
            const int sw = (t == 0) ? s0 : (t == 1) ? s1 : (t == 2) ? s2 : s3;
            const size_t b = ((size_t)(sw * 8 + h)) * 32768 + (size_t)(nc & 3) * 8192 + (size_t)tid * 16;
            pk0 = *(const uint4*)(g_Ktb + b);
            pk1 = *(const uint4*)(g_Ktb + b + 4096);
            pv0 = *(const uint4*)(g_Vtb + b);
            pv1 = *(const uint4*)(g_Vtb + b + 4096);
        }

        float s[2][8][4];
#pragma unroll
        for (int mt = 0; mt < 2; mt++)
#pragma unroll
            for (int nt = 0; nt < 8; nt++)
#pragma unroll
                for (int j = 0; j < 4; j++) s[mt][nt][j] = 0.f;

#pragma unroll
        for (int pass = 0; pass < 3; pass++) {
            const int kb = (pass == 1) ? 4 : 0;
#pragma unroll
            for (int ks = 0; ks < 2; ks++) {
                uint32_t bF[8][2];
#pragma unroll
                for (int np = 0; np < 4; np++) {
                    const int row = np * 16 + (lane & 7) + ((lane >> 4) << 3);
                    const int chk = kb + ks * 2 + ((lane >> 3) & 1);
                    uint32_t r0, r1, r2, r3;
                    ldsm_x4(r0, r1, r2, r3, sK + row * 128 + ((chk ^ (row & 7)) * 16));
                    bF[np * 2][0] = r0; bF[np * 2][1] = r1;
                    bF[np * 2 + 1][0] = r2; bF[np * 2 + 1][1] = r3;
                }
#pragma unroll
                for (int mt = 0; mt < 2; mt++) {
                    const uint32_t* aF = (pass == 2) ? ql[mt][ks] : qh[mt][ks];
#pragma unroll
                    for (int nt = 0; nt < 8; nt++)
                        mma16816(s[mt][nt], aF, bF[nt]);
                }
            }
        }

#pragma unroll
        for (int mt = 0; mt < 2; mt++)
#pragma unroll
            for (int hf = 0; hf < 2; hf++) {
                float cm = -1e30f;
#pragma unroll
                for (int nt = 0; nt < 8; nt++) {
                    cm = fmaxf(cm, s[mt][nt][hf * 2]);
                    cm = fmaxf(cm, s[mt][nt][hf * 2 + 1]);
                }
                cm = fmaxf(cm, __shfl_xor_sync(0xffffffffu, cm, 1));
                cm = fmaxf(cm, __shfl_xor_sync(0xffffffffu, cm, 2));
                const float mn = fmaxf(m[mt][hf], cm);
                const float corr = __expf(m[mt][hf] - mn);
                m[mt][hf] = mn;
                l[mt][hf] *= corr;
#pragma unroll
                for (int ct = 0; ct < 4; ct++) {
                    outA[mt][ct][hf * 2]     *= corr;
                    outA[mt][ct][hf * 2 + 1] *= corr;
                }
                float ll = 0.f;
#pragma unroll
                for (int nt = 0; nt < 8; nt++) {
                    const float e0 = __expf(s[mt][nt][hf * 2]     - mn);
                    const float e1 = __expf(s[mt][nt][hf * 2 + 1] - mn);
                    s[mt][nt][hf * 2]     = e0;
                    s[mt][nt][hf * 2 + 1] = e1;
                    ll += e0 + e1;
                }
                l[mt][hf] += ll;
            }

#pragma unroll
        for (int mt = 0; mt < 2; mt++)
#pragma unroll
            for (int nt = 0; nt < 8; nt++) {
                const float v0 = s[mt][nt][0], v1 = s[mt][nt][1];
                const float v2 = s[mt][nt][2], v3 = s[mt][nt][3];
                const __nv_bfloat16 h0 = __float2bfloat16(v0), h1 = __float2bfloat16(v1);
                const __nv_bfloat16 h2 = __float2bfloat16(v2), h3 = __float2bfloat16(v3);
                s[mt][nt][0] = __uint_as_float(pack_bf(h0, h1));
                s[mt][nt][2] = __uint_as_float(pack_bf(h2, h3));
                s[mt][nt][1] = __uint_as_float(pack_bf(__float2bfloat16(v0 - __bfloat162float(h0)),
                                                       __float2bfloat16(v1 - __bfloat162float(h1))));
                s[mt][nt][3] = __uint_as_float(pack_bf(__float2bfloat16(v2 - __bfloat162float(h2)),
                                                       __float2bfloat16(v3 - __bfloat162float(h3))));
            }

#pragma unroll
        for (int pass = 0; pass < 3; pass++) {
            const int vb = (pass == 1) ? 4 : 0;
            const int pi = (pass == 2) ? 1 : 0;
#pragma unroll
            for (int ks = 0; ks < 4; ks++) {
                uint32_t bV[4][2];
#pragma unroll
                for (int cp = 0; cp < 2; cp++) {
                    const int row = ks * 16 + (lane & 15);
                    const int chk = vb + cp * 2 + (lane >> 4);
                    uint32_t r0, r1, r2, r3;
                    ldsm_x4_t(r0, r1, r2, r3, sV + row * 128 + ((chk ^ (row & 7)) * 16));
                    bV[cp * 2][0] = r0; bV[cp * 2][1] = r1;
                    bV[cp * 2 + 1][0] = r2; bV[cp * 2 + 1][1] = r3;
                }
#pragma unroll
                for (int mt = 0; mt < 2; mt++) {
                    uint32_t aP[4];
                    aP[0] = __float_as_uint(s[mt][2 * ks][pi]);
                    aP[1] = __float_as_uint(s[mt][2 * ks][pi + 2]);
                    aP[2] = __float_as_uint(s[mt][2 * ks + 1][pi]);
                    aP[3] = __float_as_uint(s[mt][2 * ks + 1][pi + 2]);
#pragma unroll
                    for (int ct = 0; ct < 4; ct++)
                        mma16816(outA[mt][ct], aP, bV[ct]);
                }
            }
        }
        __syncthreads();
    }

    const int wy = p / 7, wx = p % 7;
#pragma unroll
    for (int mt = 0; mt < 2; mt++)
#pragma unroll
        for (int hf = 0; hf < 2; hf++) {
            float ls = l[mt][hf];
            ls += __shfl_xor_sync(0xffffffffu, ls, 1);
            ls += __shfl_xor_sync(0xffffffffu, ls, 2);
            const float inv = 1.f / ls;
            const int q = wid * 32 + mt * 16 + r + hf * 8;
            const int gy = wy * 16 + (q >> 4), gx = wx * 16 + (q & 15);
            float* o = g_y + ((size_t)(gy * IMG + gx)) * 256 + h * 32;
#pragma unroll
            for (int ct = 0; ct < 4; ct++) {
                float2 v = {outA[mt][ct][hf * 2] * inv, outA[mt][ct][hf * 2 + 1] * inv};
                *(float2*)(o + ct * 8 + c2) = v;
            }
        }
}

// ---------------------------------------------------------------------------
// LePE (coalesced image-layout v) + add attn; emit split-packed rows
// ---------------------------------------------------------------------------
__global__ __launch_bounds__(256) void lepe_k(const float* __restrict__ lw,
                                              const float* __restrict__ lb) {
    const int pix = blockIdx.x;
    const int c   = threadIdx.x;
    const int y = pix / IMG, x = pix % IMG;
    float sum = lb[c];
#pragma unroll
    for (int dy = -1; dy <= 1; dy++) {
        const int yy = y + dy;
        if (yy < 0 || yy >= IMG) continue;
#pragma unroll
        for (int dx = -1; dx <= 1; dx++) {
            const int xx = x + dx;
            if (xx < 0 || xx >= IMG) continue;
            const float v = g_vimg[((size_t)(yy * IMG + xx)) * 256 + c];
            sum += v * lw[((dy + 1) * 3 + (dx + 1)) * 256 + c];
        }
    }
    const float tot = g_y[(size_t)pix * 256 + c] + sum;
    const __nv_bfloat16 h = __float2bfloat16(tot);
    const __nv_bfloat16 l = __float2bfloat16(tot - __bfloat162float(h));
    g_Yp[(size_t)pix * KEFF + c]       = h;
    g_Yp[(size_t)pix * KEFF + 256 + c] = h;
    g_Yp[(size_t)pix * KEFF + 512 + c] = l;
}

// ---------------------------------------------------------------------------
extern "C" void kernel_launch(void* const* d_in, const int* in_sizes, int n_in,
                              void* d_out, int out_size) {
    const float* x      = (const float*)d_in[0];
    const float* w_qkv  = (const float*)d_in[1];
    const float* b_qkv  = (const float*)d_in[2];
    const float* w_o    = (const float*)d_in[3];
    const float* b_o    = (const float*)d_in[4];
    const float* lepe_w = (const float*)d_in[5];
    const float* lepe_b = (const float*)d_in[6];
    float* out = (float*)d_out;
    (void)in_sizes; (void)n_in; (void)out_size;

    prep_w<<<(NQKV * KDIM + 255) / 256, 256>>>(w_qkv, w_o);
    prep_a<<<MROWS, 256>>>(x);
    gemm_mma<0><<<dim3(NQKV / 128, MROWS / 128), 256>>>(b_qkv, nullptr);
    means1<<<dim3(P2, 8), 512>>>();
    means2<<<P2, 512>>>();
    logit_k<<<(P2 * P2 + 255) / 256, 256>>>();
    topk_k<<<1, 64>>>();
    attn_mma<<<dim3(P2, 8), 256>>>();
    lepe_k<<<IMG * IMG, 256>>>(lepe_w, lepe_b);
    gemm_mma<1><<<dim3(KDIM / 128, MROWS / 128), 256>>>(b_o, out);
}

// round 6
// speedup vs baseline: 2.4626x; 1.0590x over previous
#include <cuda_runtime.h>
#include <cuda_bf16.h>
#include <cstdint>

// ---------------------------------------------------------------------------
// BiLevelRoutingAttention, B=1, H=W=112, DIM=QK=256, HEADS=8, NWIN=7, TOPK=4
// GEMMs + attention on mma.sync bf16 hi/lo split. qkv-GEMM epilogue fuses the
// K/V tile packing (bf16 hi/lo, swizzled) and v image-layout scatter.
// Routing fused into one 49-block kernel (means finalize + logits + top-4).
// ---------------------------------------------------------------------------

#define P2     49
#define W2     256
#define MROWS  12544
#define NQKV   768
#define KDIM   256
#define KEFF   768
#define IMG    112
#define SCALE  0.0625f
#define QSCALE 0.09016844f   // SCALE * log2(e)

__device__ float g_qkv [MROWS * 512];              // q|k only, stride 512
__device__ float g_vimg[MROWS * 256];              // v, image layout
__device__ float g_part[8][P2][512];
__device__ int   g_top [P2 * 4];
__device__ float g_y   [MROWS * 256];              // attn out, image layout
__device__ __nv_bfloat16 g_Ap[MROWS * KEFF];
__device__ __nv_bfloat16 g_Yp[MROWS * KEFF];
__device__ __nv_bfloat16 g_Bq[NQKV * KEFF];
__device__ __nv_bfloat16 g_Bo[KDIM * KEFF];
// Packed K/V tiles: per (win,h): 256 rows x 128B; row = [hi(32 bf16)|lo(32 bf16)],
// 16B chunks swizzled by ^(row&7).
__device__ unsigned char g_Ktb[P2 * 8 * 32768];
__device__ unsigned char g_Vtb[P2 * 8 * 32768];

__device__ __forceinline__ uint32_t smem_u32(const void* p) {
    uint32_t a;
    asm("{ .reg .u64 t; cvta.to.shared.u64 t, %1; cvt.u32.u64 %0, t; }" : "=r"(a) : "l"(p));
    return a;
}
__device__ __forceinline__ uint32_t pack_bf(__nv_bfloat16 lo, __nv_bfloat16 hi) {
    return ((uint32_t)__bfloat16_as_ushort(hi) << 16) | __bfloat16_as_ushort(lo);
}
__device__ __forceinline__ void ldsm_x4(uint32_t& r0, uint32_t& r1, uint32_t& r2, uint32_t& r3, uint32_t a) {
    asm volatile("ldmatrix.sync.aligned.m8n8.x4.shared.b16 {%0,%1,%2,%3}, [%4];"
                 : "=r"(r0), "=r"(r1), "=r"(r2), "=r"(r3) : "r"(a));
}
__device__ __forceinline__ void ldsm_x4_t(uint32_t& r0, uint32_t& r1, uint32_t& r2, uint32_t& r3, uint32_t a) {
    asm volatile("ldmatrix.sync.aligned.m8n8.x4.trans.shared.b16 {%0,%1,%2,%3}, [%4];"
                 : "=r"(r0), "=r"(r1), "=r"(r2), "=r"(r3) : "r"(a));
}
__device__ __forceinline__ void mma16816(float* c, const uint32_t* a, const uint32_t* b) {
    asm volatile(
        "mma.sync.aligned.m16n8k16.row.col.f32.bf16.bf16.f32 "
        "{%0,%1,%2,%3}, {%4,%5,%6,%7}, {%8,%9}, {%0,%1,%2,%3};"
        : "+f"(c[0]), "+f"(c[1]), "+f"(c[2]), "+f"(c[3])
        : "r"(a[0]), "r"(a[1]), "r"(a[2]), "r"(a[3]), "r"(b[0]), "r"(b[1]));
}

// ---------------------------------------------------------------------------
// Prep kernels
// ---------------------------------------------------------------------------
__global__ __launch_bounds__(256) void prep_w(const float* __restrict__ wq,
                                              const float* __restrict__ wo) {
    const int t = blockIdx.x * 256 + threadIdx.x;
    const int n = t >> 8, k = t & 255;
    if (t < NQKV * KDIM) {
        const float v = wq[k * NQKV + n];
        const __nv_bfloat16 h = __float2bfloat16(v);
        const __nv_bfloat16 l = __float2bfloat16(v - __bfloat162float(h));
        g_Bq[n * KEFF + k]       = h;
        g_Bq[n * KEFF + 256 + k] = l;
        g_Bq[n * KEFF + 512 + k] = h;
    }
    if (t < KDIM * KDIM) {
        const float v = wo[k * KDIM + n];
        const __nv_bfloat16 h = __float2bfloat16(v);
        const __nv_bfloat16 l = __float2bfloat16(v - __bfloat162float(h));
        g_Bo[n * KEFF + k]       = h;
        g_Bo[n * KEFF + 256 + k] = l;
        g_Bo[n * KEFF + 512 + k] = h;
    }
}

__global__ __launch_bounds__(256) void prep_a(const float* __restrict__ x) {
    const int m = blockIdx.x, c = threadIdx.x;
    const int p = m >> 8, pix = m & 255;
    const int gy = (p / 7) * 16 + (pix >> 4);
    const int gx = (p % 7) * 16 + (pix & 15);
    const float v = x[(gy * IMG + gx) * KDIM + c];
    const __nv_bfloat16 h = __float2bfloat16(v);
    const __nv_bfloat16 l = __float2bfloat16(v - __bfloat162float(h));
    g_Ap[m * KEFF + c]       = h;
    g_Ap[m * KEFF + 256 + c] = h;
    g_Ap[m * KEFF + 512 + c] = l;
}

// ---------------------------------------------------------------------------
// Dense GEMM (validated). MODE 0 epilogue fuses KV packing + v image scatter.
// ---------------------------------------------------------------------------
template <int MODE>
__global__ __launch_bounds__(256) void gemm_mma(const float* __restrict__ bias,
                                                float* __restrict__ Cout) {
    __shared__ __align__(128) __nv_bfloat16 As[128 * 64];
    __shared__ __align__(128) __nv_bfloat16 Bs[128 * 64];

    const __nv_bfloat16* A = (MODE == 0) ? g_Ap : g_Yp;
    const __nv_bfloat16* B = (MODE == 0) ? g_Bq : g_Bo;

    const int tid  = threadIdx.x;
    const int wid  = tid >> 5;
    const int lane = tid & 31;
    const int m0   = blockIdx.y * 128;
    const int n0   = blockIdx.x * 128;
    const int mw   = (wid >> 1) * 32;
    const int nw   = (wid & 1) * 64;

    const uint32_t sA = smem_u32(As), sB = smem_u32(Bs);

    uint4 pa[4], pb[4];
    int grow[4], gchk[4];
#pragma unroll
    for (int i = 0; i < 4; i++) {
        const int idx = tid + 256 * i;
        grow[i] = idx >> 3;
        gchk[i] = idx & 7;
    }
#pragma unroll
    for (int i = 0; i < 4; i++) {
        pa[i] = *(const uint4*)(A + (size_t)(m0 + grow[i]) * KEFF + gchk[i] * 8);
        pb[i] = *(const uint4*)(B + (size_t)(n0 + grow[i]) * KEFF + gchk[i] * 8);
    }

    float acc[2][8][4];
#pragma unroll
    for (int mt = 0; mt < 2; mt++)
#pragma unroll
        for (int nt = 0; nt < 8; nt++)
#pragma unroll
            for (int j = 0; j < 4; j++) acc[mt][nt][j] = 0.f;

    for (int kt = 0; kt < KEFF / 64; kt++) {
#pragma unroll
        for (int i = 0; i < 4; i++) {
            const int so = grow[i] * 128 + ((gchk[i] ^ (grow[i] & 7)) * 16);
            *(uint4*)((char*)As + so) = pa[i];
            *(uint4*)((char*)Bs + so) = pb[i];
        }
        __syncthreads();
        if (kt + 1 < KEFF / 64) {
            const int k0 = (kt + 1) * 64;
#pragma unroll
            for (int i = 0; i < 4; i++) {
                pa[i] = *(const uint4*)(A + (size_t)(m0 + grow[i]) * KEFF + k0 + gchk[i] * 8);
                pb[i] = *(const uint4*)(B + (size_t)(n0 + grow[i]) * KEFF + k0 + gchk[i] * 8);
            }
        }
#pragma unroll
        for (int ks = 0; ks < 4; ks++) {
            uint32_t aF[2][4];
#pragma unroll
            for (int mt = 0; mt < 2; mt++) {
                const int row = mw + mt * 16 + (lane & 15);
                const int chk = ks * 2 + (lane >> 4);
                ldsm_x4(aF[mt][0], aF[mt][1], aF[mt][2], aF[mt][3],
                        sA + row * 128 + ((chk ^ (row & 7)) * 16));
            }
            uint32_t bF[8][2];
#pragma unroll
            for (int np = 0; np < 4; np++) {
                const int row = nw + np * 16 + (lane & 7) + ((lane >> 4) << 3);
                const int chk = ks * 2 + ((lane >> 3) & 1);
                uint32_t r0, r1, r2, r3;
                ldsm_x4(r0, r1, r2, r3, sB + row * 128 + ((chk ^ (row & 7)) * 16));
                bF[np * 2][0] = r0; bF[np * 2][1] = r1;
                bF[np * 2 + 1][0] = r2; bF[np * 2 + 1][1] = r3;
            }
#pragma unroll
            for (int mt = 0; mt < 2; mt++)
#pragma unroll
                for (int nt = 0; nt < 8; nt++)
                    mma16816(acc[mt][nt], aF[mt], bF[nt]);
        }
        __syncthreads();
    }

    const int r0 = lane >> 2, c0 = (lane & 3) * 2;
    const int kind = (MODE == 0) ? ((n0 >= 512) ? 2 : ((n0 >= 256) ? 1 : 0)) : 0;

#pragma unroll
    for (int mt = 0; mt < 2; mt++) {
#pragma unroll
        for (int nt = 0; nt < 8; nt++) {
            const int col = n0 + nw + nt * 8 + c0;
            const float bx = bias[col], by = bias[col + 1];
            const int rowa = m0 + mw + mt * 16 + r0;
            const float vx[2] = {acc[mt][nt][0] + bx, acc[mt][nt][2] + bx};
            const float vy[2] = {acc[mt][nt][1] + by, acc[mt][nt][3] + by};
            if (MODE == 1) {
                *(float2*)(Cout + (size_t)rowa * KDIM + col)       = make_float2(vx[0], vy[0]);
                *(float2*)(Cout + (size_t)(rowa + 8) * KDIM + col) = make_float2(vx[1], vy[1]);
            } else {
#pragma unroll
                for (int rr = 0; rr < 2; rr++) {
                    const int row = rowa + rr * 8;
                    if (kind < 2)
                        *(float2*)(g_qkv + (size_t)row * 512 + col) = make_float2(vx[rr], vy[rr]);
                    if (kind >= 1) {
                        const int cc = col - ((kind == 1) ? 256 : 512);
                        const int hh = cc >> 5, w = (cc & 31) >> 1;
                        const int p = row >> 8, j = row & 255;
                        unsigned char* tb = ((kind == 1) ? g_Ktb : g_Vtb)
                                          + ((size_t)(p * 8 + hh)) * 32768 + (size_t)j * 128;
                        const int sw = j & 7;
                        const int hib = (((w >> 2) ^ sw) * 16) + (w & 3) * 4;
                        const int lob = (((4 + (w >> 2)) ^ sw) * 16) + (w & 3) * 4;
                        const __nv_bfloat16 hx = __float2bfloat16(vx[rr]);
                        const __nv_bfloat16 hy = __float2bfloat16(vy[rr]);
                        *(uint32_t*)(tb + hib) = pack_bf(hx, hy);
                        *(uint32_t*)(tb + lob) = pack_bf(
                            __float2bfloat16(vx[rr] - __bfloat162float(hx)),
                            __float2bfloat16(vy[rr] - __bfloat162float(hy)));
                    }
                    if (kind == 2) {
                        const int p = row >> 8, pix = row & 255;
                        const int gy = (p / 7) * 16 + (pix >> 4);
                        const int gx = (p % 7) * 16 + (pix & 15);
                        *(float2*)(g_vimg + ((size_t)(gy * IMG + gx)) * 256 + (col - 512))
                            = make_float2(vx[rr], vy[rr]);
                    }
                }
            }
        }
    }
}

// ---------------------------------------------------------------------------
// Window partial sums (stage 1) — unchanged.
// ---------------------------------------------------------------------------
__global__ __launch_bounds__(512) void means1() {
    const int p = blockIdx.x, sl = blockIdx.y, c = threadIdx.x;
    const float* b = g_qkv + ((size_t)(p * W2 + sl * 32)) * 512 + c;
    float s = 0.f;
#pragma unroll
    for (int i = 0; i < 32; i++) s += b[(size_t)i * 512];
    g_part[sl][p][c] = s;
}

// ---------------------------------------------------------------------------
// Routing fused: block p computes its q-row sum, logits vs all 49 k-row sums,
// and top-4 (ranking invariant to the monotone mean/scale factors).
// ---------------------------------------------------------------------------
__global__ __launch_bounds__(256) void route_k() {
    __shared__ float sq[256];
    __shared__ float slog[64];
    const int p = blockIdx.x, tid = threadIdx.x, wrp = tid >> 5, lane = tid & 31;

    // q-row sum for window p
    {
        float s = 0.f;
#pragma unroll
        for (int sl = 0; sl < 8; sl++) s += g_part[sl][p][tid];
        sq[tid] = s;
    }
    __syncthreads();

    // logits: warp w handles j = w, w+8, ... ; lane covers 8 channels
    const float q0 = sq[lane * 8 + 0], q1 = sq[lane * 8 + 1];
    const float q2 = sq[lane * 8 + 2], q3 = sq[lane * 8 + 3];
    const float q4 = sq[lane * 8 + 4], q5 = sq[lane * 8 + 5];
    const float q6 = sq[lane * 8 + 6], q7 = sq[lane * 8 + 7];
    for (int j = wrp; j < P2; j += 8) {
        float kc[8];
#pragma unroll
        for (int i = 0; i < 8; i++) kc[i] = 0.f;
#pragma unroll
        for (int sl = 0; sl < 8; sl++) {
            const float4 a = *(const float4*)&g_part[sl][j][256 + lane * 8];
            const float4 b = *(const float4*)&g_part[sl][j][256 + lane * 8 + 4];
            kc[0] += a.x; kc[1] += a.y; kc[2] += a.z; kc[3] += a.w;
            kc[4] += b.x; kc[5] += b.y; kc[6] += b.z; kc[7] += b.w;
        }
        float d = q0 * kc[0] + q1 * kc[1] + q2 * kc[2] + q3 * kc[3]
                + q4 * kc[4] + q5 * kc[5] + q6 * kc[6] + q7 * kc[7];
#pragma unroll
        for (int o = 16; o > 0; o >>= 1) d += __shfl_xor_sync(0xffffffffu, d, o);
        if (lane == 0) slog[j] = d;
    }
    __syncthreads();

    if (tid == 0) {
        float bv0 = -1e30f, bv1 = -1e30f, bv2 = -1e30f, bv3 = -1e30f;
        int   bi0 = 0, bi1 = 0, bi2 = 0, bi3 = 0;
        for (int j = 0; j < P2; j++) {
            const float s = slog[j];
            if (s > bv3) {
                if (s > bv0)      { bv3=bv2;bi3=bi2; bv2=bv1;bi2=bi1; bv1=bv0;bi1=bi0; bv0=s;bi0=j; }
                else if (s > bv1) { bv3=bv2;bi3=bi2; bv2=bv1;bi2=bi1; bv1=s;bi1=j; }
                else if (s > bv2) { bv3=bv2;bi3=bi2; bv2=s;bi2=j; }
                else              { bv3=s;bi3=j; }
            }
        }
        g_top[p * 4 + 0] = bi0; g_top[p * 4 + 1] = bi1;
        g_top[p * 4 + 2] = bi2; g_top[p * 4 + 3] = bi3;
    }
}

// ---------------------------------------------------------------------------
// Attention on tensor cores (validated R4/R5). exp2-domain softmax.
// ---------------------------------------------------------------------------
__global__ __launch_bounds__(256) void attn_mma() {
    __shared__ __align__(128) unsigned char Kt[8192];
    __shared__ __align__(128) unsigned char Vt[8192];
    __shared__ int sidx[4];
    const int p = blockIdx.x, h = blockIdx.y;
    const int tid = threadIdx.x, wid = tid >> 5, lane = tid & 31;
    if (tid < 4) sidx[tid] = g_top[p * 4 + tid];

    const uint32_t sK = smem_u32(Kt), sV = smem_u32(Vt);
    const int r  = lane >> 2;
    const int c2 = (lane & 3) * 2;

    uint32_t qh[2][2][4], ql[2][2][4];
    {
        const float* qb = g_qkv + ((size_t)p * W2 + wid * 32) * 512 + h * 32;
#pragma unroll
        for (int mt = 0; mt < 2; mt++)
#pragma unroll
            for (int ks = 0; ks < 2; ks++)
#pragma unroll
                for (int idx = 0; idx < 4; idx++) {
                    const int row = mt * 16 + r + (idx & 1) * 8;
                    const int col = ks * 16 + (idx >> 1) * 8 + c2;
                    const float2 v = *(const float2*)(qb + (size_t)row * 512 + col);
                    const float f0 = v.x * QSCALE, f1 = v.y * QSCALE;
                    const __nv_bfloat16 h0 = __float2bfloat16(f0), h1 = __float2bfloat16(f1);
                    qh[mt][ks][idx] = pack_bf(h0, h1);
                    ql[mt][ks][idx] = pack_bf(__float2bfloat16(f0 - __bfloat162float(h0)),
                                              __float2bfloat16(f1 - __bfloat162float(h1)));
                }
    }
    __syncthreads();
    const int s0 = sidx[0], s1 = sidx[1], s2 = sidx[2], s3 = sidx[3];

    float m[2][2], l[2][2];
    float outA[2][4][4];
#pragma unroll
    for (int mt = 0; mt < 2; mt++)
#pragma unroll
        for (int hf = 0; hf < 2; hf++) { m[mt][hf] = -1e30f; l[mt][hf] = 0.f; }
#pragma unroll
    for (int mt = 0; mt < 2; mt++)
#pragma unroll
        for (int ct = 0; ct < 4; ct++)
#pragma unroll
            for (int j = 0; j < 4; j++) outA[mt][ct][j] = 0.f;

    uint4 pk0, pk1, pv0, pv1;
    {
        const size_t b = ((size_t)(s0 * 8 + h)) * 32768 + (size_t)tid * 16;
        pk0 = *(const uint4*)(g_Ktb + b);
        pk1 = *(const uint4*)(g_Ktb + b + 4096);
        pv0 = *(const uint4*)(g_Vtb + b);
        pv1 = *(const uint4*)(g_Vtb + b + 4096);
    }

#pragma unroll 1
    for (int ch = 0; ch < 16; ch++) {
        *(uint4*)(Kt + tid * 16)        = pk0;
        *(uint4*)(Kt + 4096 + tid * 16) = pk1;
        *(uint4*)(Vt + tid * 16)        = pv0;
        *(uint4*)(Vt + 4096 + tid * 16) = pv1;
        __syncthreads();
        if (ch + 1 < 16) {
            const int nc = ch + 1, t = nc >> 2;
            const int sw = (t == 0) ? s0 : (t == 1) ? s1 : (t == 2) ? s2 : s3;
            const size_t b = ((size_t)(sw * 8 + h)) * 32768 + (size_t)(nc & 3) * 8192 + (size_t)tid * 16;
            pk0 = *(const uint4*)(g_Ktb + b);
            pk1 = *(const uint4*)(g_Ktb + b + 4096);
            pv0 = *(const uint4*)(g_Vtb + b);
            pv1 = *(const uint4*)(g_Vtb + b + 4096);
        }

        float s[2][8][4];
#pragma unroll
        for (int mt = 0; mt < 2; mt++)
#pragma unroll
            for (int nt = 0; nt < 8; nt++)
#pragma unroll
                for (int j = 0; j < 4; j++) s[mt][nt][j] = 0.f;

#pragma unroll
        for (int pass = 0; pass < 3; pass++) {
            const int kb = (pass == 1) ? 4 : 0;
#pragma unroll
            for (int ks = 0; ks < 2; ks++) {
                uint32_t bF[8][2];
#pragma unroll
                for (int np = 0; np < 4; np++) {
                    const int row = np * 16 + (lane & 7) + ((lane >> 4) << 3);
                    const int chk = kb + ks * 2 + ((lane >> 3) & 1);
                    uint32_t r0, r1, r2, r3;
                    ldsm_x4(r0, r1, r2, r3, sK + row * 128 + ((chk ^ (row & 7)) * 16));
                    bF[np * 2][0] = r0; bF[np * 2][1] = r1;
                    bF[np * 2 + 1][0] = r2; bF[np * 2 + 1][1] = r3;
                }
#pragma unroll
                for (int mt = 0; mt < 2; mt++) {
                    const uint32_t* aF = (pass == 2) ? ql[mt][ks] : qh[mt][ks];
#pragma unroll
                    for (int nt = 0; nt < 8; nt++)
                        mma16816(s[mt][nt], aF, bF[nt]);
                }
            }
        }

#pragma unroll
        for (int mt = 0; mt < 2; mt++)
#pragma unroll
            for (int hf = 0; hf < 2; hf++) {
                float cm = -1e30f;
#pragma unroll
                for (int nt = 0; nt < 8; nt++) {
                    cm = fmaxf(cm, s[mt][nt][hf * 2]);
                    cm = fmaxf(cm, s[mt][nt][hf * 2 + 1]);
                }
                cm = fmaxf(cm, __shfl_xor_sync(0xffffffffu, cm, 1));
                cm = fmaxf(cm, __shfl_xor_sync(0xffffffffu, cm, 2));
                const float mn = fmaxf(m[mt][hf], cm);
                const float corr = exp2f(m[mt][hf] - mn);
                m[mt][hf] = mn;
                l[mt][hf] *= corr;
#pragma unroll
                for (int ct = 0; ct < 4; ct++) {
                    outA[mt][ct][hf * 2]     *= corr;
                    outA[mt][ct][hf * 2 + 1] *= corr;
                }
                float ll = 0.f;
#pragma unroll
                for (int nt = 0; nt < 8; nt++) {
                    const float e0 = exp2f(s[mt][nt][hf * 2]     - mn);
                    const float e1 = exp2f(s[mt][nt][hf * 2 + 1] - mn);
                    s[mt][nt][hf * 2]     = e0;
                    s[mt][nt][hf * 2 + 1] = e1;
                    ll += e0 + e1;
                }
                l[mt][hf] += ll;
            }

#pragma unroll
        for (int mt = 0; mt < 2; mt++)
#pragma unroll
            for (int nt = 0; nt < 8; nt++) {
                const float v0 = s[mt][nt][0], v1 = s[mt][nt][1];
                const float v2 = s[mt][nt][2], v3 = s[mt][nt][3];
                const __nv_bfloat16 h0 = __float2bfloat16(v0), h1 = __float2bfloat16(v1);
                const __nv_bfloat16 h2 = __float2bfloat16(v2), h3 = __float2bfloat16(v3);
                s[mt][nt][0] = __uint_as_float(pack_bf(h0, h1));
                s[mt][nt][2] = __uint_as_float(pack_bf(h2, h3));
                s[mt][nt][1] = __uint_as_float(pack_bf(__float2bfloat16(v0 - __bfloat162float(h0)),
                                                       __float2bfloat16(v1 - __bfloat162float(h1))));
                s[mt][nt][3] = __uint_as_float(pack_bf(__float2bfloat16(v2 - __bfloat162float(h2)),
                                                       __float2bfloat16(v3 - __bfloat162float(h3))));
            }

#pragma unroll
        for (int pass = 0; pass < 3; pass++) {
            const int vb = (pass == 1) ? 4 : 0;
            const int pi = (pass == 2) ? 1 : 0;
#pragma unroll
            for (int ks = 0; ks < 4; ks++) {
                uint32_t bV[4][2];
#pragma unroll
                for (int cp = 0; cp < 2; cp++) {
                    const int row = ks * 16 + (lane & 15);
                    const int chk = vb + cp * 2 + (lane >> 4);
                    uint32_t r0, r1, r2, r3;
                    ldsm_x4_t(r0, r1, r2, r3, sV + row * 128 + ((chk ^ (row & 7)) * 16));
                    bV[cp * 2][0] = r0; bV[cp * 2][1] = r1;
                    bV[cp * 2 + 1][0] = r2; bV[cp * 2 + 1][1] = r3;
                }
#pragma unroll
                for (int mt = 0; mt < 2; mt++) {
                    uint32_t aP[4];
                    aP[0] = __float_as_uint(s[mt][2 * ks][pi]);
                    aP[1] = __float_as_uint(s[mt][2 * ks][pi + 2]);
                    aP[2] = __float_as_uint(s[mt][2 * ks + 1][pi]);
                    aP[3] = __float_as_uint(s[mt][2 * ks + 1][pi + 2]);
#pragma unroll
                    for (int ct = 0; ct < 4; ct++)
                        mma16816(outA[mt][ct], aP, bV[ct]);
                }
            }
        }
        __syncthreads();
    }

    const int wy = p / 7, wx = p % 7;
#pragma unroll
    for (int mt = 0; mt < 2; mt++)
#pragma unroll
        for (int hf = 0; hf < 2; hf++) {
            float ls = l[mt][hf];
            ls += __shfl_xor_sync(0xffffffffu, ls, 1);
            ls += __shfl_xor_sync(0xffffffffu, ls, 2);
            const float inv = 1.f / ls;
            const int q = wid * 32 + mt * 16 + r + hf * 8;
            const int gy = wy * 16 + (q >> 4), gx = wx * 16 + (q & 15);
            float* o = g_y + ((size_t)(gy * IMG + gx)) * 256 + h * 32;
#pragma unroll
            for (int ct = 0; ct < 4; ct++) {
                float2 v = {outA[mt][ct][hf * 2] * inv, outA[mt][ct][hf * 2 + 1] * inv};
                *(float2*)(o + ct * 8 + c2) = v;
            }
        }
}

// ---------------------------------------------------------------------------
// LePE (coalesced image-layout v) + add attn; emit split-packed rows
// ---------------------------------------------------------------------------
__global__ __launch_bounds__(256) void lepe_k(const float* __restrict__ lw,
                                              const float* __restrict__ lb) {
    const int pix = blockIdx.x;
    const int c   = threadIdx.x;
    const int y = pix / IMG, x = pix % IMG;
    float sum = lb[c];
#pragma unroll
    for (int dy = -1; dy <= 1; dy++) {
        const int yy = y + dy;
        if (yy < 0 || yy >= IMG) continue;
#pragma unroll
        for (int dx = -1; dx <= 1; dx++) {
            const int xx = x + dx;
            if (xx < 0 || xx >= IMG) continue;
            const float v = g_vimg[((size_t)(yy * IMG + xx)) * 256 + c];
            sum += v * lw[((dy + 1) * 3 + (dx + 1)) * 256 + c];
        }
    }
    const float tot = g_y[(size_t)pix * 256 + c] + sum;
    const __nv_bfloat16 h = __float2bfloat16(tot);
    const __nv_bfloat16 l = __float2bfloat16(tot - __bfloat162float(h));
    g_Yp[(size_t)pix * KEFF + c]       = h;
    g_Yp[(size_t)pix * KEFF + 256 + c] = h;
    g_Yp[(size_t)pix * KEFF + 512 + c] = l;
}

// ---------------------------------------------------------------------------
extern "C" void kernel_launch(void* const* d_in, const int* in_sizes, int n_in,
                              void* d_out, int out_size) {
    const float* x      = (const float*)d_in[0];
    const float* w_qkv  = (const float*)d_in[1];
    const float* b_qkv  = (const float*)d_in[2];
    const float* w_o    = (const float*)d_in[3];
    const float* b_o    = (const float*)d_in[4];
    const float* lepe_w = (const float*)d_in[5];
    const float* lepe_b = (const float*)d_in[6];
    float* out = (float*)d_out;
    (void)in_sizes; (void)n_in; (void)out_size;

    prep_w<<<(NQKV * KDIM + 255) / 256, 256>>>(w_qkv, w_o);      // 1
    prep_a<<<MROWS, 256>>>(x);                                   // 2
    gemm_mma<0><<<dim3(NQKV / 128, MROWS / 128), 256>>>(b_qkv, nullptr);  // 3
    means1<<<dim3(P2, 8), 512>>>();                              // 4
    route_k<<<P2, 256>>>();                                      // 5
    attn_mma<<<dim3(P2, 8), 256>>>();                            // 6  <- ncu -s 5 lands here
    lepe_k<<<IMG * IMG, 256>>>(lepe_w, lepe_b);                  // 7
    gemm_mma<1><<<dim3(KDIM / 128, MROWS / 128), 256>>>(b_o, out); // 8
}

// round 7
// speedup vs baseline: 2.6291x; 1.0676x over previous
#include <cuda_runtime.h>
#include <cuda_bf16.h>
#include <cstdint>

// ---------------------------------------------------------------------------
// BiLevelRoutingAttention, B=1, H=W=112, DIM=QK=256, HEADS=8, NWIN=7, TOPK=4
// GEMMs + attention on mma.sync bf16 hi/lo split (3-term, fp32-grade).
// Split operands stored 512-wide [hi|lo]; k-loop maps 12 virtual tiles onto
// them (A: hi,hi,lo / B: hi,lo,hi). gemm0 epilogue: KV pack + v scatter +
// window column sums. Attention: no-max exp2 softmax (range-safe).
// ---------------------------------------------------------------------------

#define P2     49
#define W2     256
#define MROWS  12544
#define NQKV   768
#define KDIM   256
#define IMG    112
#define QSCALE 0.09016844f   // 256^-0.5 * log2(e)

__device__ float g_qkv [MROWS * 512];              // q|k, stride 512
__device__ float g_vimg[MROWS * 256];              // v, image layout
__device__ float g_part2[98][512];                 // per half-window column sums
__device__ int   g_top [P2 * 4];
__device__ float g_y   [MROWS * 256];              // attn out, image layout
__device__ __nv_bfloat16 g_Ap[MROWS * 512];        // x gathered  [hi|lo]
__device__ __nv_bfloat16 g_Yp[MROWS * 512];        // attn+lepe   [hi|lo]
__device__ __nv_bfloat16 g_Bq[NQKV * 512];         // w_qkv^T     [hi|lo]
__device__ __nv_bfloat16 g_Bo[KDIM * 512];         // w_o^T       [hi|lo]
// Packed K/V tiles: per (win,h): 256 rows x 128B; row = [hi(32)|lo(32)] bf16,
// 16B chunks swizzled by ^(row&7).
__device__ unsigned char g_Ktb[P2 * 8 * 32768];
__device__ unsigned char g_Vtb[P2 * 8 * 32768];

__device__ __forceinline__ uint32_t smem_u32(const void* p) {
    uint32_t a;
    asm("{ .reg .u64 t; cvta.to.shared.u64 t, %1; cvt.u32.u64 %0, t; }" : "=r"(a) : "l"(p));
    return a;
}
__device__ __forceinline__ uint32_t pack_bf(__nv_bfloat16 lo, __nv_bfloat16 hi) {
    return ((uint32_t)__bfloat16_as_ushort(hi) << 16) | __bfloat16_as_ushort(lo);
}
__device__ __forceinline__ void ldsm_x4(uint32_t& r0, uint32_t& r1, uint32_t& r2, uint32_t& r3, uint32_t a) {
    asm volatile("ldmatrix.sync.aligned.m8n8.x4.shared.b16 {%0,%1,%2,%3}, [%4];"
                 : "=r"(r0), "=r"(r1), "=r"(r2), "=r"(r3) : "r"(a));
}
__device__ __forceinline__ void ldsm_x4_t(uint32_t& r0, uint32_t& r1, uint32_t& r2, uint32_t& r3, uint32_t a) {
    asm volatile("ldmatrix.sync.aligned.m8n8.x4.trans.shared.b16 {%0,%1,%2,%3}, [%4];"
                 : "=r"(r0), "=r"(r1), "=r"(r2), "=r"(r3) : "r"(a));
}
__device__ __forceinline__ void mma16816(float* c, const uint32_t* a, const uint32_t* b) {
    asm volatile(
        "mma.sync.aligned.m16n8k16.row.col.f32.bf16.bf16.f32 "
        "{%0,%1,%2,%3}, {%4,%5,%6,%7}, {%8,%9}, {%0,%1,%2,%3};"
        : "+f"(c[0]), "+f"(c[1]), "+f"(c[2]), "+f"(c[3])
        : "r"(a[0]), "r"(a[1]), "r"(a[2]), "r"(a[3]), "r"(b[0]), "r"(b[1]));
}

// virtual k-tile (0..11) -> byte-column base in 512-wide [hi|lo] storage
__device__ __forceinline__ int soffA(int kt) {   // A: hi, hi, lo
    return (kt < 8) ? (kt & 3) * 64 : 256 + (kt & 3) * 64;
}
__device__ __forceinline__ int soffB(int kt) {   // B: hi, lo, hi
    return (kt < 4 || kt >= 8) ? (kt & 3) * 64 : 256 + (kt & 3) * 64;
}

// ---------------------------------------------------------------------------
// Merged prep: blocks [0,768) pack weights; blocks [768, 768+MROWS) pack x.
// ---------------------------------------------------------------------------
__global__ __launch_bounds__(256) void prep_all(const float* __restrict__ wq,
                                                const float* __restrict__ wo,
                                                const float* __restrict__ x) {
    const int b = blockIdx.x, tid = threadIdx.x;
    if (b < NQKV) {
        const int t = b * 256 + tid;
        const int n = t >> 8, k = t & 255;
        {
            const float v = wq[k * NQKV + n];
            const __nv_bfloat16 h = __float2bfloat16(v);
            g_Bq[n * 512 + k]       = h;
            g_Bq[n * 512 + 256 + k] = __float2bfloat16(v - __bfloat162float(h));
        }
        if (t < KDIM * KDIM) {
            const float v = wo[k * KDIM + n];
            const __nv_bfloat16 h = __float2bfloat16(v);
            g_Bo[n * 512 + k]       = h;
            g_Bo[n * 512 + 256 + k] = __float2bfloat16(v - __bfloat162float(h));
        }
    } else {
        const int m = b - NQKV, c = tid;
        const int p = m >> 8, pix = m & 255;
        const int gy = (p / 7) * 16 + (pix >> 4);
        const int gx = (p % 7) * 16 + (pix & 15);
        const float v = x[(gy * IMG + gx) * KDIM + c];
        const __nv_bfloat16 h = __float2bfloat16(v);
        g_Ap[m * 512 + c]       = h;
        g_Ap[m * 512 + 256 + c] = __float2bfloat16(v - __bfloat162float(h));
    }
}

// ---------------------------------------------------------------------------
// Dense GEMM. MODE 0: fuses KV packing, v image scatter, window column sums.
// ---------------------------------------------------------------------------
template <int MODE>
__global__ __launch_bounds__(256) void gemm_mma(const float* __restrict__ bias,
                                                float* __restrict__ Cout) {
    __shared__ __align__(128) __nv_bfloat16 As[128 * 64];
    __shared__ __align__(128) __nv_bfloat16 Bs[128 * 64];
    __shared__ float sWsum[8][64];

    const __nv_bfloat16* A = (MODE == 0) ? g_Ap : g_Yp;
    const __nv_bfloat16* B = (MODE == 0) ? g_Bq : g_Bo;

    const int tid  = threadIdx.x;
    const int wid  = tid >> 5;
    const int lane = tid & 31;
    const int m0   = blockIdx.y * 128;
    const int n0   = blockIdx.x * 128;
    const int mw   = (wid >> 1) * 32;
    const int nw   = (wid & 1) * 64;

    const uint32_t sA = smem_u32(As), sB = smem_u32(Bs);

    uint4 pa[4], pb[4];
    int grow[4], gchk[4];
#pragma unroll
    for (int i = 0; i < 4; i++) {
        const int idx = tid + 256 * i;
        grow[i] = idx >> 3;
        gchk[i] = idx & 7;
    }
#pragma unroll
    for (int i = 0; i < 4; i++) {
        pa[i] = *(const uint4*)(A + (size_t)(m0 + grow[i]) * 512 + soffA(0) + gchk[i] * 8);
        pb[i] = *(const uint4*)(B + (size_t)(n0 + grow[i]) * 512 + soffB(0) + gchk[i] * 8);
    }

    float acc[2][8][4];
#pragma unroll
    for (int mt = 0; mt < 2; mt++)
#pragma unroll
        for (int nt = 0; nt < 8; nt++)
#pragma unroll
            for (int j = 0; j < 4; j++) acc[mt][nt][j] = 0.f;

    for (int kt = 0; kt < 12; kt++) {
#pragma unroll
        for (int i = 0; i < 4; i++) {
            const int so = grow[i] * 128 + ((gchk[i] ^ (grow[i] & 7)) * 16);
            *(uint4*)((char*)As + so) = pa[i];
            *(uint4*)((char*)Bs + so) = pb[i];
        }
        __syncthreads();
        if (kt + 1 < 12) {
            const int ao = soffA(kt + 1), bo = soffB(kt + 1);
#pragma unroll
            for (int i = 0; i < 4; i++) {
                pa[i] = *(const uint4*)(A + (size_t)(m0 + grow[i]) * 512 + ao + gchk[i] * 8);
                pb[i] = *(const uint4*)(B + (size_t)(n0 + grow[i]) * 512 + bo + gchk[i] * 8);
            }
        }
#pragma unroll
        for (int ks = 0; ks < 4; ks++) {
            uint32_t aF[2][4];
#pragma unroll
            for (int mt = 0; mt < 2; mt++) {
                const int row = mw + mt * 16 + (lane & 15);
                const int chk = ks * 2 + (lane >> 4);
                ldsm_x4(aF[mt][0], aF[mt][1], aF[mt][2], aF[mt][3],
                        sA + row * 128 + ((chk ^ (row & 7)) * 16));
            }
            uint32_t bF[8][2];
#pragma unroll
            for (int np = 0; np < 4; np++) {
                const int row = nw + np * 16 + (lane & 7) + ((lane >> 4) << 3);
                const int chk = ks * 2 + ((lane >> 3) & 1);
                uint32_t r0, r1, r2, r3;
                ldsm_x4(r0, r1, r2, r3, sB + row * 128 + ((chk ^ (row & 7)) * 16));
                bF[np * 2][0] = r0; bF[np * 2][1] = r1;
                bF[np * 2 + 1][0] = r2; bF[np * 2 + 1][1] = r3;
            }
#pragma unroll
            for (int mt = 0; mt < 2; mt++)
#pragma unroll
                for (int nt = 0; nt < 8; nt++)
                    mma16816(acc[mt][nt], aF[mt], bF[nt]);
        }
        __syncthreads();
    }

    const int r0 = lane >> 2, c0 = (lane & 3) * 2;
    const int kind = (MODE == 0) ? ((n0 >= 512) ? 2 : ((n0 >= 256) ? 1 : 0)) : 0;

    float cs[8][2];
#pragma unroll
    for (int nt = 0; nt < 8; nt++) { cs[nt][0] = 0.f; cs[nt][1] = 0.f; }

#pragma unroll
    for (int mt = 0; mt < 2; mt++) {
#pragma unroll
        for (int nt = 0; nt < 8; nt++) {
            const int col = n0 + nw + nt * 8 + c0;
            const float bx = bias[col], by = bias[col + 1];
            const int rowa = m0 + mw + mt * 16 + r0;
            const float vx[2] = {acc[mt][nt][0] + bx, acc[mt][nt][2] + bx};
            const float vy[2] = {acc[mt][nt][1] + by, acc[mt][nt][3] + by};
            if (MODE == 1) {
                *(float2*)(Cout + (size_t)rowa * KDIM + col)       = make_float2(vx[0], vy[0]);
                *(float2*)(Cout + (size_t)(rowa + 8) * KDIM + col) = make_float2(vx[1], vy[1]);
            } else {
                cs[nt][0] += vx[0] + vx[1];
                cs[nt][1] += vy[0] + vy[1];
#pragma unroll
                for (int rr = 0; rr < 2; rr++) {
                    const int row = rowa + rr * 8;
                    if (kind < 2)
                        *(float2*)(g_qkv + (size_t)row * 512 + col) = make_float2(vx[rr], vy[rr]);
                    if (kind >= 1) {
                        const int cc = col - ((kind == 1) ? 256 : 512);
                        const int hh = cc >> 5, w = (cc & 31) >> 1;
                        const int p = row >> 8, j = row & 255;
                        unsigned char* tb = ((kind == 1) ? g_Ktb : g_Vtb)
                                          + ((size_t)(p * 8 + hh)) * 32768 + (size_t)j * 128;
                        const int sw = j & 7;
                        const int hib = (((w >> 2) ^ sw) * 16) + (w & 3) * 4;
                        const int lob = (((4 + (w >> 2)) ^ sw) * 16) + (w & 3) * 4;
                        const __nv_bfloat16 hx = __float2bfloat16(vx[rr]);
                        const __nv_bfloat16 hy = __float2bfloat16(vy[rr]);
                        *(uint32_t*)(tb + hib) = pack_bf(hx, hy);
                        *(uint32_t*)(tb + lob) = pack_bf(
                            __float2bfloat16(vx[rr] - __bfloat162float(hx)),
                            __float2bfloat16(vy[rr] - __bfloat162float(hy)));
                    }
                    if (kind == 2) {
                        const int p = row >> 8, pix = row & 255;
                        const int gy = (p / 7) * 16 + (pix >> 4);
                        const int gx = (p % 7) * 16 + (pix & 15);
                        *(float2*)(g_vimg + ((size_t)(gy * IMG + gx)) * 256 + (col - 512))
                            = make_float2(vx[rr], vy[rr]);
                    }
                }
            }
        }
    }

    if (MODE == 0 && kind < 2) {
        // per-block column sums -> g_part2[m-half][col]
#pragma unroll
        for (int nt = 0; nt < 8; nt++) {
            float a = cs[nt][0], b = cs[nt][1];
#pragma unroll
            for (int o = 4; o < 32; o <<= 1) {
                a += __shfl_xor_sync(0xffffffffu, a, o);
                b += __shfl_xor_sync(0xffffffffu, b, o);
            }
            if (lane < 4) {
                sWsum[wid][nt * 8 + c0]     = a;
                sWsum[wid][nt * 8 + c0 + 1] = b;
            }
        }
        __syncthreads();
        if (tid < 128) {
            const int nwsel = tid >> 6, col = tid & 63;
            const float s = sWsum[nwsel][col] + sWsum[2 + nwsel][col]
                          + sWsum[4 + nwsel][col] + sWsum[6 + nwsel][col];
            g_part2[m0 >> 7][n0 + nwsel * 64 + col] = s;
        }
    }
}

// ---------------------------------------------------------------------------
// Routing: block p: q-row sum, logits vs all k-row sums, top-4.
// ---------------------------------------------------------------------------
__global__ __launch_bounds__(256) void route_k() {
    __shared__ float sq[256];
    __shared__ float slog[64];
    const int p = blockIdx.x, tid = threadIdx.x, wrp = tid >> 5, lane = tid & 31;

    sq[tid] = g_part2[2 * p][tid] + g_part2[2 * p + 1][tid];
    __syncthreads();

    const float q0 = sq[lane * 8 + 0], q1 = sq[lane * 8 + 1];
    const float q2 = sq[lane * 8 + 2], q3 = sq[lane * 8 + 3];
    const float q4 = sq[lane * 8 + 4], q5 = sq[lane * 8 + 5];
    const float q6 = sq[lane * 8 + 6], q7 = sq[lane * 8 + 7];
    for (int j = wrp; j < P2; j += 8) {
        const float4 a0 = *(const float4*)&g_part2[2 * j][256 + lane * 8];
        const float4 a1 = *(const float4*)&g_part2[2 * j][256 + lane * 8 + 4];
        const float4 b0 = *(const float4*)&g_part2[2 * j + 1][256 + lane * 8];
        const float4 b1 = *(const float4*)&g_part2[2 * j + 1][256 + lane * 8 + 4];
        float d = q0 * (a0.x + b0.x) + q1 * (a0.y + b0.y)
                + q2 * (a0.z + b0.z) + q3 * (a0.w + b0.w)
                + q4 * (a1.x + b1.x) + q5 * (a1.y + b1.y)
                + q6 * (a1.z + b1.z) + q7 * (a1.w + b1.w);
#pragma unroll
        for (int o = 16; o > 0; o >>= 1) d += __shfl_xor_sync(0xffffffffu, d, o);
        if (lane == 0) slog[j] = d;
    }
    __syncthreads();

    if (tid == 0) {
        float bv0 = -1e30f, bv1 = -1e30f, bv2 = -1e30f, bv3 = -1e30f;
        int   bi0 = 0, bi1 = 0, bi2 = 0, bi3 = 0;
        for (int j = 0; j < P2; j++) {
            const float s = slog[j];
            if (s > bv3) {
                if (s > bv0)      { bv3=bv2;bi3=bi2; bv2=bv1;bi2=bi1; bv1=bv0;bi1=bi0; bv0=s;bi0=j; }
                else if (s > bv1) { bv3=bv2;bi3=bi2; bv2=bv1;bi2=bi1; bv1=s;bi1=j; }
                else if (s > bv2) { bv3=bv2;bi3=bi2; bv2=s;bi2=j; }
                else              { bv3=s;bi3=j; }
            }
        }
        g_top[p * 4 + 0] = bi0; g_top[p * 4 + 1] = bi1;
        g_top[p * 4 + 2] = bi2; g_top[p * 4 + 3] = bi3;
    }
}

// ---------------------------------------------------------------------------
// Attention, tensor cores, no-max exp2 softmax (range-safe: |logit| <~ 15).
// ---------------------------------------------------------------------------
__global__ __launch_bounds__(256) void attn_mma() {
    __shared__ __align__(128) unsigned char Kt[8192];
    __shared__ __align__(128) unsigned char Vt[8192];
    __shared__ int sidx[4];
    const int p = blockIdx.x, h = blockIdx.y;
    const int tid = threadIdx.x, wid = tid >> 5, lane = tid & 31;
    if (tid < 4) sidx[tid] = g_top[p * 4 + tid];

    const uint32_t sK = smem_u32(Kt), sV = smem_u32(Vt);
    const int r  = lane >> 2;
    const int c2 = (lane & 3) * 2;

    uint32_t qh[2][2][4], ql[2][2][4];
    {
        const float* qb = g_qkv + ((size_t)p * W2 + wid * 32) * 512 + h * 32;
#pragma unroll
        for (int mt = 0; mt < 2; mt++)
#pragma unroll
            for (int ks = 0; ks < 2; ks++)
#pragma unroll
                for (int idx = 0; idx < 4; idx++) {
                    const int row = mt * 16 + r + (idx & 1) * 8;
                    const int col = ks * 16 + (idx >> 1) * 8 + c2;
                    const float2 v = *(const float2*)(qb + (size_t)row * 512 + col);
                    const float f0 = v.x * QSCALE, f1 = v.y * QSCALE;
                    const __nv_bfloat16 h0 = __float2bfloat16(f0), h1 = __float2bfloat16(f1);
                    qh[mt][ks][idx] = pack_bf(h0, h1);
                    ql[mt][ks][idx] = pack_bf(__float2bfloat16(f0 - __bfloat162float(h0)),
                                              __float2bfloat16(f1 - __bfloat162float(h1)));
                }
    }
    __syncthreads();
    const int s0 = sidx[0], s1 = sidx[1], s2 = sidx[2], s3 = sidx[3];

    float l[2][2];
    float outA[2][4][4];
#pragma unroll
    for (int mt = 0; mt < 2; mt++)
#pragma unroll
        for (int hf = 0; hf < 2; hf++) l[mt][hf] = 0.f;
#pragma unroll
    for (int mt = 0; mt < 2; mt++)
#pragma unroll
        for (int ct = 0; ct < 4; ct++)
#pragma unroll
            for (int j = 0; j < 4; j++) outA[mt][ct][j] = 0.f;

    uint4 pk0, pk1, pv0, pv1;
    {
        const size_t b = ((size_t)(s0 * 8 + h)) * 32768 + (size_t)tid * 16;
        pk0 = *(const uint4*)(g_Ktb + b);
        pk1 = *(const uint4*)(g_Ktb + b + 4096);
        pv0 = *(const uint4*)(g_Vtb + b);
        pv1 = *(const uint4*)(g_Vtb + b + 4096);
    }

#pragma unroll 1
    for (int ch = 0; ch < 16; ch++) {
        *(uint4*)(Kt + tid * 16)        = pk0;
        *(uint4*)(Kt + 4096 + tid * 16) = pk1;
        *(uint4*)(Vt + tid * 16)        = pv0;
        *(uint4*)(Vt + 4096 + tid * 16) = pv1;
        __syncthreads();
        if (ch + 1 < 16) {
            const int nc = ch + 1, t = nc >> 2;
            const int sw = (t == 0) ? s0 : (t == 1) ? s1 : (t == 2) ? s2 : s3;
            const size_t b = ((size_t)(sw * 8 + h)) * 32768 + (size_t)(nc & 3) * 8192 + (size_t)tid * 16;
            pk0 = *(const uint4*)(g_Ktb + b);
            pk1 = *(const uint4*)(g_Ktb + b + 4096);
            pv0 = *(const uint4*)(g_Vtb + b);
            pv1 = *(const uint4*)(g_Vtb + b + 4096);
        }

        float s[2][8][4];
#pragma unroll
        for (int mt = 0; mt < 2; mt++)
#pragma unroll
            for (int nt = 0; nt < 8; nt++)
#pragma unroll
                for (int j = 0; j < 4; j++) s[mt][nt][j] = 0.f;

#pragma unroll
        for (int pass = 0; pass < 3; pass++) {
            const int kb = (pass == 1) ? 4 : 0;
#pragma unroll
            for (int ks = 0; ks < 2; ks++) {
                uint32_t bF[8][2];
#pragma unroll
                for (int np = 0; np < 4; np++) {
                    const int row = np * 16 + (lane & 7) + ((lane >> 4) << 3);
                    const int chk = kb + ks * 2 + ((lane >> 3) & 1);
                    uint32_t r0, r1, r2, r3;
                    ldsm_x4(r0, r1, r2, r3, sK + row * 128 + ((chk ^ (row & 7)) * 16));
                    bF[np * 2][0] = r0; bF[np * 2][1] = r1;
                    bF[np * 2 + 1][0] = r2; bF[np * 2 + 1][1] = r3;
                }
#pragma unroll
                for (int mt = 0; mt < 2; mt++) {
                    const uint32_t* aF = (pass == 2) ? ql[mt][ks] : qh[mt][ks];
#pragma unroll
                    for (int nt = 0; nt < 8; nt++)
                        mma16816(s[mt][nt], aF, bF[nt]);
                }
            }
        }

        // exp2 softmax, no max subtraction
#pragma unroll
        for (int mt = 0; mt < 2; mt++)
#pragma unroll
            for (int hf = 0; hf < 2; hf++) {
                float ll = 0.f;
#pragma unroll
                for (int nt = 0; nt < 8; nt++) {
                    const float e0 = exp2f(s[mt][nt][hf * 2]);
                    const float e1 = exp2f(s[mt][nt][hf * 2 + 1]);
                    s[mt][nt][hf * 2]     = e0;
                    s[mt][nt][hf * 2 + 1] = e1;
                    ll += e0 + e1;
                }
                l[mt][hf] += ll;
            }

#pragma unroll
        for (int mt = 0; mt < 2; mt++)
#pragma unroll
            for (int nt = 0; nt < 8; nt++) {
                const float v0 = s[mt][nt][0], v1 = s[mt][nt][1];
                const float v2 = s[mt][nt][2], v3 = s[mt][nt][3];
                const __nv_bfloat16 h0 = __float2bfloat16(v0), h1 = __float2bfloat16(v1);
                const __nv_bfloat16 h2 = __float2bfloat16(v2), h3 = __float2bfloat16(v3);
                s[mt][nt][0] = __uint_as_float(pack_bf(h0, h1));
                s[mt][nt][2] = __uint_as_float(pack_bf(h2, h3));
                s[mt][nt][1] = __uint_as_float(pack_bf(__float2bfloat16(v0 - __bfloat162float(h0)),
                                                       __float2bfloat16(v1 - __bfloat162float(h1))));
                s[mt][nt][3] = __uint_as_float(pack_bf(__float2bfloat16(v2 - __bfloat162float(h2)),
                                                       __float2bfloat16(v3 - __bfloat162float(h3))));
            }

#pragma unroll
        for (int pass = 0; pass < 3; pass++) {
            const int vb = (pass == 1) ? 4 : 0;
            const int pi = (pass == 2) ? 1 : 0;
#pragma unroll
            for (int ks = 0; ks < 4; ks++) {
                uint32_t bV[4][2];
#pragma unroll
                for (int cp = 0; cp < 2; cp++) {
                    const int row = ks * 16 + (lane & 15);
                    const int chk = vb + cp * 2 + (lane >> 4);
                    uint32_t r0, r1, r2, r3;
                    ldsm_x4_t(r0, r1, r2, r3, sV + row * 128 + ((chk ^ (row & 7)) * 16));
                    bV[cp * 2][0] = r0; bV[cp * 2][1] = r1;
                    bV[cp * 2 + 1][0] = r2; bV[cp * 2 + 1][1] = r3;
                }
#pragma unroll
                for (int mt = 0; mt < 2; mt++) {
                    uint32_t aP[4];
                    aP[0] = __float_as_uint(s[mt][2 * ks][pi]);
                    aP[1] = __float_as_uint(s[mt][2 * ks][pi + 2]);
                    aP[2] = __float_as_uint(s[mt][2 * ks + 1][pi]);
                    aP[3] = __float_as_uint(s[mt][2 * ks + 1][pi + 2]);
#pragma unroll
                    for (int ct = 0; ct < 4; ct++)
                        mma16816(outA[mt][ct], aP, bV[ct]);
                }
            }
        }
        __syncthreads();
    }

    const int wy = p / 7, wx = p % 7;
#pragma unroll
    for (int mt = 0; mt < 2; mt++)
#pragma unroll
        for (int hf = 0; hf < 2; hf++) {
            float ls = l[mt][hf];
            ls += __shfl_xor_sync(0xffffffffu, ls, 1);
            ls += __shfl_xor_sync(0xffffffffu, ls, 2);
            const float inv = 1.f / ls;
            const int q = wid * 32 + mt * 16 + r + hf * 8;
            const int gy = wy * 16 + (q >> 4), gx = wx * 16 + (q & 15);
            float* o = g_y + ((size_t)(gy * IMG + gx)) * 256 + h * 32;
#pragma unroll
            for (int ct = 0; ct < 4; ct++) {
                float2 v = {outA[mt][ct][hf * 2] * inv, outA[mt][ct][hf * 2 + 1] * inv};
                *(float2*)(o + ct * 8 + c2) = v;
            }
        }
}

// ---------------------------------------------------------------------------
// LePE + add attn; emit [hi|lo] rows for out-gemm
// ---------------------------------------------------------------------------
__global__ __launch_bounds__(256) void lepe_k(const float* __restrict__ lw,
                                              const float* __restrict__ lb) {
    const int pix = blockIdx.x;
    const int c   = threadIdx.x;
    const int y = pix / IMG, x = pix % IMG;
    float sum = lb[c];
#pragma unroll
    for (int dy = -1; dy <= 1; dy++) {
        const int yy = y + dy;
        if (yy < 0 || yy >= IMG) continue;
#pragma unroll
        for (int dx = -1; dx <= 1; dx++) {
            const int xx = x + dx;
            if (xx < 0 || xx >= IMG) continue;
            const float v = g_vimg[((size_t)(yy * IMG + xx)) * 256 + c];
            sum += v * lw[((dy + 1) * 3 + (dx + 1)) * 256 + c];
        }
    }
    const float tot = g_y[(size_t)pix * 256 + c] + sum;
    const __nv_bfloat16 h = __float2bfloat16(tot);
    g_Yp[(size_t)pix * 512 + c]       = h;
    g_Yp[(size_t)pix * 512 + 256 + c] = __float2bfloat16(tot - __bfloat162float(h));
}

// ---------------------------------------------------------------------------
extern "C" void kernel_launch(void* const* d_in, const int* in_sizes, int n_in,
                              void* d_out, int out_size) {
    const float* x      = (const float*)d_in[0];
    const float* w_qkv  = (const float*)d_in[1];
    const float* b_qkv  = (const float*)d_in[2];
    const float* w_o    = (const float*)d_in[3];
    const float* b_o    = (const float*)d_in[4];
    const float* lepe_w = (const float*)d_in[5];
    const float* lepe_b = (const float*)d_in[6];
    float* out = (float*)d_out;
    (void)in_sizes; (void)n_in; (void)out_size;

    prep_all<<<NQKV + MROWS, 256>>>(w_qkv, w_o, x);                       // 1
    gemm_mma<0><<<dim3(NQKV / 128, MROWS / 128), 256>>>(b_qkv, nullptr);  // 2
    route_k<<<P2, 256>>>();                                               // 3
    attn_mma<<<dim3(P2, 8), 256>>>();                                     // 4 <- ncu
    lepe_k<<<IMG * IMG, 256>>>(lepe_w, lepe_b);                           // 5
    gemm_mma<1><<<dim3(KDIM / 128, MROWS / 128), 256>>>(b_o, out);        // 6
}

// round 8
// speedup vs baseline: 2.7124x; 1.0317x over previous
#include <cuda_runtime.h>
#include <cuda_bf16.h>
#include <cstdint>

// ---------------------------------------------------------------------------
// BiLevelRoutingAttention, B=1, H=W=112, DIM=QK=256, HEADS=8, NWIN=7, TOPK=4
// GEMMs + attention on mma.sync bf16 hi/lo split (3-term, fp32-grade).
// Attention v2: query dim split across grid.z (128 q/CTA, 16 q/warp) to cut
// regs 255 -> <=128 and run 2 CTAs/SM (4 warps/SMSP).
// ---------------------------------------------------------------------------

#define P2     49
#define W2     256
#define MROWS  12544
#define NQKV   768
#define KDIM   256
#define IMG    112
#define QSCALE 0.09016844f   // 256^-0.5 * log2(e)

__device__ float g_qkv [MROWS * 512];              // q|k, stride 512
__device__ float g_vimg[MROWS * 256];              // v, image layout
__device__ float g_part2[98][512];                 // per half-window column sums
__device__ int   g_top [P2 * 4];
__device__ float g_y   [MROWS * 256];              // attn out, image layout
__device__ __nv_bfloat16 g_Ap[MROWS * 512];        // x gathered  [hi|lo]
__device__ __nv_bfloat16 g_Yp[MROWS * 512];        // attn+lepe   [hi|lo]
__device__ __nv_bfloat16 g_Bq[NQKV * 512];         // w_qkv^T     [hi|lo]
__device__ __nv_bfloat16 g_Bo[KDIM * 512];         // w_o^T       [hi|lo]
__device__ unsigned char g_Ktb[P2 * 8 * 32768];
__device__ unsigned char g_Vtb[P2 * 8 * 32768];

__device__ __forceinline__ uint32_t smem_u32(const void* p) {
    uint32_t a;
    asm("{ .reg .u64 t; cvta.to.shared.u64 t, %1; cvt.u32.u64 %0, t; }" : "=r"(a) : "l"(p));
    return a;
}
__device__ __forceinline__ uint32_t pack_bf(__nv_bfloat16 lo, __nv_bfloat16 hi) {
    return ((uint32_t)__bfloat16_as_ushort(hi) << 16) | __bfloat16_as_ushort(lo);
}
__device__ __forceinline__ void ldsm_x4(uint32_t& r0, uint32_t& r1, uint32_t& r2, uint32_t& r3, uint32_t a) {
    asm volatile("ldmatrix.sync.aligned.m8n8.x4.shared.b16 {%0,%1,%2,%3}, [%4];"
                 : "=r"(r0), "=r"(r1), "=r"(r2), "=r"(r3) : "r"(a));
}
__device__ __forceinline__ void ldsm_x4_t(uint32_t& r0, uint32_t& r1, uint32_t& r2, uint32_t& r3, uint32_t a) {
    asm volatile("ldmatrix.sync.aligned.m8n8.x4.trans.shared.b16 {%0,%1,%2,%3}, [%4];"
                 : "=r"(r0), "=r"(r1), "=r"(r2), "=r"(r3) : "r"(a));
}
__device__ __forceinline__ void mma16816(float* c, const uint32_t* a, const uint32_t* b) {
    asm volatile(
        "mma.sync.aligned.m16n8k16.row.col.f32.bf16.bf16.f32 "
        "{%0,%1,%2,%3}, {%4,%5,%6,%7}, {%8,%9}, {%0,%1,%2,%3};"
        : "+f"(c[0]), "+f"(c[1]), "+f"(c[2]), "+f"(c[3])
        : "r"(a[0]), "r"(a[1]), "r"(a[2]), "r"(a[3]), "r"(b[0]), "r"(b[1]));
}

// virtual k-tile (0..11) -> byte-column base in 512-wide [hi|lo] storage
__device__ __forceinline__ int soffA(int kt) {   // A: hi, hi, lo
    return (kt < 8) ? (kt & 3) * 64 : 256 + (kt & 3) * 64;
}
__device__ __forceinline__ int soffB(int kt) {   // B: hi, lo, hi
    return (kt < 4 || kt >= 8) ? (kt & 3) * 64 : 256 + (kt & 3) * 64;
}

// ---------------------------------------------------------------------------
// Merged prep
// ---------------------------------------------------------------------------
__global__ __launch_bounds__(256) void prep_all(const float* __restrict__ wq,
                                                const float* __restrict__ wo,
                                                const float* __restrict__ x) {
    const int b = blockIdx.x, tid = threadIdx.x;
    if (b < NQKV) {
        const int t = b * 256 + tid;
        const int n = t >> 8, k = t & 255;
        {
            const float v = wq[k * NQKV + n];
            const __nv_bfloat16 h = __float2bfloat16(v);
            g_Bq[n * 512 + k]       = h;
            g_Bq[n * 512 + 256 + k] = __float2bfloat16(v - __bfloat162float(h));
        }
        if (t < KDIM * KDIM) {
            const float v = wo[k * KDIM + n];
            const __nv_bfloat16 h = __float2bfloat16(v);
            g_Bo[n * 512 + k]       = h;
            g_Bo[n * 512 + 256 + k] = __float2bfloat16(v - __bfloat162float(h));
        }
    } else {
        const int m = b - NQKV, c = tid;
        const int p = m >> 8, pix = m & 255;
        const int gy = (p / 7) * 16 + (pix >> 4);
        const int gx = (p % 7) * 16 + (pix & 15);
        const float v = x[(gy * IMG + gx) * KDIM + c];
        const __nv_bfloat16 h = __float2bfloat16(v);
        g_Ap[m * 512 + c]       = h;
        g_Ap[m * 512 + 256 + c] = __float2bfloat16(v - __bfloat162float(h));
    }
}

// ---------------------------------------------------------------------------
// Dense GEMM (validated). MODE 0: fused KV pack + v scatter + column sums.
// ---------------------------------------------------------------------------
template <int MODE>
__global__ __launch_bounds__(256) void gemm_mma(const float* __restrict__ bias,
                                                float* __restrict__ Cout) {
    __shared__ __align__(128) __nv_bfloat16 As[128 * 64];
    __shared__ __align__(128) __nv_bfloat16 Bs[128 * 64];
    __shared__ float sWsum[8][64];

    const __nv_bfloat16* A = (MODE == 0) ? g_Ap : g_Yp;
    const __nv_bfloat16* B = (MODE == 0) ? g_Bq : g_Bo;

    const int tid  = threadIdx.x;
    const int wid  = tid >> 5;
    const int lane = tid & 31;
    const int m0   = blockIdx.y * 128;
    const int n0   = blockIdx.x * 128;
    const int mw   = (wid >> 1) * 32;
    const int nw   = (wid & 1) * 64;

    const uint32_t sA = smem_u32(As), sB = smem_u32(Bs);

    uint4 pa[4], pb[4];
    int grow[4], gchk[4];
#pragma unroll
    for (int i = 0; i < 4; i++) {
        const int idx = tid + 256 * i;
        grow[i] = idx >> 3;
        gchk[i] = idx & 7;
    }
#pragma unroll
    for (int i = 0; i < 4; i++) {
        pa[i] = *(const uint4*)(A + (size_t)(m0 + grow[i]) * 512 + soffA(0) + gchk[i] * 8);
        pb[i] = *(const uint4*)(B + (size_t)(n0 + grow[i]) * 512 + soffB(0) + gchk[i] * 8);
    }

    float acc[2][8][4];
#pragma unroll
    for (int mt = 0; mt < 2; mt++)
#pragma unroll
        for (int nt = 0; nt < 8; nt++)
#pragma unroll
            for (int j = 0; j < 4; j++) acc[mt][nt][j] = 0.f;

    for (int kt = 0; kt < 12; kt++) {
#pragma unroll
        for (int i = 0; i < 4; i++) {
            const int so = grow[i] * 128 + ((gchk[i] ^ (grow[i] & 7)) * 16);
            *(uint4*)((char*)As + so) = pa[i];
            *(uint4*)((char*)Bs + so) = pb[i];
        }
        __syncthreads();
        if (kt + 1 < 12) {
            const int ao = soffA(kt + 1), bo = soffB(kt + 1);
#pragma unroll
            for (int i = 0; i < 4; i++) {
                pa[i] = *(const uint4*)(A + (size_t)(m0 + grow[i]) * 512 + ao + gchk[i] * 8);
                pb[i] = *(const uint4*)(B + (size_t)(n0 + grow[i]) * 512 + bo + gchk[i] * 8);
            }
        }
#pragma unroll
        for (int ks = 0; ks < 4; ks++) {
            uint32_t aF[2][4];
#pragma unroll
            for (int mt = 0; mt < 2; mt++) {
                const int row = mw + mt * 16 + (lane & 15);
                const int chk = ks * 2 + (lane >> 4);
                ldsm_x4(aF[mt][0], aF[mt][1], aF[mt][2], aF[mt][3],
                        sA + row * 128 + ((chk ^ (row & 7)) * 16));
            }
            uint32_t bF[8][2];
#pragma unroll
            for (int np = 0; np < 4; np++) {
                const int row = nw + np * 16 + (lane & 7) + ((lane >> 4) << 3);
                const int chk = ks * 2 + ((lane >> 3) & 1);
                uint32_t r0, r1, r2, r3;
                ldsm_x4(r0, r1, r2, r3, sB + row * 128 + ((chk ^ (row & 7)) * 16));
                bF[np * 2][0] = r0; bF[np * 2][1] = r1;
                bF[np * 2 + 1][0] = r2; bF[np * 2 + 1][1] = r3;
            }
#pragma unroll
            for (int mt = 0; mt < 2; mt++)
#pragma unroll
                for (int nt = 0; nt < 8; nt++)
                    mma16816(acc[mt][nt], aF[mt], bF[nt]);
        }
        __syncthreads();
    }

    const int r0 = lane >> 2, c0 = (lane & 3) * 2;
    const int kind = (MODE == 0) ? ((n0 >= 512) ? 2 : ((n0 >= 256) ? 1 : 0)) : 0;

    float cs[8][2];
#pragma unroll
    for (int nt = 0; nt < 8; nt++) { cs[nt][0] = 0.f; cs[nt][1] = 0.f; }

#pragma unroll
    for (int mt = 0; mt < 2; mt++) {
#pragma unroll
        for (int nt = 0; nt < 8; nt++) {
            const int col = n0 + nw + nt * 8 + c0;
            const float bx = bias[col], by = bias[col + 1];
            const int rowa = m0 + mw + mt * 16 + r0;
            const float vx[2] = {acc[mt][nt][0] + bx, acc[mt][nt][2] + bx};
            const float vy[2] = {acc[mt][nt][1] + by, acc[mt][nt][3] + by};
            if (MODE == 1) {
                *(float2*)(Cout + (size_t)rowa * KDIM + col)       = make_float2(vx[0], vy[0]);
                *(float2*)(Cout + (size_t)(rowa + 8) * KDIM + col) = make_float2(vx[1], vy[1]);
            } else {
                cs[nt][0] += vx[0] + vx[1];
                cs[nt][1] += vy[0] + vy[1];
#pragma unroll
                for (int rr = 0; rr < 2; rr++) {
                    const int row = rowa + rr * 8;
                    if (kind < 2)
                        *(float2*)(g_qkv + (size_t)row * 512 + col) = make_float2(vx[rr], vy[rr]);
                    if (kind >= 1) {
                        const int cc = col - ((kind == 1) ? 256 : 512);
                        const int hh = cc >> 5, w = (cc & 31) >> 1;
                        const int p = row >> 8, j = row & 255;
                        unsigned char* tb = ((kind == 1) ? g_Ktb : g_Vtb)
                                          + ((size_t)(p * 8 + hh)) * 32768 + (size_t)j * 128;
                        const int sw = j & 7;
                        const int hib = (((w >> 2) ^ sw) * 16) + (w & 3) * 4;
                        const int lob = (((4 + (w >> 2)) ^ sw) * 16) + (w & 3) * 4;
                        const __nv_bfloat16 hx = __float2bfloat16(vx[rr]);
                        const __nv_bfloat16 hy = __float2bfloat16(vy[rr]);
                        *(uint32_t*)(tb + hib) = pack_bf(hx, hy);
                        *(uint32_t*)(tb + lob) = pack_bf(
                            __float2bfloat16(vx[rr] - __bfloat162float(hx)),
                            __float2bfloat16(vy[rr] - __bfloat162float(hy)));
                    }
                    if (kind == 2) {
                        const int p = row >> 8, pix = row & 255;
                        const int gy = (p / 7) * 16 + (pix >> 4);
                        const int gx = (p % 7) * 16 + (pix & 15);
                        *(float2*)(g_vimg + ((size_t)(gy * IMG + gx)) * 256 + (col - 512))
                            = make_float2(vx[rr], vy[rr]);
                    }
                }
            }
        }
    }

    if (MODE == 0 && kind < 2) {
#pragma unroll
        for (int nt = 0; nt < 8; nt++) {
            float a = cs[nt][0], b = cs[nt][1];
#pragma unroll
            for (int o = 4; o < 32; o <<= 1) {
                a += __shfl_xor_sync(0xffffffffu, a, o);
                b += __shfl_xor_sync(0xffffffffu, b, o);
            }
            if (lane < 4) {
                sWsum[wid][nt * 8 + c0]     = a;
                sWsum[wid][nt * 8 + c0 + 1] = b;
            }
        }
        __syncthreads();
        if (tid < 128) {
            const int nwsel = tid >> 6, col = tid & 63;
            const float s = sWsum[nwsel][col] + sWsum[2 + nwsel][col]
                          + sWsum[4 + nwsel][col] + sWsum[6 + nwsel][col];
            g_part2[m0 >> 7][n0 + nwsel * 64 + col] = s;
        }
    }
}

// ---------------------------------------------------------------------------
// Routing: block p: q-row sum, logits vs all k-row sums, top-4.
// ---------------------------------------------------------------------------
__global__ __launch_bounds__(256) void route_k() {
    __shared__ float sq[256];
    __shared__ float slog[64];
    const int p = blockIdx.x, tid = threadIdx.x, wrp = tid >> 5, lane = tid & 31;

    sq[tid] = g_part2[2 * p][tid] + g_part2[2 * p + 1][tid];
    __syncthreads();

    const float q0 = sq[lane * 8 + 0], q1 = sq[lane * 8 + 1];
    const float q2 = sq[lane * 8 + 2], q3 = sq[lane * 8 + 3];
    const float q4 = sq[lane * 8 + 4], q5 = sq[lane * 8 + 5];
    const float q6 = sq[lane * 8 + 6], q7 = sq[lane * 8 + 7];
    for (int j = wrp; j < P2; j += 8) {
        const float4 a0 = *(const float4*)&g_part2[2 * j][256 + lane * 8];
        const float4 a1 = *(const float4*)&g_part2[2 * j][256 + lane * 8 + 4];
        const float4 b0 = *(const float4*)&g_part2[2 * j + 1][256 + lane * 8];
        const float4 b1 = *(const float4*)&g_part2[2 * j + 1][256 + lane * 8 + 4];
        float d = q0 * (a0.x + b0.x) + q1 * (a0.y + b0.y)
                + q2 * (a0.z + b0.z) + q3 * (a0.w + b0.w)
                + q4 * (a1.x + b1.x) + q5 * (a1.y + b1.y)
                + q6 * (a1.z + b1.z) + q7 * (a1.w + b1.w);
#pragma unroll
        for (int o = 16; o > 0; o >>= 1) d += __shfl_xor_sync(0xffffffffu, d, o);
        if (lane == 0) slog[j] = d;
    }
    __syncthreads();

    if (tid == 0) {
        float bv0 = -1e30f, bv1 = -1e30f, bv2 = -1e30f, bv3 = -1e30f;
        int   bi0 = 0, bi1 = 0, bi2 = 0, bi3 = 0;
        for (int j = 0; j < P2; j++) {
            const float s = slog[j];
            if (s > bv3) {
                if (s > bv0)      { bv3=bv2;bi3=bi2; bv2=bv1;bi2=bi1; bv1=bv0;bi1=bi0; bv0=s;bi0=j; }
                else if (s > bv1) { bv3=bv2;bi3=bi2; bv2=bv1;bi2=bi1; bv1=s;bi1=j; }
                else if (s > bv2) { bv3=bv2;bi3=bi2; bv2=s;bi2=j; }
                else              { bv3=s;bi3=j; }
            }
        }
        g_top[p * 4 + 0] = bi0; g_top[p * 4 + 1] = bi1;
        g_top[p * 4 + 2] = bi2; g_top[p * 4 + 3] = bi3;
    }
}

// ---------------------------------------------------------------------------
// Attention v2: grid (49, 8, 2); CTA = 128 queries, warp = 16 query rows.
// Regs capped for 2 CTAs/SM. No-max exp2 softmax (range-safe).
// ---------------------------------------------------------------------------
__global__ __launch_bounds__(256, 2) void attn_mma() {
    __shared__ __align__(128) unsigned char Kt[8192];
    __shared__ __align__(128) unsigned char Vt[8192];
    __shared__ int sidx[4];
    const int p = blockIdx.x, h = blockIdx.y, qz = blockIdx.z;
    const int tid = threadIdx.x, wid = tid >> 5, lane = tid & 31;
    if (tid < 4) sidx[tid] = g_top[p * 4 + tid];

    const uint32_t sK = smem_u32(Kt), sV = smem_u32(Vt);
    const int r  = lane >> 2;
    const int c2 = (lane & 3) * 2;

    // Q fragments for 16 rows: [ks][4], hi and lo
    uint32_t qh[2][4], ql[2][4];
    {
        const float* qb = g_qkv + ((size_t)p * W2 + qz * 128 + wid * 16) * 512 + h * 32;
#pragma unroll
        for (int ks = 0; ks < 2; ks++)
#pragma unroll
            for (int idx = 0; idx < 4; idx++) {
                const int row = r + (idx & 1) * 8;
                const int col = ks * 16 + (idx >> 1) * 8 + c2;
                const float2 v = *(const float2*)(qb + (size_t)row * 512 + col);
                const float f0 = v.x * QSCALE, f1 = v.y * QSCALE;
                const __nv_bfloat16 h0 = __float2bfloat16(f0), h1 = __float2bfloat16(f1);
                qh[ks][idx] = pack_bf(h0, h1);
                ql[ks][idx] = pack_bf(__float2bfloat16(f0 - __bfloat162float(h0)),
                                      __float2bfloat16(f1 - __bfloat162float(h1)));
            }
    }
    __syncthreads();
    const int s0 = sidx[0], s1 = sidx[1], s2 = sidx[2], s3 = sidx[3];

    float l[2] = {0.f, 0.f};
    float outA[4][4];
#pragma unroll
    for (int ct = 0; ct < 4; ct++)
#pragma unroll
        for (int j = 0; j < 4; j++) outA[ct][j] = 0.f;

    uint4 pk0, pk1, pv0, pv1;
    {
        const size_t b = ((size_t)(s0 * 8 + h)) * 32768 + (size_t)tid * 16;
        pk0 = *(const uint4*)(g_Ktb + b);
        pk1 = *(const uint4*)(g_Ktb + b + 4096);
        pv0 = *(const uint4*)(g_Vtb + b);
        pv1 = *(const uint4*)(g_Vtb + b + 4096);
    }

#pragma unroll 1
    for (int ch = 0; ch < 16; ch++) {
        *(uint4*)(Kt + tid * 16)        = pk0;
        *(uint4*)(Kt + 4096 + tid * 16) = pk1;
        *(uint4*)(Vt + tid * 16)        = pv0;
        *(uint4*)(Vt + 4096 + tid * 16) = pv1;
        __syncthreads();
        if (ch + 1 < 16) {
            const int nc = ch + 1, t = nc >> 2;
            const int sw = (t == 0) ? s0 : (t == 1) ? s1 : (t == 2) ? s2 : s3;
            const size_t b = ((size_t)(sw * 8 + h)) * 32768 + (size_t)(nc & 3) * 8192 + (size_t)tid * 16;
            pk0 = *(const uint4*)(g_Ktb + b);
            pk1 = *(const uint4*)(g_Ktb + b + 4096);
            pv0 = *(const uint4*)(g_Vtb + b);
            pv1 = *(const uint4*)(g_Vtb + b + 4096);
        }

        float s[8][4];
#pragma unroll
        for (int nt = 0; nt < 8; nt++)
#pragma unroll
            for (int j = 0; j < 4; j++) s[nt][j] = 0.f;

#pragma unroll
        for (int pass = 0; pass < 3; pass++) {
            const int kb = (pass == 1) ? 4 : 0;
#pragma unroll
            for (int ks = 0; ks < 2; ks++) {
                const uint32_t* aF = (pass == 2) ? ql[ks] : qh[ks];
#pragma unroll
                for (int np = 0; np < 4; np++) {
                    const int row = np * 16 + (lane & 7) + ((lane >> 4) << 3);
                    const int chk = kb + ks * 2 + ((lane >> 3) & 1);
                    uint32_t b0, b1, b2, b3;
                    ldsm_x4(b0, b1, b2, b3, sK + row * 128 + ((chk ^ (row & 7)) * 16));
                    uint32_t bf0[2] = {b0, b1}, bf1[2] = {b2, b3};
                    mma16816(s[np * 2],     aF, bf0);
                    mma16816(s[np * 2 + 1], aF, bf1);
                }
            }
        }

        // exp2 softmax, no max subtraction
#pragma unroll
        for (int hf = 0; hf < 2; hf++) {
            float ll = 0.f;
#pragma unroll
            for (int nt = 0; nt < 8; nt++) {
                const float e0 = exp2f(s[nt][hf * 2]);
                const float e1 = exp2f(s[nt][hf * 2 + 1]);
                s[nt][hf * 2]     = e0;
                s[nt][hf * 2 + 1] = e1;
                ll += e0 + e1;
            }
            l[hf] += ll;
        }

#pragma unroll
        for (int nt = 0; nt < 8; nt++) {
            const float v0 = s[nt][0], v1 = s[nt][1];
            const float v2 = s[nt][2], v3 = s[nt][3];
            const __nv_bfloat16 h0 = __float2bfloat16(v0), h1 = __float2bfloat16(v1);
            const __nv_bfloat16 h2 = __float2bfloat16(v2), h3 = __float2bfloat16(v3);
            s[nt][0] = __uint_as_float(pack_bf(h0, h1));
            s[nt][2] = __uint_as_float(pack_bf(h2, h3));
            s[nt][1] = __uint_as_float(pack_bf(__float2bfloat16(v0 - __bfloat162float(h0)),
                                               __float2bfloat16(v1 - __bfloat162float(h1))));
            s[nt][3] = __uint_as_float(pack_bf(__float2bfloat16(v2 - __bfloat162float(h2)),
                                               __float2bfloat16(v3 - __bfloat162float(h3))));
        }

#pragma unroll
        for (int pass = 0; pass < 3; pass++) {
            const int vb = (pass == 1) ? 4 : 0;
            const int pi = (pass == 2) ? 1 : 0;
#pragma unroll
            for (int ks = 0; ks < 4; ks++) {
                uint32_t bV[4][2];
#pragma unroll
                for (int cp = 0; cp < 2; cp++) {
                    const int row = ks * 16 + (lane & 15);
                    const int chk = vb + cp * 2 + (lane >> 4);
                    uint32_t b0, b1, b2, b3;
                    ldsm_x4_t(b0, b1, b2, b3, sV + row * 128 + ((chk ^ (row & 7)) * 16));
                    bV[cp * 2][0] = b0; bV[cp * 2][1] = b1;
                    bV[cp * 2 + 1][0] = b2; bV[cp * 2 + 1][1] = b3;
                }
                uint32_t aP[4];
                aP[0] = __float_as_uint(s[2 * ks][pi]);
                aP[1] = __float_as_uint(s[2 * ks][pi + 2]);
                aP[2] = __float_as_uint(s[2 * ks + 1][pi]);
                aP[3] = __float_as_uint(s[2 * ks + 1][pi + 2]);
#pragma unroll
                for (int ct = 0; ct < 4; ct++)
                    mma16816(outA[ct], aP, bV[ct]);
            }
        }
        __syncthreads();
    }

    const int wy = p / 7, wx = p % 7;
#pragma unroll
    for (int hf = 0; hf < 2; hf++) {
        float ls = l[hf];
        ls += __shfl_xor_sync(0xffffffffu, ls, 1);
        ls += __shfl_xor_sync(0xffffffffu, ls, 2);
        const float inv = 1.f / ls;
        const int q = qz * 128 + wid * 16 + r + hf * 8;
        const int gy = wy * 16 + (q >> 4), gx = wx * 16 + (q & 15);
        float* o = g_y + ((size_t)(gy * IMG + gx)) * 256 + h * 32;
#pragma unroll
        for (int ct = 0; ct < 4; ct++) {
            float2 v = {outA[ct][hf * 2] * inv, outA[ct][hf * 2 + 1] * inv};
            *(float2*)(o + ct * 8 + c2) = v;
        }
    }
}

// ---------------------------------------------------------------------------
// LePE + add attn; emit [hi|lo] rows for out-gemm
// ---------------------------------------------------------------------------
__global__ __launch_bounds__(256) void lepe_k(const float* __restrict__ lw,
                                              const float* __restrict__ lb) {
    const int pix = blockIdx.x;
    const int c   = threadIdx.x;
    const int y = pix / IMG, x = pix % IMG;
    float sum = lb[c];
#pragma unroll
    for (int dy = -1; dy <= 1; dy++) {
        const int yy = y + dy;
        if (yy < 0 || yy >= IMG) continue;
#pragma unroll
        for (int dx = -1; dx <= 1; dx++) {
            const int xx = x + dx;
            if (xx < 0 || xx >= IMG) continue;
            const float v = g_vimg[((size_t)(yy * IMG + xx)) * 256 + c];
            sum += v * lw[((dy + 1) * 3 + (dx + 1)) * 256 + c];
        }
    }
    const float tot = g_y[(size_t)pix * 256 + c] + sum;
    const __nv_bfloat16 h = __float2bfloat16(tot);
    g_Yp[(size_t)pix * 512 + c]       = h;
    g_Yp[(size_t)pix * 512 + 256 + c] = __float2bfloat16(tot - __bfloat162float(h));
}

// ---------------------------------------------------------------------------
extern "C" void kernel_launch(void* const* d_in, const int* in_sizes, int n_in,
                              void* d_out, int out_size) {
    const float* x      = (const float*)d_in[0];
    const float* w_qkv  = (const float*)d_in[1];
    const float* b_qkv  = (const float*)d_in[2];
    const float* w_o    = (const float*)d_in[3];
    const float* b_o    = (const float*)d_in[4];
    const float* lepe_w = (const float*)d_in[5];
    const float* lepe_b = (const float*)d_in[6];
    float* out = (float*)d_out;
    (void)in_sizes; (void)n_in; (void)out_size;

    prep_all<<<NQKV + MROWS, 256>>>(w_qkv, w_o, x);                       // 1
    gemm_mma<0><<<dim3(NQKV / 128, MROWS / 128), 256>>>(b_qkv, nullptr);  // 2
    route_k<<<P2, 256>>>();                                               // 3
    attn_mma<<<dim3(P2, 8, 2), 256>>>();                                  // 4 <- ncu
    lepe_k<<<IMG * IMG, 256>>>(lepe_w, lepe_b);                           // 5
    gemm_mma<1><<<dim3(KDIM / 128, MROWS / 128), 256>>>(b_o, out);        // 6
}

// round 9
// speedup vs baseline: 2.9974x; 1.1051x over previous
#include <cuda_runtime.h>
#include <cuda_bf16.h>
#include <cstdint>

// ---------------------------------------------------------------------------
// BiLevelRoutingAttention, B=1, H=W=112, DIM=QK=256, HEADS=8, NWIN=7, TOPK=4
// GEMMs + attention on mma.sync bf16 hi/lo split (3-term, fp32-grade).
// Attention v3: double-buffered K/V smem (1 sync/chunk), dedup K ldsm,
// PV 2-pass (P kept bf16-hi only; ~4e-4 output error, threshold 1e-3).
// ---------------------------------------------------------------------------

#define P2     49
#define W2     256
#define MROWS  12544
#define NQKV   768
#define KDIM   256
#define IMG    112
#define QSCALE 0.09016844f   // 256^-0.5 * log2(e)

__device__ float g_qkv [MROWS * 512];              // q|k, stride 512
__device__ float g_vimg[MROWS * 256];              // v, image layout
__device__ float g_part2[98][512];                 // per half-window column sums
__device__ int   g_top [P2 * 4];
__device__ float g_y   [MROWS * 256];              // attn out, image layout
__device__ __nv_bfloat16 g_Ap[MROWS * 512];        // x gathered  [hi|lo]
__device__ __nv_bfloat16 g_Yp[MROWS * 512];        // attn+lepe   [hi|lo]
__device__ __nv_bfloat16 g_Bq[NQKV * 512];         // w_qkv^T     [hi|lo]
__device__ __nv_bfloat16 g_Bo[KDIM * 512];         // w_o^T       [hi|lo]
__device__ unsigned char g_Ktb[P2 * 8 * 32768];
__device__ unsigned char g_Vtb[P2 * 8 * 32768];

__device__ __forceinline__ uint32_t smem_u32(const void* p) {
    uint32_t a;
    asm("{ .reg .u64 t; cvta.to.shared.u64 t, %1; cvt.u32.u64 %0, t; }" : "=r"(a) : "l"(p));
    return a;
}
__device__ __forceinline__ uint32_t pack_bf(__nv_bfloat16 lo, __nv_bfloat16 hi) {
    return ((uint32_t)__bfloat16_as_ushort(hi) << 16) | __bfloat16_as_ushort(lo);
}
__device__ __forceinline__ void ldsm_x4(uint32_t& r0, uint32_t& r1, uint32_t& r2, uint32_t& r3, uint32_t a) {
    asm volatile("ldmatrix.sync.aligned.m8n8.x4.shared.b16 {%0,%1,%2,%3}, [%4];"
                 : "=r"(r0), "=r"(r1), "=r"(r2), "=r"(r3) : "r"(a));
}
__device__ __forceinline__ void ldsm_x4_t(uint32_t& r0, uint32_t& r1, uint32_t& r2, uint32_t& r3, uint32_t a) {
    asm volatile("ldmatrix.sync.aligned.m8n8.x4.trans.shared.b16 {%0,%1,%2,%3}, [%4];"
                 : "=r"(r0), "=r"(r1), "=r"(r2), "=r"(r3) : "r"(a));
}
__device__ __forceinline__ void mma16816(float* c, const uint32_t* a, const uint32_t* b) {
    asm volatile(
        "mma.sync.aligned.m16n8k16.row.col.f32.bf16.bf16.f32 "
        "{%0,%1,%2,%3}, {%4,%5,%6,%7}, {%8,%9}, {%0,%1,%2,%3};"
        : "+f"(c[0]), "+f"(c[1]), "+f"(c[2]), "+f"(c[3])
        : "r"(a[0]), "r"(a[1]), "r"(a[2]), "r"(a[3]), "r"(b[0]), "r"(b[1]));
}

// virtual k-tile (0..11) -> byte-column base in 512-wide [hi|lo] storage
__device__ __forceinline__ int soffA(int kt) {   // A: hi, hi, lo
    return (kt < 8) ? (kt & 3) * 64 : 256 + (kt & 3) * 64;
}
__device__ __forceinline__ int soffB(int kt) {   // B: hi, lo, hi
    return (kt < 4 || kt >= 8) ? (kt & 3) * 64 : 256 + (kt & 3) * 64;
}

// ---------------------------------------------------------------------------
// Merged prep
// ---------------------------------------------------------------------------
__global__ __launch_bounds__(256) void prep_all(const float* __restrict__ wq,
                                                const float* __restrict__ wo,
                                                const float* __restrict__ x) {
    const int b = blockIdx.x, tid = threadIdx.x;
    if (b < NQKV) {
        const int t = b * 256 + tid;
        const int n = t >> 8, k = t & 255;
        {
            const float v = wq[k * NQKV + n];
            const __nv_bfloat16 h = __float2bfloat16(v);
            g_Bq[n * 512 + k]       = h;
            g_Bq[n * 512 + 256 + k] = __float2bfloat16(v - __bfloat162float(h));
        }
        if (t < KDIM * KDIM) {
            const float v = wo[k * KDIM + n];
            const __nv_bfloat16 h = __float2bfloat16(v);
            g_Bo[n * 512 + k]       = h;
            g_Bo[n * 512 + 256 + k] = __float2bfloat16(v - __bfloat162float(h));
        }
    } else {
        const int m = b - NQKV, c = tid;
        const int p = m >> 8, pix = m & 255;
        const int gy = (p / 7) * 16 + (pix >> 4);
        const int gx = (p % 7) * 16 + (pix & 15);
        const float v = x[(gy * IMG + gx) * KDIM + c];
        const __nv_bfloat16 h = __float2bfloat16(v);
        g_Ap[m * 512 + c]       = h;
        g_Ap[m * 512 + 256 + c] = __float2bfloat16(v - __bfloat162float(h));
    }
}

// ---------------------------------------------------------------------------
// Dense GEMM (validated). MODE 0: fused KV pack + v scatter + column sums.
// ---------------------------------------------------------------------------
template <int MODE>
__global__ __launch_bounds__(256) void gemm_mma(const float* __restrict__ bias,
                                                float* __restrict__ Cout) {
    __shared__ __align__(128) __nv_bfloat16 As[128 * 64];
    __shared__ __align__(128) __nv_bfloat16 Bs[128 * 64];
    __shared__ float sWsum[8][64];

    const __nv_bfloat16* A = (MODE == 0) ? g_Ap : g_Yp;
    const __nv_bfloat16* B = (MODE == 0) ? g_Bq : g_Bo;

    const int tid  = threadIdx.x;
    const int wid  = tid >> 5;
    const int lane = tid & 31;
    const int m0   = blockIdx.y * 128;
    const int n0   = blockIdx.x * 128;
    const int mw   = (wid >> 1) * 32;
    const int nw   = (wid & 1) * 64;

    const uint32_t sA = smem_u32(As), sB = smem_u32(Bs);

    uint4 pa[4], pb[4];
    int grow[4], gchk[4];
#pragma unroll
    for (int i = 0; i < 4; i++) {
        const int idx = tid + 256 * i;
        grow[i] = idx >> 3;
        gchk[i] = idx & 7;
    }
#pragma unroll
    for (int i = 0; i < 4; i++) {
        pa[i] = *(const uint4*)(A + (size_t)(m0 + grow[i]) * 512 + soffA(0) + gchk[i] * 8);
        pb[i] = *(const uint4*)(B + (size_t)(n0 + grow[i]) * 512 + soffB(0) + gchk[i] * 8);
    }

    float acc[2][8][4];
#pragma unroll
    for (int mt = 0; mt < 2; mt++)
#pragma unroll
        for (int nt = 0; nt < 8; nt++)
#pragma unroll
            for (int j = 0; j < 4; j++) acc[mt][nt][j] = 0.f;

    for (int kt = 0; kt < 12; kt++) {
#pragma unroll
        for (int i = 0; i < 4; i++) {
            const int so = grow[i] * 128 + ((gchk[i] ^ (grow[i] & 7)) * 16);
            *(uint4*)((char*)As + so) = pa[i];
            *(uint4*)((char*)Bs + so) = pb[i];
        }
        __syncthreads();
        if (kt + 1 < 12) {
            const int ao = soffA(kt + 1), bo = soffB(kt + 1);
#pragma unroll
            for (int i = 0; i < 4; i++) {
                pa[i] = *(const uint4*)(A + (size_t)(m0 + grow[i]) * 512 + ao + gchk[i] * 8);
                pb[i] = *(const uint4*)(B + (size_t)(n0 + grow[i]) * 512 + bo + gchk[i] * 8);
            }
        }
#pragma unroll
        for (int ks = 0; ks < 4; ks++) {
            uint32_t aF[2][4];
#pragma unroll
            for (int mt = 0; mt < 2; mt++) {
                const int row = mw + mt * 16 + (lane & 15);
                const int chk = ks * 2 + (lane >> 4);
                ldsm_x4(aF[mt][0], aF[mt][1], aF[mt][2], aF[mt][3],
                        sA + row * 128 + ((chk ^ (row & 7)) * 16));
            }
            uint32_t bF[8][2];
#pragma unroll
            for (int np = 0; np < 4; np++) {
                const int row = nw + np * 16 + (lane & 7) + ((lane >> 4) << 3);
                const int chk = ks * 2 + ((lane >> 3) & 1);
                uint32_t r0, r1, r2, r3;
                ldsm_x4(r0, r1, r2, r3, sB + row * 128 + ((chk ^ (row & 7)) * 16));
                bF[np * 2][0] = r0; bF[np * 2][1] = r1;
                bF[np * 2 + 1][0] = r2; bF[np * 2 + 1][1] = r3;
            }
#pragma unroll
            for (int mt = 0; mt < 2; mt++)
#pragma unroll
                for (int nt = 0; nt < 8; nt++)
                    mma16816(acc[mt][nt], aF[mt], bF[nt]);
        }
        __syncthreads();
    }

    const int r0 = lane >> 2, c0 = (lane & 3) * 2;
    const int kind = (MODE == 0) ? ((n0 >= 512) ? 2 : ((n0 >= 256) ? 1 : 0)) : 0;

    float cs[8][2];
#pragma unroll
    for (int nt = 0; nt < 8; nt++) { cs[nt][0] = 0.f; cs[nt][1] = 0.f; }

#pragma unroll
    for (int mt = 0; mt < 2; mt++) {
#pragma unroll
        for (int nt = 0; nt < 8; nt++) {
            const int col = n0 + nw + nt * 8 + c0;
            const float bx = bias[col], by = bias[col + 1];
            const int rowa = m0 + mw + mt * 16 + r0;
            const float vx[2] = {acc[mt][nt][0] + bx, acc[mt][nt][2] + bx};
            const float vy[2] = {acc[mt][nt][1] + by, acc[mt][nt][3] + by};
            if (MODE == 1) {
                *(float2*)(Cout + (size_t)rowa * KDIM + col)       = make_float2(vx[0], vy[0]);
                *(float2*)(Cout + (size_t)(rowa + 8) * KDIM + col) = make_float2(vx[1], vy[1]);
            } else {
                cs[nt][0] += vx[0] + vx[1];
                cs[nt][1] += vy[0] + vy[1];
#pragma unroll
                for (int rr = 0; rr < 2; rr++) {
                    const int row = rowa + rr * 8;
                    if (kind < 2)
                        *(float2*)(g_qkv + (size_t)row * 512 + col) = make_float2(vx[rr], vy[rr]);
                    if (kind >= 1) {
                        const int cc = col - ((kind == 1) ? 256 : 512);
                        const int hh = cc >> 5, w = (cc & 31) >> 1;
                        const int p = row >> 8, j = row & 255;
                        unsigned char* tb = ((kind == 1) ? g_Ktb : g_Vtb)
                                          + ((size_t)(p * 8 + hh)) * 32768 + (size_t)j * 128;
                        const int sw = j & 7;
                        const int hib = (((w >> 2) ^ sw) * 16) + (w & 3) * 4;
                        const int lob = (((4 + (w >> 2)) ^ sw) * 16) + (w & 3) * 4;
                        const __nv_bfloat16 hx = __float2bfloat16(vx[rr]);
                        const __nv_bfloat16 hy = __float2bfloat16(vy[rr]);
                        *(uint32_t*)(tb + hib) = pack_bf(hx, hy);
                        *(uint32_t*)(tb + lob) = pack_bf(
                            __float2bfloat16(vx[rr] - __bfloat162float(hx)),
                            __float2bfloat16(vy[rr] - __bfloat162float(hy)));
                    }
                    if (kind == 2) {
                        const int p = row >> 8, pix = row & 255;
                        const int gy = (p / 7) * 16 + (pix >> 4);
                        const int gx = (p % 7) * 16 + (pix & 15);
                        *(float2*)(g_vimg + ((size_t)(gy * IMG + gx)) * 256 + (col - 512))
                            = make_float2(vx[rr], vy[rr]);
                    }
                }
            }
        }
    }

    if (MODE == 0 && kind < 2) {
#pragma unroll
        for (int nt = 0; nt < 8; nt++) {
            float a = cs[nt][0], b = cs[nt][1];
#pragma unroll
            for (int o = 4; o < 32; o <<= 1) {
                a += __shfl_xor_sync(0xffffffffu, a, o);
                b += __shfl_xor_sync(0xffffffffu, b, o);
            }
            if (lane < 4) {
                sWsum[wid][nt * 8 + c0]     = a;
                sWsum[wid][nt * 8 + c0 + 1] = b;
            }
        }
        __syncthreads();
        if (tid < 128) {
            const int nwsel = tid >> 6, col = tid & 63;
            const float s = sWsum[nwsel][col] + sWsum[2 + nwsel][col]
                          + sWsum[4 + nwsel][col] + sWsum[6 + nwsel][col];
            g_part2[m0 >> 7][n0 + nwsel * 64 + col] = s;
        }
    }
}

// ---------------------------------------------------------------------------
// Routing: block p: q-row sum, logits vs all k-row sums, top-4.
// ---------------------------------------------------------------------------
__global__ __launch_bounds__(256) void route_k() {
    __shared__ float sq[256];
    __shared__ float slog[64];
    const int p = blockIdx.x, tid = threadIdx.x, wrp = tid >> 5, lane = tid & 31;

    sq[tid] = g_part2[2 * p][tid] + g_part2[2 * p + 1][tid];
    __syncthreads();

    const float q0 = sq[lane * 8 + 0], q1 = sq[lane * 8 + 1];
    const float q2 = sq[lane * 8 + 2], q3 = sq[lane * 8 + 3];
    const float q4 = sq[lane * 8 + 4], q5 = sq[lane * 8 + 5];
    const float q6 = sq[lane * 8 + 6], q7 = sq[lane * 8 + 7];
    for (int j = wrp; j < P2; j += 8) {
        const float4 a0 = *(const float4*)&g_part2[2 * j][256 + lane * 8];
        const float4 a1 = *(const float4*)&g_part2[2 * j][256 + lane * 8 + 4];
        const float4 b0 = *(const float4*)&g_part2[2 * j + 1][256 + lane * 8];
        const float4 b1 = *(const float4*)&g_part2[2 * j + 1][256 + lane * 8 + 4];
        float d = q0 * (a0.x + b0.x) + q1 * (a0.y + b0.y)
                + q2 * (a0.z + b0.z) + q3 * (a0.w + b0.w)
                + q4 * (a1.x + b1.x) + q5 * (a1.y + b1.y)
                + q6 * (a1.z + b1.z) + q7 * (a1.w + b1.w);
#pragma unroll
        for (int o = 16; o > 0; o >>= 1) d += __shfl_xor_sync(0xffffffffu, d, o);
        if (lane == 0) slog[j] = d;
    }
    __syncthreads();

    if (tid == 0) {
        float bv0 = -1e30f, bv1 = -1e30f, bv2 = -1e30f, bv3 = -1e30f;
        int   bi0 = 0, bi1 = 0, bi2 = 0, bi3 = 0;
        for (int j = 0; j < P2; j++) {
            const float s = slog[j];
            if (s > bv3) {
                if (s > bv0)      { bv3=bv2;bi3=bi2; bv2=bv1;bi2=bi1; bv1=bv0;bi1=bi0; bv0=s;bi0=j; }
                else if (s > bv1) { bv3=bv2;bi3=bi2; bv2=bv1;bi2=bi1; bv1=s;bi1=j; }
                else if (s > bv2) { bv3=bv2;bi3=bi2; bv2=s;bi2=j; }
                else              { bv3=s;bi3=j; }
            }
        }
        g_top[p * 4 + 0] = bi0; g_top[p * 4 + 1] = bi1;
        g_top[p * 4 + 2] = bi2; g_top[p * 4 + 3] = bi3;
    }
}

// ---------------------------------------------------------------------------
// Attention v3: grid (49, 8, 2); CTA = 128 q, warp = 16 q rows, 2 CTAs/SM.
// Double-buffered K/V smem, 1 sync/chunk. QK 3-term with dedup K loads.
// PV 2-term: P as bf16-hi only (x V-hi + V-lo).
// ---------------------------------------------------------------------------
__global__ __launch_bounds__(256, 2) void attn_mma() {
    __shared__ __align__(128) unsigned char Kt[16384];   // 2 buffers x 8KB
    __shared__ __align__(128) unsigned char Vt[16384];
    __shared__ int sidx[4];
    const int p = blockIdx.x, h = blockIdx.y, qz = blockIdx.z;
    const int tid = threadIdx.x, wid = tid >> 5, lane = tid & 31;
    if (tid < 4) sidx[tid] = g_top[p * 4 + tid];

    const uint32_t sK = smem_u32(Kt), sV = smem_u32(Vt);
    const int r  = lane >> 2;
    const int c2 = (lane & 3) * 2;

    // Q fragments for 16 rows: [ks][4], hi and lo
    uint32_t qh[2][4], ql[2][4];
    {
        const float* qb = g_qkv + ((size_t)p * W2 + qz * 128 + wid * 16) * 512 + h * 32;
#pragma unroll
        for (int ks = 0; ks < 2; ks++)
#pragma unroll
            for (int idx = 0; idx < 4; idx++) {
                const int row = r + (idx & 1) * 8;
                const int col = ks * 16 + (idx >> 1) * 8 + c2;
                const float2 v = *(const float2*)(qb + (size_t)row * 512 + col);
                const float f0 = v.x * QSCALE, f1 = v.y * QSCALE;
                const __nv_bfloat16 h0 = __float2bfloat16(f0), h1 = __float2bfloat16(f1);
                qh[ks][idx] = pack_bf(h0, h1);
                ql[ks][idx] = pack_bf(__float2bfloat16(f0 - __bfloat162float(h0)),
                                      __float2bfloat16(f1 - __bfloat162float(h1)));
            }
    }
    __syncthreads();
    const int s0 = sidx[0], s1 = sidx[1], s2 = sidx[2], s3 = sidx[3];

    float l[2] = {0.f, 0.f};
    float outA[4][4];
#pragma unroll
    for (int ct = 0; ct < 4; ct++)
#pragma unroll
        for (int j = 0; j < 4; j++) outA[ct][j] = 0.f;

    // prefetch chunk 0
    uint4 pk0, pk1, pv0, pv1;
    {
        const size_t b = ((size_t)(s0 * 8 + h)) * 32768 + (size_t)tid * 16;
        pk0 = *(const uint4*)(g_Ktb + b);
        pk1 = *(const uint4*)(g_Ktb + b + 4096);
        pv0 = *(const uint4*)(g_Vtb + b);
        pv1 = *(const uint4*)(g_Vtb + b + 4096);
    }
    // fill buffer 0
    *(uint4*)(Kt + tid * 16)        = pk0;
    *(uint4*)(Kt + 4096 + tid * 16) = pk1;
    *(uint4*)(Vt + tid * 16)        = pv0;
    *(uint4*)(Vt + 4096 + tid * 16) = pv1;
    __syncthreads();

#pragma unroll 1
    for (int ch = 0; ch < 16; ch++) {
        const int cb = (ch & 1) * 8192;
        const bool more = (ch + 1 < 16);
        if (more) {
            const int nc = ch + 1, t = nc >> 2;
            const int sw = (t == 0) ? s0 : (t == 1) ? s1 : (t == 2) ? s2 : s3;
            const size_t b = ((size_t)(sw * 8 + h)) * 32768 + (size_t)(nc & 3) * 8192 + (size_t)tid * 16;
            pk0 = *(const uint4*)(g_Ktb + b);
            pk1 = *(const uint4*)(g_Ktb + b + 4096);
            pv0 = *(const uint4*)(g_Vtb + b);
            pv1 = *(const uint4*)(g_Vtb + b + 4096);
        }

        float s[8][4];
#pragma unroll
        for (int nt = 0; nt < 8; nt++)
#pragma unroll
            for (int j = 0; j < 4; j++) s[nt][j] = 0.f;

        // ---- QK^T: K-hi feeds qh and ql; K-lo feeds qh only ----
#pragma unroll
        for (int ks = 0; ks < 2; ks++) {
#pragma unroll
            for (int np = 0; np < 4; np++) {
                const int row = np * 16 + (lane & 7) + ((lane >> 4) << 3);
                const int chk = ks * 2 + ((lane >> 3) & 1);
                uint32_t b0, b1, b2, b3;
                ldsm_x4(b0, b1, b2, b3, sK + cb + row * 128 + ((chk ^ (row & 7)) * 16));
                uint32_t f0[2] = {b0, b1}, f1[2] = {b2, b3};
                mma16816(s[np * 2],     qh[ks], f0);
                mma16816(s[np * 2 + 1], qh[ks], f1);
                mma16816(s[np * 2],     ql[ks], f0);
                mma16816(s[np * 2 + 1], ql[ks], f1);
            }
#pragma unroll
            for (int np = 0; np < 4; np++) {
                const int row = np * 16 + (lane & 7) + ((lane >> 4) << 3);
                const int chk = 4 + ks * 2 + ((lane >> 3) & 1);
                uint32_t b0, b1, b2, b3;
                ldsm_x4(b0, b1, b2, b3, sK + cb + row * 128 + ((chk ^ (row & 7)) * 16));
                uint32_t f0[2] = {b0, b1}, f1[2] = {b2, b3};
                mma16816(s[np * 2],     qh[ks], f0);
                mma16816(s[np * 2 + 1], qh[ks], f1);
            }
        }

        // ---- exp2 softmax, no max subtraction (range-safe) ----
#pragma unroll
        for (int hf = 0; hf < 2; hf++) {
            float ll = 0.f;
#pragma unroll
            for (int nt = 0; nt < 8; nt++) {
                const float e0 = exp2f(s[nt][hf * 2]);
                const float e1 = exp2f(s[nt][hf * 2 + 1]);
                s[nt][hf * 2]     = e0;
                s[nt][hf * 2 + 1] = e1;
                ll += e0 + e1;
            }
            l[hf] += ll;
        }

        // ---- pack P hi only ----
#pragma unroll
        for (int nt = 0; nt < 8; nt++) {
            const float v0 = s[nt][0], v1 = s[nt][1];
            const float v2 = s[nt][2], v3 = s[nt][3];
            s[nt][0] = __uint_as_float(pack_bf(__float2bfloat16(v0), __float2bfloat16(v1)));
            s[nt][2] = __uint_as_float(pack_bf(__float2bfloat16(v2), __float2bfloat16(v3)));
        }

        // ---- P*V: P-hi x (V-hi, V-lo) ----
#pragma unroll
        for (int vb = 0; vb < 8; vb += 4) {
#pragma unroll
            for (int ks = 0; ks < 4; ks++) {
                uint32_t bV[4][2];
#pragma unroll
                for (int cp = 0; cp < 2; cp++) {
                    const int row = ks * 16 + (lane & 15);
                    const int chk = vb + cp * 2 + (lane >> 4);
                    uint32_t b0, b1, b2, b3;
                    ldsm_x4_t(b0, b1, b2, b3, sV + cb + row * 128 + ((chk ^ (row & 7)) * 16));
                    bV[cp * 2][0] = b0; bV[cp * 2][1] = b1;
                    bV[cp * 2 + 1][0] = b2; bV[cp * 2 + 1][1] = b3;
                }
                uint32_t aP[4];
                aP[0] = __float_as_uint(s[2 * ks][0]);
                aP[1] = __float_as_uint(s[2 * ks][2]);
                aP[2] = __float_as_uint(s[2 * ks + 1][0]);
                aP[3] = __float_as_uint(s[2 * ks + 1][2]);
#pragma unroll
                for (int ct = 0; ct < 4; ct++)
                    mma16816(outA[ct], aP, bV[ct]);
            }
        }

        // fill the other buffer for next chunk, then publish
        if (more) {
            const int nb = cb ^ 8192;
            *(uint4*)(Kt + nb + tid * 16)        = pk0;
            *(uint4*)(Kt + nb + 4096 + tid * 16) = pk1;
            *(uint4*)(Vt + nb + tid * 16)        = pv0;
            *(uint4*)(Vt + nb + 4096 + tid * 16) = pv1;
        }
        __syncthreads();
    }

    const int wy = p / 7, wx = p % 7;
#pragma unroll
    for (int hf = 0; hf < 2; hf++) {
        float ls = l[hf];
        ls += __shfl_xor_sync(0xffffffffu, ls, 1);
        ls += __shfl_xor_sync(0xffffffffu, ls, 2);
        const float inv = 1.f / ls;
        const int q = qz * 128 + wid * 16 + r + hf * 8;
        const int gy = wy * 16 + (q >> 4), gx = wx * 16 + (q & 15);
        float* o = g_y + ((size_t)(gy * IMG + gx)) * 256 + h * 32;
#pragma unroll
        for (int ct = 0; ct < 4; ct++) {
            float2 v = {outA[ct][hf * 2] * inv, outA[ct][hf * 2 + 1] * inv};
            *(float2*)(o + ct * 8 + c2) = v;
        }
    }
}

// ---------------------------------------------------------------------------
// LePE + add attn; emit [hi|lo] rows for out-gemm
// ---------------------------------------------------------------------------
__global__ __launch_bounds__(256) void lepe_k(const float* __restrict__ lw,
                                              const float* __restrict__ lb) {
    const int pix = blockIdx.x;
    const int c   = threadIdx.x;
    const int y = pix / IMG, x = pix % IMG;
    float sum = lb[c];
#pragma unroll
    for (int dy = -1; dy <= 1; dy++) {
        const int yy = y + dy;
        if (yy < 0 || yy >= IMG) continue;
#pragma unroll
        for (int dx = -1; dx <= 1; dx++) {
            const int xx = x + dx;
            if (xx < 0 || xx >= IMG) continue;
            const float v = g_vimg[((size_t)(yy * IMG + xx)) * 256 + c];
            sum += v * lw[((dy + 1) * 3 + (dx + 1)) * 256 + c];
        }
    }
    const float tot = g_y[(size_t)pix * 256 + c] + sum;
    const __nv_bfloat16 h = __float2bfloat16(tot);
    g_Yp[(size_t)pix * 512 + c]       = h;
    g_Yp[(size_t)pix * 512 + 256 + c] = __float2bfloat16(tot - __bfloat162float(h));
}

// ---------------------------------------------------------------------------
extern "C" void kernel_launch(void* const* d_in, const int* in_sizes, int n_in,
                              void* d_out, int out_size) {
    const float* x      = (const float*)d_in[0];
    const float* w_qkv  = (const float*)d_in[1];
    const float* b_qkv  = (const float*)d_in[2];
    const float* w_o    = (const float*)d_in[3];
    const float* b_o    = (const float*)d_in[4];
    const float* lepe_w = (const float*)d_in[5];
    const float* lepe_b = (const float*)d_in[6];
    float* out = (float*)d_out;
    (void)in_sizes; (void)n_in; (void)out_size;

    prep_all<<<NQKV + MROWS, 256>>>(w_qkv, w_o, x);                       // 1
    gemm_mma<0><<<dim3(NQKV / 128, MROWS / 128), 256>>>(b_qkv, nullptr);  // 2
    route_k<<<P2, 256>>>();                                               // 3
    attn_mma<<<dim3(P2, 8, 2), 256>>>();                                  // 4 <- ncu
    lepe_k<<<IMG * IMG, 256>>>(lepe_w, lepe_b);                           // 5
    gemm_mma<1><<<dim3(KDIM / 128, MROWS / 128), 256>>>(b_o, out);        // 6
}

// round 10
// speedup vs baseline: 3.4660x; 1.1563x over previous
#include <cuda_runtime.h>
#include <cuda_bf16.h>
#include <cuda_fp16.h>
#include <cstdint>

// ---------------------------------------------------------------------------
// BiLevelRoutingAttention, B=1, H=W=112, DIM=QK=256, HEADS=8, NWIN=7, TOPK=4
// Dense GEMMs: mma.sync bf16 hi/lo 3-term. Attention v4: fp16 fragments —
// QK 3-term fp16 (near-exact), PV single-term (P fp16 x V fp16-hi),
// exp2(s-4) no-max softmax, double-buffered K/V smem.
// ---------------------------------------------------------------------------

#define P2     49
#define W2     256
#define MROWS  12544
#define NQKV   768
#define KDIM   256
#define IMG    112
#define QSCALE 0.09016844f   // 256^-0.5 * log2(e)

__device__ float g_qkv [MROWS * 512];              // q|k, stride 512
__device__ float g_vimg[MROWS * 256];              // v, image layout
__device__ float g_part2[98][512];                 // per half-window column sums
__device__ int   g_top [P2 * 4];
__device__ float g_y   [MROWS * 256];              // attn out, image layout
__device__ __nv_bfloat16 g_Ap[MROWS * 512];        // x gathered  [hi|lo]
__device__ __nv_bfloat16 g_Yp[MROWS * 512];        // attn+lepe   [hi|lo]
__device__ __nv_bfloat16 g_Bq[NQKV * 512];         // w_qkv^T     [hi|lo]
__device__ __nv_bfloat16 g_Bo[KDIM * 512];         // w_o^T       [hi|lo]
// Packed K/V tiles (fp16): per (win,h): 256 rows x 128B; row = [hi(32)|lo(32)],
// 16B chunks swizzled by ^(row&7). V-lo never written/used.
__device__ unsigned char g_Ktb[P2 * 8 * 32768];
__device__ unsigned char g_Vtb[P2 * 8 * 32768];

__device__ __forceinline__ uint32_t smem_u32(const void* p) {
    uint32_t a;
    asm("{ .reg .u64 t; cvta.to.shared.u64 t, %1; cvt.u32.u64 %0, t; }" : "=r"(a) : "l"(p));
    return a;
}
__device__ __forceinline__ uint32_t pack_bf(__nv_bfloat16 lo, __nv_bfloat16 hi) {
    return ((uint32_t)__bfloat16_as_ushort(hi) << 16) | __bfloat16_as_ushort(lo);
}
__device__ __forceinline__ uint32_t pack_h2(__half lo, __half hi) {
    return ((uint32_t)__half_as_ushort(hi) << 16) | __half_as_ushort(lo);
}
__device__ __forceinline__ void ldsm_x4(uint32_t& r0, uint32_t& r1, uint32_t& r2, uint32_t& r3, uint32_t a) {
    asm volatile("ldmatrix.sync.aligned.m8n8.x4.shared.b16 {%0,%1,%2,%3}, [%4];"
                 : "=r"(r0), "=r"(r1), "=r"(r2), "=r"(r3) : "r"(a));
}
__device__ __forceinline__ void ldsm_x4_t(uint32_t& r0, uint32_t& r1, uint32_t& r2, uint32_t& r3, uint32_t a) {
    asm volatile("ldmatrix.sync.aligned.m8n8.x4.trans.shared.b16 {%0,%1,%2,%3}, [%4];"
                 : "=r"(r0), "=r"(r1), "=r"(r2), "=r"(r3) : "r"(a));
}
__device__ __forceinline__ void mma16816(float* c, const uint32_t* a, const uint32_t* b) {
    asm volatile(
        "mma.sync.aligned.m16n8k16.row.col.f32.bf16.bf16.f32 "
        "{%0,%1,%2,%3}, {%4,%5,%6,%7}, {%8,%9}, {%0,%1,%2,%3};"
        : "+f"(c[0]), "+f"(c[1]), "+f"(c[2]), "+f"(c[3])
        : "r"(a[0]), "r"(a[1]), "r"(a[2]), "r"(a[3]), "r"(b[0]), "r"(b[1]));
}
__device__ __forceinline__ void mma16816h(float* c, const uint32_t* a, const uint32_t* b) {
    asm volatile(
        "mma.sync.aligned.m16n8k16.row.col.f32.f16.f16.f32 "
        "{%0,%1,%2,%3}, {%4,%5,%6,%7}, {%8,%9}, {%0,%1,%2,%3};"
        : "+f"(c[0]), "+f"(c[1]), "+f"(c[2]), "+f"(c[3])
        : "r"(a[0]), "r"(a[1]), "r"(a[2]), "r"(a[3]), "r"(b[0]), "r"(b[1]));
}

// virtual k-tile (0..11) -> byte-column base in 512-wide [hi|lo] storage
__device__ __forceinline__ int soffA(int kt) {   // A: hi, hi, lo
    return (kt < 8) ? (kt & 3) * 64 : 256 + (kt & 3) * 64;
}
__device__ __forceinline__ int soffB(int kt) {   // B: hi, lo, hi
    return (kt < 4 || kt >= 8) ? (kt & 3) * 64 : 256 + (kt & 3) * 64;
}

// ---------------------------------------------------------------------------
// Merged prep
// ---------------------------------------------------------------------------
__global__ __launch_bounds__(256) void prep_all(const float* __restrict__ wq,
                                                const float* __restrict__ wo,
                                                const float* __restrict__ x) {
    const int b = blockIdx.x, tid = threadIdx.x;
    if (b < NQKV) {
        const int t = b * 256 + tid;
        const int n = t >> 8, k = t & 255;
        {
            const float v = wq[k * NQKV + n];
            const __nv_bfloat16 h = __float2bfloat16(v);
            g_Bq[n * 512 + k]       = h;
            g_Bq[n * 512 + 256 + k] = __float2bfloat16(v - __bfloat162float(h));
        }
        if (t < KDIM * KDIM) {
            const float v = wo[k * KDIM + n];
            const __nv_bfloat16 h = __float2bfloat16(v);
            g_Bo[n * 512 + k]       = h;
            g_Bo[n * 512 + 256 + k] = __float2bfloat16(v - __bfloat162float(h));
        }
    } else {
        const int m = b - NQKV, c = tid;
        const int p = m >> 8, pix = m & 255;
        const int gy = (p / 7) * 16 + (pix >> 4);
        const int gx = (p % 7) * 16 + (pix & 15);
        const float v = x[(gy * IMG + gx) * KDIM + c];
        const __nv_bfloat16 h = __float2bfloat16(v);
        g_Ap[m * 512 + c]       = h;
        g_Ap[m * 512 + 256 + c] = __float2bfloat16(v - __bfloat162float(h));
    }
}

// ---------------------------------------------------------------------------
// Dense GEMM (validated). MODE 0: fused KV pack (fp16) + v scatter + col sums.
// ---------------------------------------------------------------------------
template <int MODE>
__global__ __launch_bounds__(256) void gemm_mma(const float* __restrict__ bias,
                                                float* __restrict__ Cout) {
    __shared__ __align__(128) __nv_bfloat16 As[128 * 64];
    __shared__ __align__(128) __nv_bfloat16 Bs[128 * 64];
    __shared__ float sWsum[8][64];

    const __nv_bfloat16* A = (MODE == 0) ? g_Ap : g_Yp;
    const __nv_bfloat16* B = (MODE == 0) ? g_Bq : g_Bo;

    const int tid  = threadIdx.x;
    const int wid  = tid >> 5;
    const int lane = tid & 31;
    const int m0   = blockIdx.y * 128;
    const int n0   = blockIdx.x * 128;
    const int mw   = (wid >> 1) * 32;
    const int nw   = (wid & 1) * 64;

    const uint32_t sA = smem_u32(As), sB = smem_u32(Bs);

    uint4 pa[4], pb[4];
    int grow[4], gchk[4];
#pragma unroll
    for (int i = 0; i < 4; i++) {
        const int idx = tid + 256 * i;
        grow[i] = idx >> 3;
        gchk[i] = idx & 7;
    }
#pragma unroll
    for (int i = 0; i < 4; i++) {
        pa[i] = *(const uint4*)(A + (size_t)(m0 + grow[i]) * 512 + soffA(0) + gchk[i] * 8);
        pb[i] = *(const uint4*)(B + (size_t)(n0 + grow[i]) * 512 + soffB(0) + gchk[i] * 8);
    }

    float acc[2][8][4];
#pragma unroll
    for (int mt = 0; mt < 2; mt++)
#pragma unroll
        for (int nt = 0; nt < 8; nt++)
#pragma unroll
            for (int j = 0; j < 4; j++) acc[mt][nt][j] = 0.f;

    for (int kt = 0; kt < 12; kt++) {
#pragma unroll
        for (int i = 0; i < 4; i++) {
            const int so = grow[i] * 128 + ((gchk[i] ^ (grow[i] & 7)) * 16);
            *(uint4*)((char*)As + so) = pa[i];
            *(uint4*)((char*)Bs + so) = pb[i];
        }
        __syncthreads();
        if (kt + 1 < 12) {
            const int ao = soffA(kt + 1), bo = soffB(kt + 1);
#pragma unroll
            for (int i = 0; i < 4; i++) {
                pa[i] = *(const uint4*)(A + (size_t)(m0 + grow[i]) * 512 + ao + gchk[i] * 8);
                pb[i] = *(const uint4*)(B + (size_t)(n0 + grow[i]) * 512 + bo + gchk[i] * 8);
            }
        }
#pragma unroll
        for (int ks = 0; ks < 4; ks++) {
            uint32_t aF[2][4];
#pragma unroll
            for (int mt = 0; mt < 2; mt++) {
                const int row = mw + mt * 16 + (lane & 15);
                const int chk = ks * 2 + (lane >> 4);
                ldsm_x4(aF[mt][0], aF[mt][1], aF[mt][2], aF[mt][3],
                        sA + row * 128 + ((chk ^ (row & 7)) * 16));
            }
            uint32_t bF[8][2];
#pragma unroll
            for (int np = 0; np < 4; np++) {
                const int row = nw + np * 16 + (lane & 7) + ((lane >> 4) << 3);
                const int chk = ks * 2 + ((lane >> 3) & 1);
                uint32_t r0, r1, r2, r3;
                ldsm_x4(r0, r1, r2, r3, sB + row * 128 + ((chk ^ (row & 7)) * 16));
                bF[np * 2][0] = r0; bF[np * 2][1] = r1;
                bF[np * 2 + 1][0] = r2; bF[np * 2 + 1][1] = r3;
            }
#pragma unroll
            for (int mt = 0; mt < 2; mt++)
#pragma unroll
                for (int nt = 0; nt < 8; nt++)
                    mma16816(acc[mt][nt], aF[mt], bF[nt]);
        }
        __syncthreads();
    }

    const int r0 = lane >> 2, c0 = (lane & 3) * 2;
    const int kind = (MODE == 0) ? ((n0 >= 512) ? 2 : ((n0 >= 256) ? 1 : 0)) : 0;

    float cs[8][2];
#pragma unroll
    for (int nt = 0; nt < 8; nt++) { cs[nt][0] = 0.f; cs[nt][1] = 0.f; }

#pragma unroll
    for (int mt = 0; mt < 2; mt++) {
#pragma unroll
        for (int nt = 0; nt < 8; nt++) {
            const int col = n0 + nw + nt * 8 + c0;
            const float bx = bias[col], by = bias[col + 1];
            const int rowa = m0 + mw + mt * 16 + r0;
            const float vx[2] = {acc[mt][nt][0] + bx, acc[mt][nt][2] + bx};
            const float vy[2] = {acc[mt][nt][1] + by, acc[mt][nt][3] + by};
            if (MODE == 1) {
                *(float2*)(Cout + (size_t)rowa * KDIM + col)       = make_float2(vx[0], vy[0]);
                *(float2*)(Cout + (size_t)(rowa + 8) * KDIM + col) = make_float2(vx[1], vy[1]);
            } else {
                cs[nt][0] += vx[0] + vx[1];
                cs[nt][1] += vy[0] + vy[1];
#pragma unroll
                for (int rr = 0; rr < 2; rr++) {
                    const int row = rowa + rr * 8;
                    if (kind < 2)
                        *(float2*)(g_qkv + (size_t)row * 512 + col) = make_float2(vx[rr], vy[rr]);
                    if (kind >= 1) {
                        const int cc = col - ((kind == 1) ? 256 : 512);
                        const int hh = cc >> 5, w = (cc & 31) >> 1;
                        const int p = row >> 8, j = row & 255;
                        unsigned char* tb = ((kind == 1) ? g_Ktb : g_Vtb)
                                          + ((size_t)(p * 8 + hh)) * 32768 + (size_t)j * 128;
                        const int sw = j & 7;
                        const int hib = (((w >> 2) ^ sw) * 16) + (w & 3) * 4;
                        const __half hx = __float2half_rn(vx[rr]);
                        const __half hy = __float2half_rn(vy[rr]);
                        *(uint32_t*)(tb + hib) = pack_h2(hx, hy);
                        if (kind == 1) {
                            const int lob = (((4 + (w >> 2)) ^ sw) * 16) + (w & 3) * 4;
                            *(uint32_t*)(tb + lob) = pack_h2(
                                __float2half_rn(vx[rr] - __half2float(hx)),
                                __float2half_rn(vy[rr] - __half2float(hy)));
                        }
                    }
                    if (kind == 2) {
                        const int p = row >> 8, pix = row & 255;
                        const int gy = (p / 7) * 16 + (pix >> 4);
                        const int gx = (p % 7) * 16 + (pix & 15);
                        *(float2*)(g_vimg + ((size_t)(gy * IMG + gx)) * 256 + (col - 512))
                            = make_float2(vx[rr], vy[rr]);
                    }
                }
            }
        }
    }

    if (MODE == 0 && kind < 2) {
#pragma unroll
        for (int nt = 0; nt < 8; nt++) {
            float a = cs[nt][0], b = cs[nt][1];
#pragma unroll
            for (int o = 4; o < 32; o <<= 1) {
                a += __shfl_xor_sync(0xffffffffu, a, o);
                b += __shfl_xor_sync(0xffffffffu, b, o);
            }
            if (lane < 4) {
                sWsum[wid][nt * 8 + c0]     = a;
                sWsum[wid][nt * 8 + c0 + 1] = b;
            }
        }
        __syncthreads();
        if (tid < 128) {
            const int nwsel = tid >> 6, col = tid & 63;
            const float s = sWsum[nwsel][col] + sWsum[2 + nwsel][col]
                          + sWsum[4 + nwsel][col] + sWsum[6 + nwsel][col];
            g_part2[m0 >> 7][n0 + nwsel * 64 + col] = s;
        }
    }
}

// ---------------------------------------------------------------------------
// Routing: block p: q-row sum, logits vs all k-row sums, top-4.
// ---------------------------------------------------------------------------
__global__ __launch_bounds__(256) void route_k() {
    __shared__ float sq[256];
    __shared__ float slog[64];
    const int p = blockIdx.x, tid = threadIdx.x, wrp = tid >> 5, lane = tid & 31;

    sq[tid] = g_part2[2 * p][tid] + g_part2[2 * p + 1][tid];
    __syncthreads();

    const float q0 = sq[lane * 8 + 0], q1 = sq[lane * 8 + 1];
    const float q2 = sq[lane * 8 + 2], q3 = sq[lane * 8 + 3];
    const float q4 = sq[lane * 8 + 4], q5 = sq[lane * 8 + 5];
    const float q6 = sq[lane * 8 + 6], q7 = sq[lane * 8 + 7];
    for (int j = wrp; j < P2; j += 8) {
        const float4 a0 = *(const float4*)&g_part2[2 * j][256 + lane * 8];
        const float4 a1 = *(const float4*)&g_part2[2 * j][256 + lane * 8 + 4];
        const float4 b0 = *(const float4*)&g_part2[2 * j + 1][256 + lane * 8];
        const float4 b1 = *(const float4*)&g_part2[2 * j + 1][256 + lane * 8 + 4];
        float d = q0 * (a0.x + b0.x) + q1 * (a0.y + b0.y)
                + q2 * (a0.z + b0.z) + q3 * (a0.w + b0.w)
                + q4 * (a1.x + b1.x) + q5 * (a1.y + b1.y)
                + q6 * (a1.z + b1.z) + q7 * (a1.w + b1.w);
#pragma unroll
        for (int o = 16; o > 0; o >>= 1) d += __shfl_xor_sync(0xffffffffu, d, o);
        if (lane == 0) slog[j] = d;
    }
    __syncthreads();

    if (tid == 0) {
        float bv0 = -1e30f, bv1 = -1e30f, bv2 = -1e30f, bv3 = -1e30f;
        int   bi0 = 0, bi1 = 0, bi2 = 0, bi3 = 0;
        for (int j = 0; j < P2; j++) {
            const float s = slog[j];
            if (s > bv3) {
                if (s > bv0)      { bv3=bv2;bi3=bi2; bv2=bv1;bi2=bi1; bv1=bv0;bi1=bi0; bv0=s;bi0=j; }
                else if (s > bv1) { bv3=bv2;bi3=bi2; bv2=bv1;bi2=bi1; bv1=s;bi1=j; }
                else if (s > bv2) { bv3=bv2;bi3=bi2; bv2=s;bi2=j; }
                else              { bv3=s;bi3=j; }
            }
        }
        g_top[p * 4 + 0] = bi0; g_top[p * 4 + 1] = bi1;
        g_top[p * 4 + 2] = bi2; g_top[p * 4 + 3] = bi3;
    }
}

// ---------------------------------------------------------------------------
// Attention v4: fp16. grid (49, 8, 2); CTA = 128 q, warp = 16 q rows.
// QK 3-term fp16 (dedup K loads), PV single-term, exp2(s-4) softmax.
// ---------------------------------------------------------------------------
__global__ __launch_bounds__(256, 2) void attn_mma() {
    __shared__ __align__(128) unsigned char Kt[16384];   // 2 buffers x 8KB
    __shared__ __align__(128) unsigned char Vt[16384];
    __shared__ int sidx[4];
    const int p = blockIdx.x, h = blockIdx.y, qz = blockIdx.z;
    const int tid = threadIdx.x, wid = tid >> 5, lane = tid & 31;
    if (tid < 4) sidx[tid] = g_top[p * 4 + tid];

    const uint32_t sK = smem_u32(Kt), sV = smem_u32(Vt);
    const int r  = lane >> 2;
    const int c2 = (lane & 3) * 2;

    // Q fragments (fp16 hi/lo) for 16 rows
    uint32_t qh[2][4], ql[2][4];
    {
        const float* qb = g_qkv + ((size_t)p * W2 + qz * 128 + wid * 16) * 512 + h * 32;
#pragma unroll
        for (int ks = 0; ks < 2; ks++)
#pragma unroll
            for (int idx = 0; idx < 4; idx++) {
                const int row = r + (idx & 1) * 8;
                const int col = ks * 16 + (idx >> 1) * 8 + c2;
                const float2 v = *(const float2*)(qb + (size_t)row * 512 + col);
                const float f0 = v.x * QSCALE, f1 = v.y * QSCALE;
                const __half h0 = __float2half_rn(f0), h1 = __float2half_rn(f1);
                qh[ks][idx] = pack_h2(h0, h1);
                ql[ks][idx] = pack_h2(__float2half_rn(f0 - __half2float(h0)),
                                      __float2half_rn(f1 - __half2float(h1)));
            }
    }
    __syncthreads();
    const int s0 = sidx[0], s1 = sidx[1], s2 = sidx[2], s3 = sidx[3];

    float l[2] = {0.f, 0.f};
    float outA[4][4];
#pragma unroll
    for (int ct = 0; ct < 4; ct++)
#pragma unroll
        for (int j = 0; j < 4; j++) outA[ct][j] = 0.f;

    // prefetch chunk 0
    uint4 pk0, pk1, pv0, pv1;
    {
        const size_t b = ((size_t)(s0 * 8 + h)) * 32768 + (size_t)tid * 16;
        pk0 = *(const uint4*)(g_Ktb + b);
        pk1 = *(const uint4*)(g_Ktb + b + 4096);
        pv0 = *(const uint4*)(g_Vtb + b);
        pv1 = *(const uint4*)(g_Vtb + b + 4096);
    }
    *(uint4*)(Kt + tid * 16)        = pk0;
    *(uint4*)(Kt + 4096 + tid * 16) = pk1;
    *(uint4*)(Vt + tid * 16)        = pv0;
    *(uint4*)(Vt + 4096 + tid * 16) = pv1;
    __syncthreads();

#pragma unroll 1
    for (int ch = 0; ch < 16; ch++) {
        const int cb = (ch & 1) * 8192;
        const bool more = (ch + 1 < 16);
        if (more) {
            const int nc = ch + 1, t = nc >> 2;
            const int sw = (t == 0) ? s0 : (t == 1) ? s1 : (t == 2) ? s2 : s3;
            const size_t b = ((size_t)(sw * 8 + h)) * 32768 + (size_t)(nc & 3) * 8192 + (size_t)tid * 16;
            pk0 = *(const uint4*)(g_Ktb + b);
            pk1 = *(const uint4*)(g_Ktb + b + 4096);
            pv0 = *(const uint4*)(g_Vtb + b);
            pv1 = *(const uint4*)(g_Vtb + b + 4096);
        }

        float s[8][4];
#pragma unroll
        for (int nt = 0; nt < 8; nt++)
#pragma unroll
            for (int j = 0; j < 4; j++) s[nt][j] = 0.f;

        // ---- QK^T (fp16): K-hi feeds qh and ql; K-lo feeds qh only ----
#pragma unroll
        for (int ks = 0; ks < 2; ks++) {
#pragma unroll
            for (int np = 0; np < 4; np++) {
                const int row = np * 16 + (lane & 7) + ((lane >> 4) << 3);
                const int chk = ks * 2 + ((lane >> 3) & 1);
                uint32_t b0, b1, b2, b3;
                ldsm_x4(b0, b1, b2, b3, sK + cb + row * 128 + ((chk ^ (row & 7)) * 16));
                uint32_t f0[2] = {b0, b1}, f1[2] = {b2, b3};
                mma16816h(s[np * 2],     qh[ks], f0);
                mma16816h(s[np * 2 + 1], qh[ks], f1);
                mma16816h(s[np * 2],     ql[ks], f0);
                mma16816h(s[np * 2 + 1], ql[ks], f1);
            }
#pragma unroll
            for (int np = 0; np < 4; np++) {
                const int row = np * 16 + (lane & 7) + ((lane >> 4) << 3);
                const int chk = 4 + ks * 2 + ((lane >> 3) & 1);
                uint32_t b0, b1, b2, b3;
                ldsm_x4(b0, b1, b2, b3, sK + cb + row * 128 + ((chk ^ (row & 7)) * 16));
                uint32_t f0[2] = {b0, b1}, f1[2] = {b2, b3};
                mma16816h(s[np * 2],     qh[ks], f0);
                mma16816h(s[np * 2 + 1], qh[ks], f1);
            }
        }

        // ---- exp2(s - 4) softmax (shift cancels in normalization) ----
#pragma unroll
        for (int hf = 0; hf < 2; hf++) {
            float ll = 0.f;
#pragma unroll
            for (int nt = 0; nt < 8; nt++) {
                const float e0 = exp2f(s[nt][hf * 2]     - 4.0f);
                const float e1 = exp2f(s[nt][hf * 2 + 1] - 4.0f);
                s[nt][hf * 2]     = e0;
                s[nt][hf * 2 + 1] = e1;
                ll += e0 + e1;
            }
            l[hf] += ll;
        }

        // ---- pack P fp16 ----
#pragma unroll
        for (int nt = 0; nt < 8; nt++) {
            const __half2 p0 = __floats2half2_rn(s[nt][0], s[nt][1]);
            const __half2 p1 = __floats2half2_rn(s[nt][2], s[nt][3]);
            s[nt][0] = __uint_as_float(*(const uint32_t*)&p0);
            s[nt][2] = __uint_as_float(*(const uint32_t*)&p1);
        }

        // ---- P*V: single term (P fp16 x V fp16-hi) ----
#pragma unroll
        for (int ks = 0; ks < 4; ks++) {
            uint32_t bV[4][2];
#pragma unroll
            for (int cp = 0; cp < 2; cp++) {
                const int row = ks * 16 + (lane & 15);
                const int chk = cp * 2 + (lane >> 4);
                uint32_t b0, b1, b2, b3;
                ldsm_x4_t(b0, b1, b2, b3, sV + cb + row * 128 + ((chk ^ (row & 7)) * 16));
                bV[cp * 2][0] = b0; bV[cp * 2][1] = b1;
                bV[cp * 2 + 1][0] = b2; bV[cp * 2 + 1][1] = b3;
            }
            uint32_t aP[4];
            aP[0] = __float_as_uint(s[2 * ks][0]);
            aP[1] = __float_as_uint(s[2 * ks][2]);
            aP[2] = __float_as_uint(s[2 * ks + 1][0]);
            aP[3] = __float_as_uint(s[2 * ks + 1][2]);
#pragma unroll
            for (int ct = 0; ct < 4; ct++)
                mma16816h(outA[ct], aP, bV[ct]);
        }

        if (more) {
            const int nb = cb ^ 8192;
            *(uint4*)(Kt + nb + tid * 16)        = pk0;
            *(uint4*)(Kt + nb + 4096 + tid * 16) = pk1;
            *(uint4*)(Vt + nb + tid * 16)        = pv0;
            *(uint4*)(Vt + nb + 4096 + tid * 16) = pv1;
        }
        __syncthreads();
    }

    const int wy = p / 7, wx = p % 7;
#pragma unroll
    for (int hf = 0; hf < 2; hf++) {
        float ls = l[hf];
        ls += __shfl_xor_sync(0xffffffffu, ls, 1);
        ls += __shfl_xor_sync(0xffffffffu, ls, 2);
        const float inv = 1.f / ls;
        const int q = qz * 128 + wid * 16 + r + hf * 8;
        const int gy = wy * 16 + (q >> 4), gx = wx * 16 + (q & 15);
        float* o = g_y + ((size_t)(gy * IMG + gx)) * 256 + h * 32;
#pragma unroll
        for (int ct = 0; ct < 4; ct++) {
            float2 v = {outA[ct][hf * 2] * inv, outA[ct][hf * 2 + 1] * inv};
            *(float2*)(o + ct * 8 + c2) = v;
        }
    }
}

// ---------------------------------------------------------------------------
// LePE + add attn; emit [hi|lo] rows for out-gemm
// ---------------------------------------------------------------------------
__global__ __launch_bounds__(256) void lepe_k(const float* __restrict__ lw,
                                              const float* __restrict__ lb) {
    const int pix = blockIdx.x;
    const int c   = threadIdx.x;
    const int y = pix / IMG, x = pix % IMG;
    float sum = lb[c];
#pragma unroll
    for (int dy = -1; dy <= 1; dy++) {
        const int yy = y + dy;
        if (yy < 0 || yy >= IMG) continue;
#pragma unroll
        for (int dx = -1; dx <= 1; dx++) {
            const int xx = x + dx;
            if (xx < 0 || xx >= IMG) continue;
            const float v = g_vimg[((size_t)(yy * IMG + xx)) * 256 + c];
            sum += v * lw[((dy + 1) * 3 + (dx + 1)) * 256 + c];
        }
    }
    const float tot = g_y[(size_t)pix * 256 + c] + sum;
    const __nv_bfloat16 h = __float2bfloat16(tot);
    g_Yp[(size_t)pix * 512 + c]       = h;
    g_Yp[(size_t)pix * 512 + 256 + c] = __float2bfloat16(tot - __bfloat162float(h));
}

// ---------------------------------------------------------------------------
extern "C" void kernel_launch(void* const* d_in, const int* in_sizes, int n_in,
                              void* d_out, int out_size) {
    const float* x      = (const float*)d_in[0];
    const float* w_qkv  = (const float*)d_in[1];
    const float* b_qkv  = (const float*)d_in[2];
    const float* w_o    = (const float*)d_in[3];
    const float* b_o    = (const float*)d_in[4];
    const float* lepe_w = (const float*)d_in[5];
    const float* lepe_b = (const float*)d_in[6];
    float* out = (float*)d_out;
    (void)in_sizes; (void)n_in; (void)out_size;

    prep_all<<<NQKV + MROWS, 256>>>(w_qkv, w_o, x);                       // 1
    gemm_mma<0><<<dim3(NQKV / 128, MROWS / 128), 256>>>(b_qkv, nullptr);  // 2
    route_k<<<P2, 256>>>();                                               // 3
    attn_mma<<<dim3(P2, 8, 2), 256>>>();                                  // 4 <- ncu
    lepe_k<<<IMG * IMG, 256>>>(lepe_w, lepe_b);                           // 5
    gemm_mma<1><<<dim3(KDIM / 128, MROWS / 128), 256>>>(b_o, out);        // 6
}

// round 11
// speedup vs baseline: 4.1060x; 1.1846x over previous
#include <cuda_runtime.h>
#include <cuda_bf16.h>
#include <cuda_fp16.h>
#include <cstdint>

// ---------------------------------------------------------------------------
// BiLevelRoutingAttention, B=1, H=W=112, DIM=QK=256, HEADS=8, NWIN=7, TOPK=4
// Dense GEMMs: mma.sync bf16 hi/lo 3-term. Attention v5: single-term fp16 QK
// (error ~3.5e-4 in weights), f16x2 ex2 softmax, l via ones-mma, PV fp16.
// ---------------------------------------------------------------------------

#define P2     49
#define W2     256
#define MROWS  12544
#define NQKV   768
#define KDIM   256
#define IMG    112
#define QSCALE 0.09016844f   // 256^-0.5 * log2(e)

__device__ float g_qkv [MROWS * 512];              // q|k, stride 512
__device__ float g_vimg[MROWS * 256];              // v, image layout
__device__ float g_part2[98][512];                 // per half-window column sums
__device__ int   g_top [P2 * 4];
__device__ float g_y   [MROWS * 256];              // attn out, image layout
__device__ __nv_bfloat16 g_Ap[MROWS * 512];        // x gathered  [hi|lo]
__device__ __nv_bfloat16 g_Yp[MROWS * 512];        // attn+lepe   [hi|lo]
__device__ __nv_bfloat16 g_Bq[NQKV * 512];         // w_qkv^T     [hi|lo]
__device__ __nv_bfloat16 g_Bo[KDIM * 512];         // w_o^T       [hi|lo]
// Packed K/V tiles (fp16): per (win,h): 256 rows x 128B; only the hi half
// (chunks 0..3 of each row) is written/read. Swizzle ^(row&7) on 16B chunks.
__device__ unsigned char g_Ktb[P2 * 8 * 32768];
__device__ unsigned char g_Vtb[P2 * 8 * 32768];

__device__ __forceinline__ uint32_t smem_u32(const void* p) {
    uint32_t a;
    asm("{ .reg .u64 t; cvta.to.shared.u64 t, %1; cvt.u32.u64 %0, t; }" : "=r"(a) : "l"(p));
    return a;
}
__device__ __forceinline__ uint32_t pack_h2(__half lo, __half hi) {
    return ((uint32_t)__half_as_ushort(hi) << 16) | __half_as_ushort(lo);
}
// exp2(x - 6) elementwise on a packed pair, fp16 in/out.
__device__ __forceinline__ uint32_t exp2_h2(float hi, float lo) {
    uint32_t d;
    asm("cvt.rn.f16x2.f32 %0, %1, %2;" : "=r"(d) : "f"(hi), "f"(lo));
    asm("sub.f16x2 %0, %0, %1;" : "+r"(d) : "r"(0x46004600u));   // 6.0 | 6.0
    asm("ex2.approx.f16x2 %0, %0;" : "+r"(d));
    return d;
}
__device__ __forceinline__ void ldsm_x4(uint32_t& r0, uint32_t& r1, uint32_t& r2, uint32_t& r3, uint32_t a) {
    asm volatile("ldmatrix.sync.aligned.m8n8.x4.shared.b16 {%0,%1,%2,%3}, [%4];"
                 : "=r"(r0), "=r"(r1), "=r"(r2), "=r"(r3) : "r"(a));
}
__device__ __forceinline__ void ldsm_x4_t(uint32_t& r0, uint32_t& r1, uint32_t& r2, uint32_t& r3, uint32_t a) {
    asm volatile("ldmatrix.sync.aligned.m8n8.x4.trans.shared.b16 {%0,%1,%2,%3}, [%4];"
                 : "=r"(r0), "=r"(r1), "=r"(r2), "=r"(r3) : "r"(a));
}
__device__ __forceinline__ void mma16816(float* c, const uint32_t* a, const uint32_t* b) {
    asm volatile(
        "mma.sync.aligned.m16n8k16.row.col.f32.bf16.bf16.f32 "
        "{%0,%1,%2,%3}, {%4,%5,%6,%7}, {%8,%9}, {%0,%1,%2,%3};"
        : "+f"(c[0]), "+f"(c[1]), "+f"(c[2]), "+f"(c[3])
        : "r"(a[0]), "r"(a[1]), "r"(a[2]), "r"(a[3]), "r"(b[0]), "r"(b[1]));
}
__device__ __forceinline__ void mma16816h(float* c, const uint32_t* a, const uint32_t* b) {
    asm volatile(
        "mma.sync.aligned.m16n8k16.row.col.f32.f16.f16.f32 "
        "{%0,%1,%2,%3}, {%4,%5,%6,%7}, {%8,%9}, {%0,%1,%2,%3};"
        : "+f"(c[0]), "+f"(c[1]), "+f"(c[2]), "+f"(c[3])
        : "r"(a[0]), "r"(a[1]), "r"(a[2]), "r"(a[3]), "r"(b[0]), "r"(b[1]));
}

// virtual k-tile (0..11) -> byte-column base in 512-wide [hi|lo] storage
__device__ __forceinline__ int soffA(int kt) {   // A: hi, hi, lo
    return (kt < 8) ? (kt & 3) * 64 : 256 + (kt & 3) * 64;
}
__device__ __forceinline__ int soffB(int kt) {   // B: hi, lo, hi
    return (kt < 4 || kt >= 8) ? (kt & 3) * 64 : 256 + (kt & 3) * 64;
}

// ---------------------------------------------------------------------------
// Merged prep
// ---------------------------------------------------------------------------
__global__ __launch_bounds__(256) void prep_all(const float* __restrict__ wq,
                                                const float* __restrict__ wo,
                                                const float* __restrict__ x) {
    const int b = blockIdx.x, tid = threadIdx.x;
    if (b < NQKV) {
        const int t = b * 256 + tid;
        const int n = t >> 8, k = t & 255;
        {
            const float v = wq[k * NQKV + n];
            const __nv_bfloat16 h = __float2bfloat16(v);
            g_Bq[n * 512 + k]       = h;
            g_Bq[n * 512 + 256 + k] = __float2bfloat16(v - __bfloat162float(h));
        }
        if (t < KDIM * KDIM) {
            const float v = wo[k * KDIM + n];
            const __nv_bfloat16 h = __float2bfloat16(v);
            g_Bo[n * 512 + k]       = h;
            g_Bo[n * 512 + 256 + k] = __float2bfloat16(v - __bfloat162float(h));
        }
    } else {
        const int m = b - NQKV, c = tid;
        const int p = m >> 8, pix = m & 255;
        const int gy = (p / 7) * 16 + (pix >> 4);
        const int gx = (p % 7) * 16 + (pix & 15);
        const float v = x[(gy * IMG + gx) * KDIM + c];
        const __nv_bfloat16 h = __float2bfloat16(v);
        g_Ap[m * 512 + c]       = h;
        g_Ap[m * 512 + 256 + c] = __float2bfloat16(v - __bfloat162float(h));
    }
}

// ---------------------------------------------------------------------------
// Dense GEMM (validated). MODE 0: fused KV pack (fp16 hi-only) + v scatter +
// window column sums.
// ---------------------------------------------------------------------------
template <int MODE>
__global__ __launch_bounds__(256) void gemm_mma(const float* __restrict__ bias,
                                                float* __restrict__ Cout) {
    __shared__ __align__(128) __nv_bfloat16 As[128 * 64];
    __shared__ __align__(128) __nv_bfloat16 Bs[128 * 64];
    __shared__ float sWsum[8][64];

    const __nv_bfloat16* A = (MODE == 0) ? g_Ap : g_Yp;
    const __nv_bfloat16* B = (MODE == 0) ? g_Bq : g_Bo;

    const int tid  = threadIdx.x;
    const int wid  = tid >> 5;
    const int lane = tid & 31;
    const int m0   = blockIdx.y * 128;
    const int n0   = blockIdx.x * 128;
    const int mw   = (wid >> 1) * 32;
    const int nw   = (wid & 1) * 64;

    const uint32_t sA = smem_u32(As), sB = smem_u32(Bs);

    uint4 pa[4], pb[4];
    int grow[4], gchk[4];
#pragma unroll
    for (int i = 0; i < 4; i++) {
        const int idx = tid + 256 * i;
        grow[i] = idx >> 3;
        gchk[i] = idx & 7;
    }
#pragma unroll
    for (int i = 0; i < 4; i++) {
        pa[i] = *(const uint4*)(A + (size_t)(m0 + grow[i]) * 512 + soffA(0) + gchk[i] * 8);
        pb[i] = *(const uint4*)(B + (size_t)(n0 + grow[i]) * 512 + soffB(0) + gchk[i] * 8);
    }

    float acc[2][8][4];
#pragma unroll
    for (int mt = 0; mt < 2; mt++)
#pragma unroll
        for (int nt = 0; nt < 8; nt++)
#pragma unroll
            for (int j = 0; j < 4; j++) acc[mt][nt][j] = 0.f;

    for (int kt = 0; kt < 12; kt++) {
#pragma unroll
        for (int i = 0; i < 4; i++) {
            const int so = grow[i] * 128 + ((gchk[i] ^ (grow[i] & 7)) * 16);
            *(uint4*)((char*)As + so) = pa[i];
            *(uint4*)((char*)Bs + so) = pb[i];
        }
        __syncthreads();
        if (kt + 1 < 12) {
            const int ao = soffA(kt + 1), bo = soffB(kt + 1);
#pragma unroll
            for (int i = 0; i < 4; i++) {
                pa[i] = *(const uint4*)(A + (size_t)(m0 + grow[i]) * 512 + ao + gchk[i] * 8);
                pb[i] = *(const uint4*)(B + (size_t)(n0 + grow[i]) * 512 + bo + gchk[i] * 8);
            }
        }
#pragma unroll
        for (int ks = 0; ks < 4; ks++) {
            uint32_t aF[2][4];
#pragma unroll
            for (int mt = 0; mt < 2; mt++) {
                const int row = mw + mt * 16 + (lane & 15);
                const int chk = ks * 2 + (lane >> 4);
                ldsm_x4(aF[mt][0], aF[mt][1], aF[mt][2], aF[mt][3],
                        sA + row * 128 + ((chk ^ (row & 7)) * 16));
            }
            uint32_t bF[8][2];
#pragma unroll
            for (int np = 0; np < 4; np++) {
                const int row = nw + np * 16 + (lane & 7) + ((lane >> 4) << 3);
                const int chk = ks * 2 + ((lane >> 3) & 1);
                uint32_t r0, r1, r2, r3;
                ldsm_x4(r0, r1, r2, r3, sB + row * 128 + ((chk ^ (row & 7)) * 16));
                bF[np * 2][0] = r0; bF[np * 2][1] = r1;
                bF[np * 2 + 1][0] = r2; bF[np * 2 + 1][1] = r3;
            }
#pragma unroll
            for (int mt = 0; mt < 2; mt++)
#pragma unroll
                for (int nt = 0; nt < 8; nt++)
                    mma16816(acc[mt][nt], aF[mt], bF[nt]);
        }
        __syncthreads();
    }

    const int r0 = lane >> 2, c0 = (lane & 3) * 2;
    const int kind = (MODE == 0) ? ((n0 >= 512) ? 2 : ((n0 >= 256) ? 1 : 0)) : 0;

    float cs[8][2];
#pragma unroll
    for (int nt = 0; nt < 8; nt++) { cs[nt][0] = 0.f; cs[nt][1] = 0.f; }

#pragma unroll
    for (int mt = 0; mt < 2; mt++) {
#pragma unroll
        for (int nt = 0; nt < 8; nt++) {
            const int col = n0 + nw + nt * 8 + c0;
            const float bx = bias[col], by = bias[col + 1];
            const int rowa = m0 + mw + mt * 16 + r0;
            const float vx[2] = {acc[mt][nt][0] + bx, acc[mt][nt][2] + bx};
            const float vy[2] = {acc[mt][nt][1] + by, acc[mt][nt][3] + by};
            if (MODE == 1) {
                *(float2*)(Cout + (size_t)rowa * KDIM + col)       = make_float2(vx[0], vy[0]);
                *(float2*)(Cout + (size_t)(rowa + 8) * KDIM + col) = make_float2(vx[1], vy[1]);
            } else {
                cs[nt][0] += vx[0] + vx[1];
                cs[nt][1] += vy[0] + vy[1];
#pragma unroll
                for (int rr = 0; rr < 2; rr++) {
                    const int row = rowa + rr * 8;
                    if (kind < 2)
                        *(float2*)(g_qkv + (size_t)row * 512 + col) = make_float2(vx[rr], vy[rr]);
                    if (kind >= 1) {
                        const int cc = col - ((kind == 1) ? 256 : 512);
                        const int hh = cc >> 5, w = (cc & 31) >> 1;
                        const int p = row >> 8, j = row & 255;
                        unsigned char* tb = ((kind == 1) ? g_Ktb : g_Vtb)
                                          + ((size_t)(p * 8 + hh)) * 32768 + (size_t)j * 128;
                        const int sw = j & 7;
                        const int hib = (((w >> 2) ^ sw) * 16) + (w & 3) * 4;
                        *(uint32_t*)(tb + hib) = pack_h2(__float2half_rn(vx[rr]),
                                                         __float2half_rn(vy[rr]));
                    }
                    if (kind == 2) {
                        const int p = row >> 8, pix = row & 255;
                        const int gy = (p / 7) * 16 + (pix >> 4);
                        const int gx = (p % 7) * 16 + (pix & 15);
                        *(float2*)(g_vimg + ((size_t)(gy * IMG + gx)) * 256 + (col - 512))
                            = make_float2(vx[rr], vy[rr]);
                    }
                }
            }
        }
    }

    if (MODE == 0 && kind < 2) {
#pragma unroll
        for (int nt = 0; nt < 8; nt++) {
            float a = cs[nt][0], b = cs[nt][1];
#pragma unroll
            for (int o = 4; o < 32; o <<= 1) {
                a += __shfl_xor_sync(0xffffffffu, a, o);
                b += __shfl_xor_sync(0xffffffffu, b, o);
            }
            if (lane < 4) {
                sWsum[wid][nt * 8 + c0]     = a;
                sWsum[wid][nt * 8 + c0 + 1] = b;
            }
        }
        __syncthreads();
        if (tid < 128) {
            const int nwsel = tid >> 6, col = tid & 63;
            const float s = sWsum[nwsel][col] + sWsum[2 + nwsel][col]
                          + sWsum[4 + nwsel][col] + sWsum[6 + nwsel][col];
            g_part2[m0 >> 7][n0 + nwsel * 64 + col] = s;
        }
    }
}

// ---------------------------------------------------------------------------
// Routing: block p: q-row sum, logits vs all k-row sums, top-4.
// ---------------------------------------------------------------------------
__global__ __launch_bounds__(256) void route_k() {
    __shared__ float sq[256];
    __shared__ float slog[64];
    const int p = blockIdx.x, tid = threadIdx.x, wrp = tid >> 5, lane = tid & 31;

    sq[tid] = g_part2[2 * p][tid] + g_part2[2 * p + 1][tid];
    __syncthreads();

    const float q0 = sq[lane * 8 + 0], q1 = sq[lane * 8 + 1];
    const float q2 = sq[lane * 8 + 2], q3 = sq[lane * 8 + 3];
    const float q4 = sq[lane * 8 + 4], q5 = sq[lane * 8 + 5];
    const float q6 = sq[lane * 8 + 6], q7 = sq[lane * 8 + 7];
    for (int j = wrp; j < P2; j += 8) {
        const float4 a0 = *(const float4*)&g_part2[2 * j][256 + lane * 8];
        const float4 a1 = *(const float4*)&g_part2[2 * j][256 + lane * 8 + 4];
        const float4 b0 = *(const float4*)&g_part2[2 * j + 1][256 + lane * 8];
        const float4 b1 = *(const float4*)&g_part2[2 * j + 1][256 + lane * 8 + 4];
        float d = q0 * (a0.x + b0.x) + q1 * (a0.y + b0.y)
                + q2 * (a0.z + b0.z) + q3 * (a0.w + b0.w)
                + q4 * (a1.x + b1.x) + q5 * (a1.y + b1.y)
                + q6 * (a1.z + b1.z) + q7 * (a1.w + b1.w);
#pragma unroll
        for (int o = 16; o > 0; o >>= 1) d += __shfl_xor_sync(0xffffffffu, d, o);
        if (lane == 0) slog[j] = d;
    }
    __syncthreads();

    if (tid == 0) {
        float bv0 = -1e30f, bv1 = -1e30f, bv2 = -1e30f, bv3 = -1e30f;
        int   bi0 = 0, bi1 = 0, bi2 = 0, bi3 = 0;
        for (int j = 0; j < P2; j++) {
            const float s = slog[j];
            if (s > bv3) {
                if (s > bv0)      { bv3=bv2;bi3=bi2; bv2=bv1;bi2=bi1; bv1=bv0;bi1=bi0; bv0=s;bi0=j; }
                else if (s > bv1) { bv3=bv2;bi3=bi2; bv2=bv1;bi2=bi1; bv1=s;bi1=j; }
                else if (s > bv2) { bv3=bv2;bi3=bi2; bv2=s;bi2=j; }
                else              { bv3=s;bi3=j; }
            }
        }
        g_top[p * 4 + 0] = bi0; g_top[p * 4 + 1] = bi1;
        g_top[p * 4 + 2] = bi2; g_top[p * 4 + 3] = bi3;
    }
}

// ---------------------------------------------------------------------------
// Attention v5: grid (49, 8, 2); CTA = 128 q, warp = 16 q rows, 2 CTAs/SM.
// Single-term fp16 QK, f16x2 ex2(s-6) softmax, l via ones-mma, fp16 PV.
// Only hi halves of K/V tiles are loaded (2 uint4/thread/chunk).
// ---------------------------------------------------------------------------
__global__ __launch_bounds__(256, 2) void attn_mma() {
    __shared__ __align__(128) unsigned char Kt[16384];   // 2 buffers x 8KB (hi half used)
    __shared__ __align__(128) unsigned char Vt[16384];
    __shared__ int sidx[4];
    const int p = blockIdx.x, h = blockIdx.y, qz = blockIdx.z;
    const int tid = threadIdx.x, wid = tid >> 5, lane = tid & 31;
    if (tid < 4) sidx[tid] = g_top[p * 4 + tid];

    const uint32_t sK = smem_u32(Kt), sV = smem_u32(Vt);
    const int r  = lane >> 2;
    const int c2 = (lane & 3) * 2;

    // per-thread hi-chunk offset within an 8KB chunk (64 rows x 128B, hi 64B)
    const int lrow = tid >> 2, lc = tid & 3;
    const int loff = lrow * 128 + ((lc ^ (lrow & 7)) * 16);

    // Q fragments (fp16) for 16 rows
    uint32_t qh[2][4];
    {
        const float* qb = g_qkv + ((size_t)p * W2 + qz * 128 + wid * 16) * 512 + h * 32;
#pragma unroll
        for (int ks = 0; ks < 2; ks++)
#pragma unroll
            for (int idx = 0; idx < 4; idx++) {
                const int row = r + (idx & 1) * 8;
                const int col = ks * 16 + (idx >> 1) * 8 + c2;
                const float2 v = *(const float2*)(qb + (size_t)row * 512 + col);
                qh[ks][idx] = pack_h2(__float2half_rn(v.x * QSCALE),
                                      __float2half_rn(v.y * QSCALE));
            }
    }
    __syncthreads();
    const int s0 = sidx[0], s1 = sidx[1], s2 = sidx[2], s3 = sidx[3];

    float lacc[4];
    float outA[4][4];
#pragma unroll
    for (int j = 0; j < 4; j++) lacc[j] = 0.f;
#pragma unroll
    for (int ct = 0; ct < 4; ct++)
#pragma unroll
        for (int j = 0; j < 4; j++) outA[ct][j] = 0.f;
    const uint32_t ONE2 = 0x3C003C00u;
    const uint32_t bones[2] = {ONE2, ONE2};

    // prefetch chunk 0
    uint4 pk, pv;
    {
        const size_t b = ((size_t)(s0 * 8 + h)) * 32768 + loff;
        pk = *(const uint4*)(g_Ktb + b);
        pv = *(const uint4*)(g_Vtb + b);
    }
    *(uint4*)(Kt + loff) = pk;
    *(uint4*)(Vt + loff) = pv;
    __syncthreads();

#pragma unroll 1
    for (int ch = 0; ch < 16; ch++) {
        const int cb = (ch & 1) * 8192;
        const bool more = (ch + 1 < 16);
        if (more) {
            const int nc = ch + 1, t = nc >> 2;
            const int sw = (t == 0) ? s0 : (t == 1) ? s1 : (t == 2) ? s2 : s3;
            const size_t b = ((size_t)(sw * 8 + h)) * 32768 + (size_t)(nc & 3) * 8192 + loff;
            pk = *(const uint4*)(g_Ktb + b);
            pv = *(const uint4*)(g_Vtb + b);
        }

        float s[8][4];
#pragma unroll
        for (int nt = 0; nt < 8; nt++)
#pragma unroll
            for (int j = 0; j < 4; j++) s[nt][j] = 0.f;

        // ---- QK^T single-term fp16 ----
#pragma unroll
        for (int ks = 0; ks < 2; ks++) {
#pragma unroll
            for (int np = 0; np < 4; np++) {
                const int row = np * 16 + (lane & 7) + ((lane >> 4) << 3);
                const int chk = ks * 2 + ((lane >> 3) & 1);
                uint32_t b0, b1, b2, b3;
                ldsm_x4(b0, b1, b2, b3, sK + cb + row * 128 + ((chk ^ (row & 7)) * 16));
                uint32_t f0[2] = {b0, b1}, f1[2] = {b2, b3};
                mma16816h(s[np * 2],     qh[ks], f0);
                mma16816h(s[np * 2 + 1], qh[ks], f1);
            }
        }

        // ---- softmax: P = ex2.f16x2(s - 6), packed fp16 ----
        uint32_t pp[8][2];
#pragma unroll
        for (int nt = 0; nt < 8; nt++) {
            pp[nt][0] = exp2_h2(s[nt][1], s[nt][0]);
            pp[nt][1] = exp2_h2(s[nt][3], s[nt][2]);
        }

        // ---- l and PV via fp16 mma ----
#pragma unroll
        for (int ks = 0; ks < 4; ks++) {
            uint32_t aP[4];
            aP[0] = pp[2 * ks][0];
            aP[1] = pp[2 * ks][1];
            aP[2] = pp[2 * ks + 1][0];
            aP[3] = pp[2 * ks + 1][1];
            mma16816h(lacc, aP, bones);
            uint32_t bV[4][2];
#pragma unroll
            for (int cp = 0; cp < 2; cp++) {
                const int row = ks * 16 + (lane & 15);
                const int chk = cp * 2 + (lane >> 4);
                uint32_t b0, b1, b2, b3;
                ldsm_x4_t(b0, b1, b2, b3, sV + cb + row * 128 + ((chk ^ (row & 7)) * 16));
                bV[cp * 2][0] = b0; bV[cp * 2][1] = b1;
                bV[cp * 2 + 1][0] = b2; bV[cp * 2 + 1][1] = b3;
            }
#pragma unroll
            for (int ct = 0; ct < 4; ct++)
                mma16816h(outA[ct], aP, bV[ct]);
        }

        if (more) {
            const int nb = cb ^ 8192;
            *(uint4*)(Kt + nb + loff) = pk;
            *(uint4*)(Vt + nb + loff) = pv;
        }
        __syncthreads();
    }

    const int wy = p / 7, wx = p % 7;
#pragma unroll
    for (int hf = 0; hf < 2; hf++) {
        const float inv = 1.f / lacc[hf * 2];   // ones-mma: full row sum, no shfl
        const int q = qz * 128 + wid * 16 + r + hf * 8;
        const int gy = wy * 16 + (q >> 4), gx = wx * 16 + (q & 15);
        float* o = g_y + ((size_t)(gy * IMG + gx)) * 256 + h * 32;
#pragma unroll
        for (int ct = 0; ct < 4; ct++) {
            float2 v = {outA[ct][hf * 2] * inv, outA[ct][hf * 2 + 1] * inv};
            *(float2*)(o + ct * 8 + c2) = v;
        }
    }
}

// ---------------------------------------------------------------------------
// LePE + add attn; emit [hi|lo] rows for out-gemm
// ---------------------------------------------------------------------------
__global__ __launch_bounds__(256) void lepe_k(const float* __restrict__ lw,
                                              const float* __restrict__ lb) {
    const int pix = blockIdx.x;
    const int c   = threadIdx.x;
    const int y = pix / IMG, x = pix % IMG;
    float sum = lb[c];
#pragma unroll
    for (int dy = -1; dy <= 1; dy++) {
        const int yy = y + dy;
        if (yy < 0 || yy >= IMG) continue;
#pragma unroll
        for (int dx = -1; dx <= 1; dx++) {
            const int xx = x + dx;
            if (xx < 0 || xx >= IMG) continue;
            const float v = g_vimg[((size_t)(yy * IMG + xx)) * 256 + c];
            sum += v * lw[((dy + 1) * 3 + (dx + 1)) * 256 + c];
        }
    }
    const float tot = g_y[(size_t)pix * 256 + c] + sum;
    const __nv_bfloat16 h = __float2bfloat16(tot);
    g_Yp[(size_t)pix * 512 + c]       = h;
    g_Yp[(size_t)pix * 512 + 256 + c] = __float2bfloat16(tot - __bfloat162float(h));
}

// ---------------------------------------------------------------------------
extern "C" void kernel_launch(void* const* d_in, const int* in_sizes, int n_in,
                              void* d_out, int out_size) {
    const float* x      = (const float*)d_in[0];
    const float* w_qkv  = (const float*)d_in[1];
    const float* b_qkv  = (const float*)d_in[2];
    const float* w_o    = (const float*)d_in[3];
    const float* b_o    = (const float*)d_in[4];
    const float* lepe_w = (const float*)d_in[5];
    const float* lepe_b = (const float*)d_in[6];
    float* out = (float*)d_out;
    (void)in_sizes; (void)n_in; (void)out_size;

    prep_all<<<NQKV + MROWS, 256>>>(w_qkv, w_o, x);                       // 1
    gemm_mma<0><<<dim3(NQKV / 128, MROWS / 128), 256>>>(b_qkv, nullptr);  // 2
    route_k<<<P2, 256>>>();                                               // 3
    attn_mma<<<dim3(P2, 8, 2), 256>>>();                                  // 4 <- ncu
    lepe_k<<<IMG * IMG, 256>>>(lepe_w, lepe_b);                           // 5
    gemm_mma<1><<<dim3(KDIM / 128, MROWS / 128), 256>>>(b_o, out);        // 6
}

// round 12
// speedup vs baseline: 4.9038x; 1.1943x over previous
#include <cuda_runtime.h>
#include <cuda_bf16.h>
#include <cuda_fp16.h>
#include <cstdint>

// ---------------------------------------------------------------------------
// BiLevelRoutingAttention, B=1, H=W=112, DIM=QK=256, HEADS=8, NWIN=7, TOPK=4
// Dense GEMMs: fp16 2-term (Ahi+Alo)*Bhi, fp32 accum. Attention v6: 4 warps x
// 32 q-rows (halved smem traffic), single-term fp16 QK, f16x2 ex2 softmax,
// l via ones-mma.
// ---------------------------------------------------------------------------

#define P2     49
#define W2     256
#define MROWS  12544
#define NQKV   768
#define KDIM   256
#define IMG    112
#define QSCALE 0.09016844f   // 256^-0.5 * log2(e)

__device__ float g_qkv [MROWS * 512];              // q only used (stride 512)
__device__ float g_vimg[MROWS * 256];              // v, image layout
__device__ float g_part2[98][512];                 // per half-window column sums
__device__ int   g_top [P2 * 4];
__device__ float g_y   [MROWS * 256];              // attn out, image layout
__device__ __half g_Ap[MROWS * 512];               // x gathered  [hi|lo]
__device__ __half g_Yp[MROWS * 512];               // attn+lepe   [hi|lo]
__device__ __half g_Bq[NQKV * 512];                // w_qkv^T     [hi| - ]
__device__ __half g_Bo[KDIM * 512];                // w_o^T       [hi| - ]
// Packed K/V tiles (fp16): per (win,h): 256 rows x 128B; only hi half used.
__device__ unsigned char g_Ktb[P2 * 8 * 32768];
__device__ unsigned char g_Vtb[P2 * 8 * 32768];

__device__ __forceinline__ uint32_t smem_u32(const void* p) {
    uint32_t a;
    asm("{ .reg .u64 t; cvta.to.shared.u64 t, %1; cvt.u32.u64 %0, t; }" : "=r"(a) : "l"(p));
    return a;
}
__device__ __forceinline__ uint32_t pack_h2(__half lo, __half hi) {
    return ((uint32_t)__half_as_ushort(hi) << 16) | __half_as_ushort(lo);
}
// exp2(x - 6) elementwise on a packed pair, fp16 in/out.
__device__ __forceinline__ uint32_t exp2_h2(float hi, float lo) {
    uint32_t d;
    asm("cvt.rn.f16x2.f32 %0, %1, %2;" : "=r"(d) : "f"(hi), "f"(lo));
    asm("sub.f16x2 %0, %0, %1;" : "+r"(d) : "r"(0x46004600u));   // 6.0 | 6.0
    asm("ex2.approx.f16x2 %0, %0;" : "+r"(d));
    return d;
}
__device__ __forceinline__ void ldsm_x4(uint32_t& r0, uint32_t& r1, uint32_t& r2, uint32_t& r3, uint32_t a) {
    asm volatile("ldmatrix.sync.aligned.m8n8.x4.shared.b16 {%0,%1,%2,%3}, [%4];"
                 : "=r"(r0), "=r"(r1), "=r"(r2), "=r"(r3) : "r"(a));
}
__device__ __forceinline__ void ldsm_x4_t(uint32_t& r0, uint32_t& r1, uint32_t& r2, uint32_t& r3, uint32_t a) {
    asm volatile("ldmatrix.sync.aligned.m8n8.x4.trans.shared.b16 {%0,%1,%2,%3}, [%4];"
                 : "=r"(r0), "=r"(r1), "=r"(r2), "=r"(r3) : "r"(a));
}
__device__ __forceinline__ void mma16816h(float* c, const uint32_t* a, const uint32_t* b) {
    asm volatile(
        "mma.sync.aligned.m16n8k16.row.col.f32.f16.f16.f32 "
        "{%0,%1,%2,%3}, {%4,%5,%6,%7}, {%8,%9}, {%0,%1,%2,%3};"
        : "+f"(c[0]), "+f"(c[1]), "+f"(c[2]), "+f"(c[3])
        : "r"(a[0]), "r"(a[1]), "r"(a[2]), "r"(a[3]), "r"(b[0]), "r"(b[1]));
}

// virtual k-tile (0..7) -> byte-column base in 512-wide [hi|lo] storage
__device__ __forceinline__ int soffA(int kt) {   // A: hi (0-3), lo (4-7)
    return (kt < 4) ? (kt & 3) * 64 : 256 + (kt & 3) * 64;
}
__device__ __forceinline__ int soffB(int kt) {   // B: hi always
    return (kt & 3) * 64;
}

// ---------------------------------------------------------------------------
// Merged prep (fp16)
// ---------------------------------------------------------------------------
__global__ __launch_bounds__(256) void prep_all(const float* __restrict__ wq,
                                                const float* __restrict__ wo,
                                                const float* __restrict__ x) {
    const int b = blockIdx.x, tid = threadIdx.x;
    if (b < NQKV) {
        const int t = b * 256 + tid;
        const int n = t >> 8, k = t & 255;
        g_Bq[n * 512 + k] = __float2half_rn(wq[k * NQKV + n]);
        if (t < KDIM * KDIM)
            g_Bo[n * 512 + k] = __float2half_rn(wo[k * KDIM + n]);
    } else {
        const int m = b - NQKV, c = tid;
        const int p = m >> 8, pix = m & 255;
        const int gy = (p / 7) * 16 + (pix >> 4);
        const int gx = (p % 7) * 16 + (pix & 15);
        const float v = x[(gy * IMG + gx) * KDIM + c];
        const __half h = __float2half_rn(v);
        g_Ap[m * 512 + c]       = h;
        g_Ap[m * 512 + 256 + c] = __float2half_rn(v - __half2float(h));
    }
}

// ---------------------------------------------------------------------------
// Dense GEMM fp16 2-term. MODE 0: fused KV pack + v scatter + column sums.
// ---------------------------------------------------------------------------
template <int MODE>
__global__ __launch_bounds__(256) void gemm_mma(const float* __restrict__ bias,
                                                float* __restrict__ Cout) {
    __shared__ __align__(128) __half As[128 * 64];
    __shared__ __align__(128) __half Bs[128 * 64];
    __shared__ float sWsum[8][64];

    const __half* A = (MODE == 0) ? g_Ap : g_Yp;
    const __half* B = (MODE == 0) ? g_Bq : g_Bo;

    const int tid  = threadIdx.x;
    const int wid  = tid >> 5;
    const int lane = tid & 31;
    const int m0   = blockIdx.y * 128;
    const int n0   = blockIdx.x * 128;
    const int mw   = (wid >> 1) * 32;
    const int nw   = (wid & 1) * 64;

    const uint32_t sA = smem_u32(As), sB = smem_u32(Bs);

    uint4 pa[4], pb[4];
    int grow[4], gchk[4];
#pragma unroll
    for (int i = 0; i < 4; i++) {
        const int idx = tid + 256 * i;
        grow[i] = idx >> 3;
        gchk[i] = idx & 7;
    }
#pragma unroll
    for (int i = 0; i < 4; i++) {
        pa[i] = *(const uint4*)(A + (size_t)(m0 + grow[i]) * 512 + soffA(0) + gchk[i] * 8);
        pb[i] = *(const uint4*)(B + (size_t)(n0 + grow[i]) * 512 + soffB(0) + gchk[i] * 8);
    }

    float acc[2][8][4];
#pragma unroll
    for (int mt = 0; mt < 2; mt++)
#pragma unroll
        for (int nt = 0; nt < 8; nt++)
#pragma unroll
            for (int j = 0; j < 4; j++) acc[mt][nt][j] = 0.f;

    for (int kt = 0; kt < 8; kt++) {
#pragma unroll
        for (int i = 0; i < 4; i++) {
            const int so = grow[i] * 128 + ((gchk[i] ^ (grow[i] & 7)) * 16);
            *(uint4*)((char*)As + so) = pa[i];
            *(uint4*)((char*)Bs + so) = pb[i];
        }
        __syncthreads();
        if (kt + 1 < 8) {
            const int ao = soffA(kt + 1), bo = soffB(kt + 1);
#pragma unroll
            for (int i = 0; i < 4; i++) {
                pa[i] = *(const uint4*)(A + (size_t)(m0 + grow[i]) * 512 + ao + gchk[i] * 8);
                pb[i] = *(const uint4*)(B + (size_t)(n0 + grow[i]) * 512 + bo + gchk[i] * 8);
            }
        }
#pragma unroll
        for (int ks = 0; ks < 4; ks++) {
            uint32_t aF[2][4];
#pragma unroll
            for (int mt = 0; mt < 2; mt++) {
                const int row = mw + mt * 16 + (lane & 15);
                const int chk = ks * 2 + (lane >> 4);
                ldsm_x4(aF[mt][0], aF[mt][1], aF[mt][2], aF[mt][3],
                        sA + row * 128 + ((chk ^ (row & 7)) * 16));
            }
            uint32_t bF[8][2];
#pragma unroll
            for (int np = 0; np < 4; np++) {
                const int row = nw + np * 16 + (lane & 7) + ((lane >> 4) << 3);
                const int chk = ks * 2 + ((lane >> 3) & 1);
                uint32_t r0, r1, r2, r3;
                ldsm_x4(r0, r1, r2, r3, sB + row * 128 + ((chk ^ (row & 7)) * 16));
                bF[np * 2][0] = r0; bF[np * 2][1] = r1;
                bF[np * 2 + 1][0] = r2; bF[np * 2 + 1][1] = r3;
            }
#pragma unroll
            for (int mt = 0; mt < 2; mt++)
#pragma unroll
                for (int nt = 0; nt < 8; nt++)
                    mma16816h(acc[mt][nt], aF[mt], bF[nt]);
        }
        __syncthreads();
    }

    const int r0 = lane >> 2, c0 = (lane & 3) * 2;
    const int kind = (MODE == 0) ? ((n0 >= 512) ? 2 : ((n0 >= 256) ? 1 : 0)) : 0;

    float cs[8][2];
#pragma unroll
    for (int nt = 0; nt < 8; nt++) { cs[nt][0] = 0.f; cs[nt][1] = 0.f; }

#pragma unroll
    for (int mt = 0; mt < 2; mt++) {
#pragma unroll
        for (int nt = 0; nt < 8; nt++) {
            const int col = n0 + nw + nt * 8 + c0;
            const float bx = bias[col], by = bias[col + 1];
            const int rowa = m0 + mw + mt * 16 + r0;
            const float vx[2] = {acc[mt][nt][0] + bx, acc[mt][nt][2] + bx};
            const float vy[2] = {acc[mt][nt][1] + by, acc[mt][nt][3] + by};
            if (MODE == 1) {
                *(float2*)(Cout + (size_t)rowa * KDIM + col)       = make_float2(vx[0], vy[0]);
                *(float2*)(Cout + (size_t)(rowa + 8) * KDIM + col) = make_float2(vx[1], vy[1]);
            } else {
                cs[nt][0] += vx[0] + vx[1];
                cs[nt][1] += vy[0] + vy[1];
#pragma unroll
                for (int rr = 0; rr < 2; rr++) {
                    const int row = rowa + rr * 8;
                    if (kind == 0)
                        *(float2*)(g_qkv + (size_t)row * 512 + col) = make_float2(vx[rr], vy[rr]);
                    if (kind >= 1) {
                        const int cc = col - ((kind == 1) ? 256 : 512);
                        const int hh = cc >> 5, w = (cc & 31) >> 1;
                        const int p = row >> 8, j = row & 255;
                        unsigned char* tb = ((kind == 1) ? g_Ktb : g_Vtb)
                                          + ((size_t)(p * 8 + hh)) * 32768 + (size_t)j * 128;
                        const int sw = j & 7;
                        const int hib = (((w >> 2) ^ sw) * 16) + (w & 3) * 4;
                        *(uint32_t*)(tb + hib) = pack_h2(__float2half_rn(vx[rr]),
                                                         __float2half_rn(vy[rr]));
                    }
                    if (kind == 2) {
                        const int p = row >> 8, pix = row & 255;
                        const int gy = (p / 7) * 16 + (pix >> 4);
                        const int gx = (p % 7) * 16 + (pix & 15);
                        *(float2*)(g_vimg + ((size_t)(gy * IMG + gx)) * 256 + (col - 512))
                            = make_float2(vx[rr], vy[rr]);
                    }
                }
            }
        }
    }

    if (MODE == 0 && kind < 2) {
#pragma unroll
        for (int nt = 0; nt < 8; nt++) {
            float a = cs[nt][0], b = cs[nt][1];
#pragma unroll
            for (int o = 4; o < 32; o <<= 1) {
                a += __shfl_xor_sync(0xffffffffu, a, o);
                b += __shfl_xor_sync(0xffffffffu, b, o);
            }
            if (lane < 4) {
                sWsum[wid][nt * 8 + c0]     = a;
                sWsum[wid][nt * 8 + c0 + 1] = b;
            }
        }
        __syncthreads();
        if (tid < 128) {
            const int nwsel = tid >> 6, col = tid & 63;
            const float s = sWsum[nwsel][col] + sWsum[2 + nwsel][col]
                          + sWsum[4 + nwsel][col] + sWsum[6 + nwsel][col];
            g_part2[m0 >> 7][n0 + nwsel * 64 + col] = s;
        }
    }
}

// ---------------------------------------------------------------------------
// Routing: block p: q-row sum, logits vs all k-row sums, top-4.
// ---------------------------------------------------------------------------
__global__ __launch_bounds__(256) void route_k() {
    __shared__ float sq[256];
    __shared__ float slog[64];
    const int p = blockIdx.x, tid = threadIdx.x, wrp = tid >> 5, lane = tid & 31;

    sq[tid] = g_part2[2 * p][tid] + g_part2[2 * p + 1][tid];
    __syncthreads();

    const float q0 = sq[lane * 8 + 0], q1 = sq[lane * 8 + 1];
    const float q2 = sq[lane * 8 + 2], q3 = sq[lane * 8 + 3];
    const float q4 = sq[lane * 8 + 4], q5 = sq[lane * 8 + 5];
    const float q6 = sq[lane * 8 + 6], q7 = sq[lane * 8 + 7];
    for (int j = wrp; j < P2; j += 8) {
        const float4 a0 = *(const float4*)&g_part2[2 * j][256 + lane * 8];
        const float4 a1 = *(const float4*)&g_part2[2 * j][256 + lane * 8 + 4];
        const float4 b0 = *(const float4*)&g_part2[2 * j + 1][256 + lane * 8];
        const float4 b1 = *(const float4*)&g_part2[2 * j + 1][256 + lane * 8 + 4];
        float d = q0 * (a0.x + b0.x) + q1 * (a0.y + b0.y)
                + q2 * (a0.z + b0.z) + q3 * (a0.w + b0.w)
                + q4 * (a1.x + b1.x) + q5 * (a1.y + b1.y)
                + q6 * (a1.z + b1.z) + q7 * (a1.w + b1.w);
#pragma unroll
        for (int o = 16; o > 0; o >>= 1) d += __shfl_xor_sync(0xffffffffu, d, o);
        if (lane == 0) slog[j] = d;
    }
    __syncthreads();

    if (tid == 0) {
        float bv0 = -1e30f, bv1 = -1e30f, bv2 = -1e30f, bv3 = -1e30f;
        int   bi0 = 0, bi1 = 0, bi2 = 0, bi3 = 0;
        for (int j = 0; j < P2; j++) {
            const float s = slog[j];
            if (s > bv3) {
                if (s > bv0)      { bv3=bv2;bi3=bi2; bv2=bv1;bi2=bi1; bv1=bv0;bi1=bi0; bv0=s;bi0=j; }
                else if (s > bv1) { bv3=bv2;bi3=bi2; bv2=bv1;bi2=bi1; bv1=s;bi1=j; }
                else if (s > bv2) { bv3=bv2;bi3=bi2; bv2=s;bi2=j; }
                else              { bv3=s;bi3=j; }
            }
        }
        g_top[p * 4 + 0] = bi0; g_top[p * 4 + 1] = bi1;
        g_top[p * 4 + 2] = bi2; g_top[p * 4 + 3] = bi3;
    }
}

// ---------------------------------------------------------------------------
// Attention v6: grid (49, 8, 2); CTA = 128 threads (4 warps x 32 q rows).
// Single-term fp16 QK, f16x2 ex2(s-6) softmax, l via ones-mma, fp16 PV.
// Each K/V fragment feeds 2 m-tiles -> smem read traffic halved vs v5.
// ---------------------------------------------------------------------------
__global__ __launch_bounds__(128) void attn_mma() {
    __shared__ __align__(128) unsigned char Kt[16384];   // 2 buffers x 8KB (hi half used)
    __shared__ __align__(128) unsigned char Vt[16384];
    __shared__ int sidx[4];
    const int p = blockIdx.x, h = blockIdx.y, qz = blockIdx.z;
    const int tid = threadIdx.x, wid = tid >> 5, lane = tid & 31;
    if (tid < 4) sidx[tid] = g_top[p * 4 + tid];

    const uint32_t sK = smem_u32(Kt), sV = smem_u32(Vt);
    const int r  = lane >> 2;
    const int c2 = (lane & 3) * 2;

    // per-thread hi-chunk offsets (two per buffer with 128 threads)
    int loff[2];
#pragma unroll
    for (int i = 0; i < 2; i++) {
        const int t = tid + i * 128;
        const int lrow = t >> 2, lc = t & 3;
        loff[i] = lrow * 128 + ((lc ^ (lrow & 7)) * 16);
    }

    // Q fragments (fp16) for 32 rows: [mt][ks][4]
    uint32_t qh[2][2][4];
    {
        const float* qb = g_qkv + ((size_t)p * W2 + qz * 128 + wid * 32) * 512 + h * 32;
#pragma unroll
        for (int mt = 0; mt < 2; mt++)
#pragma unroll
            for (int ks = 0; ks < 2; ks++)
#pragma unroll
                for (int idx = 0; idx < 4; idx++) {
                    const int row = mt * 16 + r + (idx & 1) * 8;
                    const int col = ks * 16 + (idx >> 1) * 8 + c2;
                    const float2 v = *(const float2*)(qb + (size_t)row * 512 + col);
                    qh[mt][ks][idx] = pack_h2(__float2half_rn(v.x * QSCALE),
                                              __float2half_rn(v.y * QSCALE));
                }
    }
    __syncthreads();
    const int s0 = sidx[0], s1 = sidx[1], s2 = sidx[2], s3 = sidx[3];

    float lacc[2][4];
    float outA[2][4][4];
#pragma unroll
    for (int mt = 0; mt < 2; mt++) {
#pragma unroll
        for (int j = 0; j < 4; j++) lacc[mt][j] = 0.f;
#pragma unroll
        for (int ct = 0; ct < 4; ct++)
#pragma unroll
            for (int j = 0; j < 4; j++) outA[mt][ct][j] = 0.f;
    }
    const uint32_t ONE2 = 0x3C003C00u;
    const uint32_t bones[2] = {ONE2, ONE2};

    // prefetch chunk 0
    uint4 pk[2], pv[2];
    {
        const size_t b = ((size_t)(s0 * 8 + h)) * 32768;
#pragma unroll
        for (int i = 0; i < 2; i++) {
            pk[i] = *(const uint4*)(g_Ktb + b + loff[i]);
            pv[i] = *(const uint4*)(g_Vtb + b + loff[i]);
        }
    }
#pragma unroll
    for (int i = 0; i < 2; i++) {
        *(uint4*)(Kt + loff[i]) = pk[i];
        *(uint4*)(Vt + loff[i]) = pv[i];
    }
    __syncthreads();

#pragma unroll 1
    for (int ch = 0; ch < 16; ch++) {
        const int cb = (ch & 1) * 8192;
        const bool more = (ch + 1 < 16);
        if (more) {
            const int nc = ch + 1, t = nc >> 2;
            const int sw = (t == 0) ? s0 : (t == 1) ? s1 : (t == 2) ? s2 : s3;
            const size_t b = ((size_t)(sw * 8 + h)) * 32768 + (size_t)(nc & 3) * 8192;
#pragma unroll
            for (int i = 0; i < 2; i++) {
                pk[i] = *(const uint4*)(g_Ktb + b + loff[i]);
                pv[i] = *(const uint4*)(g_Vtb + b + loff[i]);
            }
        }

        float s[2][8][4];
#pragma unroll
        for (int mt = 0; mt < 2; mt++)
#pragma unroll
            for (int nt = 0; nt < 8; nt++)
#pragma unroll
                for (int j = 0; j < 4; j++) s[mt][nt][j] = 0.f;

        // ---- QK^T single-term fp16 (each K fragment feeds 2 m-tiles) ----
#pragma unroll
        for (int ks = 0; ks < 2; ks++) {
#pragma unroll
            for (int np = 0; np < 4; np++) {
                const int row = np * 16 + (lane & 7) + ((lane >> 4) << 3);
                const int chk = ks * 2 + ((lane >> 3) & 1);
                uint32_t b0, b1, b2, b3;
                ldsm_x4(b0, b1, b2, b3, sK + cb + row * 128 + ((chk ^ (row & 7)) * 16));
                uint32_t f0[2] = {b0, b1}, f1[2] = {b2, b3};
#pragma unroll
                for (int mt = 0; mt < 2; mt++) {
                    mma16816h(s[mt][np * 2],     qh[mt][ks], f0);
                    mma16816h(s[mt][np * 2 + 1], qh[mt][ks], f1);
                }
            }
        }

        // ---- softmax: P = ex2.f16x2(s - 6), packed fp16 ----
        uint32_t pp[2][8][2];
#pragma unroll
        for (int mt = 0; mt < 2; mt++)
#pragma unroll
            for (int nt = 0; nt < 8; nt++) {
                pp[mt][nt][0] = exp2_h2(s[mt][nt][1], s[mt][nt][0]);
                pp[mt][nt][1] = exp2_h2(s[mt][nt][3], s[mt][nt][2]);
            }

        // ---- l and PV via fp16 mma (each V fragment feeds 2 m-tiles) ----
#pragma unroll
        for (int ks = 0; ks < 4; ks++) {
            uint32_t bV[4][2];
#pragma unroll
            for (int cp = 0; cp < 2; cp++) {
                const int row = ks * 16 + (lane & 15);
                const int chk = cp * 2 + (lane >> 4);
                uint32_t b0, b1, b2, b3;
                ldsm_x4_t(b0, b1, b2, b3, sV + cb + row * 128 + ((chk ^ (row & 7)) * 16));
                bV[cp * 2][0] = b0; bV[cp * 2][1] = b1;
                bV[cp * 2 + 1][0] = b2; bV[cp * 2 + 1][1] = b3;
            }
#pragma unroll
            for (int mt = 0; mt < 2; mt++) {
                uint32_t aP[4];
                aP[0] = pp[mt][2 * ks][0];
                aP[1] = pp[mt][2 * ks][1];
                aP[2] = pp[mt][2 * ks + 1][0];
                aP[3] = pp[mt][2 * ks + 1][1];
                mma16816h(lacc[mt], aP, bones);
#pragma unroll
                for (int ct = 0; ct < 4; ct++)
                    mma16816h(outA[mt][ct], aP, bV[ct]);
            }
        }

        if (more) {
            const int nb = cb ^ 8192;
#pragma unroll
            for (int i = 0; i < 2; i++) {
                *(uint4*)(Kt + nb + loff[i]) = pk[i];
                *(uint4*)(Vt + nb + loff[i]) = pv[i];
            }
        }
        __syncthreads();
    }

    const int wy = p / 7, wx = p % 7;
#pragma unroll
    for (int mt = 0; mt < 2; mt++)
#pragma unroll
        for (int hf = 0; hf < 2; hf++) {
            const float inv = 1.f / lacc[mt][hf * 2];
            const int q = qz * 128 + wid * 32 + mt * 16 + r + hf * 8;
            const int gy = wy * 16 + (q >> 4), gx = wx * 16 + (q & 15);
            float* o = g_y + ((size_t)(gy * IMG + gx)) * 256 + h * 32;
#pragma unroll
            for (int ct = 0; ct < 4; ct++) {
                float2 v = {outA[mt][ct][hf * 2] * inv, outA[mt][ct][hf * 2 + 1] * inv};
                *(float2*)(o + ct * 8 + c2) = v;
            }
        }
}

// ---------------------------------------------------------------------------
// LePE + add attn; emit fp16 [hi|lo] rows for out-gemm
// ---------------------------------------------------------------------------
__global__ __launch_bounds__(256) void lepe_k(const float* __restrict__ lw,
                                              const float* __restrict__ lb) {
    const int pix = blockIdx.x;
    const int c   = threadIdx.x;
    const int y = pix / IMG, x = pix % IMG;
    float sum = lb[c];
#pragma unroll
    for (int dy = -1; dy <= 1; dy++) {
        const int yy = y + dy;
        if (yy < 0 || yy >= IMG) continue;
#pragma unroll
        for (int dx = -1; dx <= 1; dx++) {
            const int xx = x + dx;
            if (xx < 0 || xx >= IMG) continue;
            const float v = g_vimg[((size_t)(yy * IMG + xx)) * 256 + c];
            sum += v * lw[((dy + 1) * 3 + (dx + 1)) * 256 + c];
        }
    }
    const float tot = g_y[(size_t)pix * 256 + c] + sum;
    const __half h = __float2half_rn(tot);
    g_Yp[(size_t)pix * 512 + c]       = h;
    g_Yp[(size_t)pix * 512 + 256 + c] = __float2half_rn(tot - __half2float(h));
}

// ---------------------------------------------------------------------------
extern "C" void kernel_launch(void* const* d_in, const int* in_sizes, int n_in,
                              void* d_out, int out_size) {
    const float* x      = (const float*)d_in[0];
    const float* w_qkv  = (const float*)d_in[1];
    const float* b_qkv  = (const float*)d_in[2];
    const float* w_o    = (const float*)d_in[3];
    const float* b_o    = (const float*)d_in[4];
    const float* lepe_w = (const float*)d_in[5];
    const float* lepe_b = (const float*)d_in[6];
    float* out = (float*)d_out;
    (void)in_sizes; (void)n_in; (void)out_size;

    prep_all<<<NQKV + MROWS, 256>>>(w_qkv, w_o, x);                       // 1
    gemm_mma<0><<<dim3(NQKV / 128, MROWS / 128), 256>>>(b_qkv, nullptr);  // 2
    route_k<<<P2, 256>>>();                                               // 3
    attn_mma<<<dim3(P2, 8, 2), 128>>>();                                  // 4 <- ncu
    lepe_k<<<IMG * IMG, 256>>>(lepe_w, lepe_b);                           // 5
    gemm_mma<1><<<dim3(KDIM / 128, MROWS / 128), 256>>>(b_o, out);        // 6
}

// round 13
// speedup vs baseline: 5.1473x; 1.0497x over previous
#include <cuda_runtime.h>
#include <cuda_bf16.h>
#include <cuda_fp16.h>
#include <cstdint>

// ---------------------------------------------------------------------------
// BiLevelRoutingAttention, B=1, H=W=112, DIM=QK=256, HEADS=8, NWIN=7, TOPK=4
// gemm0: fp16 2-term (Ahi+Alo)*Bhi. gemm1: fp16 single-term. Attention v7:
// 4 warps x 32 q-rows, cp.async K/V fills, single-term fp16 QK, f16x2 ex2
// softmax, l via ones-mma.
// ---------------------------------------------------------------------------

#define P2     49
#define W2     256
#define MROWS  12544
#define NQKV   768
#define KDIM   256
#define IMG    112
#define QSCALE 0.09016844f   // 256^-0.5 * log2(e)

__device__ float g_qkv [MROWS * 512];              // q only used (stride 512)
__device__ float g_vimg[MROWS * 256];              // v, image layout
__device__ float g_part2[98][512];                 // per half-window column sums
__device__ int   g_top [P2 * 4];
__device__ float g_y   [MROWS * 256];              // attn out, image layout
__device__ __half g_Ap[MROWS * 512];               // x gathered  [hi|lo]
__device__ __half g_Yp[MROWS * 512];               // attn+lepe   [hi| - ]
__device__ __half g_Bq[NQKV * 512];                // w_qkv^T     [hi| - ]
__device__ __half g_Bo[KDIM * 512];                // w_o^T       [hi| - ]
// Packed K/V tiles (fp16): per (win,h): 256 rows x 128B; only hi half used.
__device__ unsigned char g_Ktb[P2 * 8 * 32768];
__device__ unsigned char g_Vtb[P2 * 8 * 32768];

__device__ __forceinline__ uint32_t smem_u32(const void* p) {
    uint32_t a;
    asm("{ .reg .u64 t; cvta.to.shared.u64 t, %1; cvt.u32.u64 %0, t; }" : "=r"(a) : "l"(p));
    return a;
}
__device__ __forceinline__ uint32_t pack_h2(__half lo, __half hi) {
    return ((uint32_t)__half_as_ushort(hi) << 16) | __half_as_ushort(lo);
}
__device__ __forceinline__ uint32_t exp2_h2(float hi, float lo) {
    uint32_t d;
    asm("cvt.rn.f16x2.f32 %0, %1, %2;" : "=r"(d) : "f"(hi), "f"(lo));
    asm("sub.f16x2 %0, %0, %1;" : "+r"(d) : "r"(0x46004600u));   // 6.0 | 6.0
    asm("ex2.approx.f16x2 %0, %0;" : "+r"(d));
    return d;
}
__device__ __forceinline__ void ldsm_x4(uint32_t& r0, uint32_t& r1, uint32_t& r2, uint32_t& r3, uint32_t a) {
    asm volatile("ldmatrix.sync.aligned.m8n8.x4.shared.b16 {%0,%1,%2,%3}, [%4];"
                 : "=r"(r0), "=r"(r1), "=r"(r2), "=r"(r3) : "r"(a));
}
__device__ __forceinline__ void ldsm_x4_t(uint32_t& r0, uint32_t& r1, uint32_t& r2, uint32_t& r3, uint32_t a) {
    asm volatile("ldmatrix.sync.aligned.m8n8.x4.trans.shared.b16 {%0,%1,%2,%3}, [%4];"
                 : "=r"(r0), "=r"(r1), "=r"(r2), "=r"(r3) : "r"(a));
}
__device__ __forceinline__ void mma16816h(float* c, const uint32_t* a, const uint32_t* b) {
    asm volatile(
        "mma.sync.aligned.m16n8k16.row.col.f32.f16.f16.f32 "
        "{%0,%1,%2,%3}, {%4,%5,%6,%7}, {%8,%9}, {%0,%1,%2,%3};"
        : "+f"(c[0]), "+f"(c[1]), "+f"(c[2]), "+f"(c[3])
        : "r"(a[0]), "r"(a[1]), "r"(a[2]), "r"(a[3]), "r"(b[0]), "r"(b[1]));
}
#define CP_ASYNC16(sa, gp) asm volatile("cp.async.cg.shared.global [%0], [%1], 16;" :: "r"(sa), "l"(gp) : "memory")
#define CP_COMMIT()        asm volatile("cp.async.commit_group;" ::: "memory")
#define CP_WAIT0()         asm volatile("cp.async.wait_group 0;" ::: "memory")

// ---------------------------------------------------------------------------
// Prep kernels
// ---------------------------------------------------------------------------
__global__ __launch_bounds__(256) void prep_w(const float* __restrict__ wq,
                                              const float* __restrict__ wo) {
    const int t = blockIdx.x * 256 + threadIdx.x;
    const int n = t >> 8, k = t & 255;
    g_Bq[n * 512 + k] = __float2half_rn(wq[k * NQKV + n]);
    if (t < KDIM * KDIM)
        g_Bo[n * 512 + k] = __float2half_rn(wo[k * KDIM + n]);
}
__global__ __launch_bounds__(256) void prep_a(const float* __restrict__ x) {
    const int m = blockIdx.x, c = threadIdx.x;
    const int p = m >> 8, pix = m & 255;
    const int gy = (p / 7) * 16 + (pix >> 4);
    const int gx = (p % 7) * 16 + (pix & 15);
    const float v = x[(gy * IMG + gx) * KDIM + c];
    const __half h = __float2half_rn(v);
    g_Ap[m * 512 + c]       = h;
    g_Ap[m * 512 + 256 + c] = __float2half_rn(v - __half2float(h));
}
__global__ void nop_k() {}

// ---------------------------------------------------------------------------
// Dense GEMM fp16. MODE 0: 8 k-tiles (A hi+lo), fused KV pack + v scatter +
// column sums. MODE 1: 4 k-tiles (hi only), plain output.
// ---------------------------------------------------------------------------
template <int MODE>
__global__ __launch_bounds__(256) void gemm_mma(const float* __restrict__ bias,
                                                float* __restrict__ Cout) {
    __shared__ __align__(128) __half As[128 * 64];
    __shared__ __align__(128) __half Bs[128 * 64];
    __shared__ float sWsum[8][64];

    const __half* A = (MODE == 0) ? g_Ap : g_Yp;
    const __half* B = (MODE == 0) ? g_Bq : g_Bo;
    constexpr int NKT = (MODE == 0) ? 8 : 4;

    const int tid  = threadIdx.x;
    const int wid  = tid >> 5;
    const int lane = tid & 31;
    const int m0   = blockIdx.y * 128;
    const int n0   = blockIdx.x * 128;
    const int mw   = (wid >> 1) * 32;
    const int nw   = (wid & 1) * 64;

    const uint32_t sA = smem_u32(As), sB = smem_u32(Bs);

    uint4 pa[4], pb[4];
    int grow[4], gchk[4];
#pragma unroll
    for (int i = 0; i < 4; i++) {
        const int idx = tid + 256 * i;
        grow[i] = idx >> 3;
        gchk[i] = idx & 7;
    }
#pragma unroll
    for (int i = 0; i < 4; i++) {
        pa[i] = *(const uint4*)(A + (size_t)(m0 + grow[i]) * 512 + gchk[i] * 8);
        pb[i] = *(const uint4*)(B + (size_t)(n0 + grow[i]) * 512 + gchk[i] * 8);
    }

    float acc[2][8][4];
#pragma unroll
    for (int mt = 0; mt < 2; mt++)
#pragma unroll
        for (int nt = 0; nt < 8; nt++)
#pragma unroll
            for (int j = 0; j < 4; j++) acc[mt][nt][j] = 0.f;

    for (int kt = 0; kt < NKT; kt++) {
#pragma unroll
        for (int i = 0; i < 4; i++) {
            const int so = grow[i] * 128 + ((gchk[i] ^ (grow[i] & 7)) * 16);
            *(uint4*)((char*)As + so) = pa[i];
            *(uint4*)((char*)Bs + so) = pb[i];
        }
        __syncthreads();
        if (kt + 1 < NKT) {
            const int kn = kt + 1;
            const int ao = (MODE == 0) ? ((kn < 4) ? (kn & 3) * 64 : 256 + (kn & 3) * 64)
                                       : (kn & 3) * 64;
            const int bo = (kn & 3) * 64;
#pragma unroll
            for (int i = 0; i < 4; i++) {
                pa[i] = *(const uint4*)(A + (size_t)(m0 + grow[i]) * 512 + ao + gchk[i] * 8);
                pb[i] = *(const uint4*)(B + (size_t)(n0 + grow[i]) * 512 + bo + gchk[i] * 8);
            }
        }
#pragma unroll
        for (int ks = 0; ks < 4; ks++) {
            uint32_t aF[2][4];
#pragma unroll
            for (int mt = 0; mt < 2; mt++) {
                const int row = mw + mt * 16 + (lane & 15);
                const int chk = ks * 2 + (lane >> 4);
                ldsm_x4(aF[mt][0], aF[mt][1], aF[mt][2], aF[mt][3],
                        sA + row * 128 + ((chk ^ (row & 7)) * 16));
            }
            uint32_t bF[8][2];
#pragma unroll
            for (int np = 0; np < 4; np++) {
                const int row = nw + np * 16 + (lane & 7) + ((lane >> 4) << 3);
                const int chk = ks * 2 + ((lane >> 3) & 1);
                uint32_t r0, r1, r2, r3;
                ldsm_x4(r0, r1, r2, r3, sB + row * 128 + ((chk ^ (row & 7)) * 16));
                bF[np * 2][0] = r0; bF[np * 2][1] = r1;
                bF[np * 2 + 1][0] = r2; bF[np * 2 + 1][1] = r3;
            }
#pragma unroll
            for (int mt = 0; mt < 2; mt++)
#pragma unroll
                for (int nt = 0; nt < 8; nt++)
                    mma16816h(acc[mt][nt], aF[mt], bF[nt]);
        }
        __syncthreads();
    }

    const int r0 = lane >> 2, c0 = (lane & 3) * 2;
    const int kind = (MODE == 0) ? ((n0 >= 512) ? 2 : ((n0 >= 256) ? 1 : 0)) : 0;

    float cs[8][2];
#pragma unroll
    for (int nt = 0; nt < 8; nt++) { cs[nt][0] = 0.f; cs[nt][1] = 0.f; }

#pragma unroll
    for (int mt = 0; mt < 2; mt++) {
#pragma unroll
        for (int nt = 0; nt < 8; nt++) {
            const int col = n0 + nw + nt * 8 + c0;
            const float bx = bias[col], by = bias[col + 1];
            const int rowa = m0 + mw + mt * 16 + r0;
            const float vx[2] = {acc[mt][nt][0] + bx, acc[mt][nt][2] + bx};
            const float vy[2] = {acc[mt][nt][1] + by, acc[mt][nt][3] + by};
            if (MODE == 1) {
                *(float2*)(Cout + (size_t)rowa * KDIM + col)       = make_float2(vx[0], vy[0]);
                *(float2*)(Cout + (size_t)(rowa + 8) * KDIM + col) = make_float2(vx[1], vy[1]);
            } else {
                cs[nt][0] += vx[0] + vx[1];
                cs[nt][1] += vy[0] + vy[1];
#pragma unroll
                for (int rr = 0; rr < 2; rr++) {
                    const int row = rowa + rr * 8;
                    if (kind == 0)
                        *(float2*)(g_qkv + (size_t)row * 512 + col) = make_float2(vx[rr], vy[rr]);
                    if (kind >= 1) {
                        const int cc = col - ((kind == 1) ? 256 : 512);
                        const int hh = cc >> 5, w = (cc & 31) >> 1;
                        const int p = row >> 8, j = row & 255;
                        unsigned char* tb = ((kind == 1) ? g_Ktb : g_Vtb)
                                          + ((size_t)(p * 8 + hh)) * 32768 + (size_t)j * 128;
                        const int sw = j & 7;
                        const int hib = (((w >> 2) ^ sw) * 16) + (w & 3) * 4;
                        *(uint32_t*)(tb + hib) = pack_h2(__float2half_rn(vx[rr]),
                                                         __float2half_rn(vy[rr]));
                    }
                    if (kind == 2) {
                        const int p = row >> 8, pix = row & 255;
                        const int gy = (p / 7) * 16 + (pix >> 4);
                        const int gx = (p % 7) * 16 + (pix & 15);
                        *(float2*)(g_vimg + ((size_t)(gy * IMG + gx)) * 256 + (col - 512))
                            = make_float2(vx[rr], vy[rr]);
                    }
                }
            }
        }
    }

    if (MODE == 0 && kind < 2) {
#pragma unroll
        for (int nt = 0; nt < 8; nt++) {
            float a = cs[nt][0], b = cs[nt][1];
#pragma unroll
            for (int o = 4; o < 32; o <<= 1) {
                a += __shfl_xor_sync(0xffffffffu, a, o);
                b += __shfl_xor_sync(0xffffffffu, b, o);
            }
            if (lane < 4) {
                sWsum[wid][nt * 8 + c0]     = a;
                sWsum[wid][nt * 8 + c0 + 1] = b;
            }
        }
        __syncthreads();
        if (tid < 128) {
            const int nwsel = tid >> 6, col = tid & 63;
            const float s = sWsum[nwsel][col] + sWsum[2 + nwsel][col]
                          + sWsum[4 + nwsel][col] + sWsum[6 + nwsel][col];
            g_part2[m0 >> 7][n0 + nwsel * 64 + col] = s;
        }
    }
}

// ---------------------------------------------------------------------------
// Routing: block p: q-row sum, logits vs all k-row sums, top-4.
// ---------------------------------------------------------------------------
__global__ __launch_bounds__(256) void route_k() {
    __shared__ float sq[256];
    __shared__ float slog[64];
    const int p = blockIdx.x, tid = threadIdx.x, wrp = tid >> 5, lane = tid & 31;

    sq[tid] = g_part2[2 * p][tid] + g_part2[2 * p + 1][tid];
    __syncthreads();

    const float q0 = sq[lane * 8 + 0], q1 = sq[lane * 8 + 1];
    const float q2 = sq[lane * 8 + 2], q3 = sq[lane * 8 + 3];
    const float q4 = sq[lane * 8 + 4], q5 = sq[lane * 8 + 5];
    const float q6 = sq[lane * 8 + 6], q7 = sq[lane * 8 + 7];
    for (int j = wrp; j < P2; j += 8) {
        const float4 a0 = *(const float4*)&g_part2[2 * j][256 + lane * 8];
        const float4 a1 = *(const float4*)&g_part2[2 * j][256 + lane * 8 + 4];
        const float4 b0 = *(const float4*)&g_part2[2 * j + 1][256 + lane * 8];
        const float4 b1 = *(const float4*)&g_part2[2 * j + 1][256 + lane * 8 + 4];
        float d = q0 * (a0.x + b0.x) + q1 * (a0.y + b0.y)
                + q2 * (a0.z + b0.z) + q3 * (a0.w + b0.w)
                + q4 * (a1.x + b1.x) + q5 * (a1.y + b1.y)
                + q6 * (a1.z + b1.z) + q7 * (a1.w + b1.w);
#pragma unroll
        for (int o = 16; o > 0; o >>= 1) d += __shfl_xor_sync(0xffffffffu, d, o);
        if (lane == 0) slog[j] = d;
    }
    __syncthreads();

    if (tid == 0) {
        float bv0 = -1e30f, bv1 = -1e30f, bv2 = -1e30f, bv3 = -1e30f;
        int   bi0 = 0, bi1 = 0, bi2 = 0, bi3 = 0;
        for (int j = 0; j < P2; j++) {
            const float s = slog[j];
            if (s > bv3) {
                if (s > bv0)      { bv3=bv2;bi3=bi2; bv2=bv1;bi2=bi1; bv1=bv0;bi1=bi0; bv0=s;bi0=j; }
                else if (s > bv1) { bv3=bv2;bi3=bi2; bv2=bv1;bi2=bi1; bv1=s;bi1=j; }
                else if (s > bv2) { bv3=bv2;bi3=bi2; bv2=s;bi2=j; }
                else              { bv3=s;bi3=j; }
            }
        }
        g_top[p * 4 + 0] = bi0; g_top[p * 4 + 1] = bi1;
        g_top[p * 4 + 2] = bi2; g_top[p * 4 + 3] = bi3;
    }
}

// ---------------------------------------------------------------------------
// Attention v7: grid (49, 8, 2); CTA = 128 threads (4 warps x 32 q rows).
// cp.async double-buffered K/V fills; single-term fp16 QK; ex2.f16x2 softmax;
// l via ones-mma; fp16 PV.
// ---------------------------------------------------------------------------
__global__ __launch_bounds__(128) void attn_mma() {
    __shared__ __align__(128) unsigned char Kt[16384];   // 2 buffers x 8KB
    __shared__ __align__(128) unsigned char Vt[16384];
    __shared__ int sidx[4];
    const int p = blockIdx.x, h = blockIdx.y, qz = blockIdx.z;
    const int tid = threadIdx.x, wid = tid >> 5, lane = tid & 31;
    if (tid < 4) sidx[tid] = g_top[p * 4 + tid];

    const uint32_t sK = smem_u32(Kt), sV = smem_u32(Vt);
    const int r  = lane >> 2;
    const int c2 = (lane & 3) * 2;

    int loff[2];
#pragma unroll
    for (int i = 0; i < 2; i++) {
        const int t = tid + i * 128;
        const int lrow = t >> 2, lc = t & 3;
        loff[i] = lrow * 128 + ((lc ^ (lrow & 7)) * 16);
    }

    uint32_t qh[2][2][4];
    {
        const float* qb = g_qkv + ((size_t)p * W2 + qz * 128 + wid * 32) * 512 + h * 32;
#pragma unroll
        for (int mt = 0; mt < 2; mt++)
#pragma unroll
            for (int ks = 0; ks < 2; ks++)
#pragma unroll
                for (int idx = 0; idx < 4; idx++) {
                    const int row = mt * 16 + r + (idx & 1) * 8;
                    const int col = ks * 16 + (idx >> 1) * 8 + c2;
                    const float2 v = *(const float2*)(qb + (size_t)row * 512 + col);
                    qh[mt][ks][idx] = pack_h2(__float2half_rn(v.x * QSCALE),
                                              __float2half_rn(v.y * QSCALE));
                }
    }
    __syncthreads();
    const int s0 = sidx[0], s1 = sidx[1], s2 = sidx[2], s3 = sidx[3];

    float lacc[2][4];
    float outA[2][4][4];
#pragma unroll
    for (int mt = 0; mt < 2; mt++) {
#pragma unroll
        for (int j = 0; j < 4; j++) lacc[mt][j] = 0.f;
#pragma unroll
        for (int ct = 0; ct < 4; ct++)
#pragma unroll
            for (int j = 0; j < 4; j++) outA[mt][ct][j] = 0.f;
    }
    const uint32_t ONE2 = 0x3C003C00u;
    const uint32_t bones[2] = {ONE2, ONE2};

    // fill chunk 0 via cp.async
    {
        const size_t b = ((size_t)(s0 * 8 + h)) * 32768;
#pragma unroll
        for (int i = 0; i < 2; i++) {
            CP_ASYNC16(sK + loff[i], g_Ktb + b + loff[i]);
            CP_ASYNC16(sV + loff[i], g_Vtb + b + loff[i]);
        }
        CP_COMMIT();
        CP_WAIT0();
    }
    __syncthreads();

#pragma unroll 1
    for (int ch = 0; ch < 16; ch++) {
        const int cb = (ch & 1) * 8192;
        const bool more = (ch + 1 < 16);
        if (more) {
            const int nc = ch + 1, t = nc >> 2;
            const int sw = (t == 0) ? s0 : (t == 1) ? s1 : (t == 2) ? s2 : s3;
            const size_t b = ((size_t)(sw * 8 + h)) * 32768 + (size_t)(nc & 3) * 8192;
            const int nb = cb ^ 8192;
#pragma unroll
            for (int i = 0; i < 2; i++) {
                CP_ASYNC16(sK + nb + loff[i], g_Ktb + b + loff[i]);
                CP_ASYNC16(sV + nb + loff[i], g_Vtb + b + loff[i]);
            }
            CP_COMMIT();
        }

        float s[2][8][4];
#pragma unroll
        for (int mt = 0; mt < 2; mt++)
#pragma unroll
            for (int nt = 0; nt < 8; nt++)
#pragma unroll
                for (int j = 0; j < 4; j++) s[mt][nt][j] = 0.f;

        // ---- QK^T single-term fp16 ----
#pragma unroll
        for (int ks = 0; ks < 2; ks++) {
#pragma unroll
            for (int np = 0; np < 4; np++) {
                const int row = np * 16 + (lane & 7) + ((lane >> 4) << 3);
                const int chk = ks * 2 + ((lane >> 3) & 1);
                uint32_t b0, b1, b2, b3;
                ldsm_x4(b0, b1, b2, b3, sK + cb + row * 128 + ((chk ^ (row & 7)) * 16));
                uint32_t f0[2] = {b0, b1}, f1[2] = {b2, b3};
#pragma unroll
                for (int mt = 0; mt < 2; mt++) {
                    mma16816h(s[mt][np * 2],     qh[mt][ks], f0);
                    mma16816h(s[mt][np * 2 + 1], qh[mt][ks], f1);
                }
            }
        }

        // ---- softmax: P = ex2.f16x2(s - 6) ----
        uint32_t pp[2][8][2];
#pragma unroll
        for (int mt = 0; mt < 2; mt++)
#pragma unroll
            for (int nt = 0; nt < 8; nt++) {
                pp[mt][nt][0] = exp2_h2(s[mt][nt][1], s[mt][nt][0]);
                pp[mt][nt][1] = exp2_h2(s[mt][nt][3], s[mt][nt][2]);
            }

        // ---- l and PV via fp16 mma ----
#pragma unroll
        for (int ks = 0; ks < 4; ks++) {
            uint32_t bV[4][2];
#pragma unroll
            for (int cp = 0; cp < 2; cp++) {
                const int row = ks * 16 + (lane & 15);
                const int chk = cp * 2 + (lane >> 4);
                uint32_t b0, b1, b2, b3;
                ldsm_x4_t(b0, b1, b2, b3, sV + cb + row * 128 + ((chk ^ (row & 7)) * 16));
                bV[cp * 2][0] = b0; bV[cp * 2][1] = b1;
                bV[cp * 2 + 1][0] = b2; bV[cp * 2 + 1][1] = b3;
            }
#pragma unroll
            for (int mt = 0; mt < 2; mt++) {
                uint32_t aP[4];
                aP[0] = pp[mt][2 * ks][0];
                aP[1] = pp[mt][2 * ks][1];
                aP[2] = pp[mt][2 * ks + 1][0];
                aP[3] = pp[mt][2 * ks + 1][1];
                mma16816h(lacc[mt], aP, bones);
#pragma unroll
                for (int ct = 0; ct < 4; ct++)
                    mma16816h(outA[mt][ct], aP, bV[ct]);
            }
        }

        if (more) CP_WAIT0();
        __syncthreads();
    }

    const int wy = p / 7, wx = p % 7;
#pragma unroll
    for (int mt = 0; mt < 2; mt++)
#pragma unroll
        for (int hf = 0; hf < 2; hf++) {
            const float inv = 1.f / lacc[mt][hf * 2];
            const int q = qz * 128 + wid * 32 + mt * 16 + r + hf * 8;
            const int gy = wy * 16 + (q >> 4), gx = wx * 16 + (q & 15);
            float* o = g_y + ((size_t)(gy * IMG + gx)) * 256 + h * 32;
#pragma unroll
            for (int ct = 0; ct < 4; ct++) {
                float2 v = {outA[mt][ct][hf * 2] * inv, outA[mt][ct][hf * 2 + 1] * inv};
                *(float2*)(o + ct * 8 + c2) = v;
            }
        }
}

// ---------------------------------------------------------------------------
// LePE + add attn; emit fp16 hi rows for out-gemm (single-term)
// ---------------------------------------------------------------------------
__global__ __launch_bounds__(256) void lepe_k(const float* __restrict__ lw,
                                              const float* __restrict__ lb) {
    const int pix = blockIdx.x;
    const int c   = threadIdx.x;
    const int y = pix / IMG, x = pix % IMG;
    float sum = lb[c];
#pragma unroll
    for (int dy = -1; dy <= 1; dy++) {
        const int yy = y + dy;
        if (yy < 0 || yy >= IMG) continue;
#pragma unroll
        for (int dx = -1; dx <= 1; dx++) {
            const int xx = x + dx;
            if (xx < 0 || xx >= IMG) continue;
            const float v = g_vimg[((size_t)(yy * IMG + xx)) * 256 + c];
            sum += v * lw[((dy + 1) * 3 + (dx + 1)) * 256 + c];
        }
    }
    const float tot = g_y[(size_t)pix * 256 + c] + sum;
    g_Yp[(size_t)pix * 512 + c] = __float2half_rn(tot);
}

// ---------------------------------------------------------------------------
extern "C" void kernel_launch(void* const* d_in, const int* in_sizes, int n_in,
                              void* d_out, int out_size) {
    const float* x      = (const float*)d_in[0];
    const float* w_qkv  = (const float*)d_in[1];
    const float* b_qkv  = (const float*)d_in[2];
    const float* w_o    = (const float*)d_in[3];
    const float* b_o    = (const float*)d_in[4];
    const float* lepe_w = (const float*)d_in[5];
    const float* lepe_b = (const float*)d_in[6];
    float* out = (float*)d_out;
    (void)in_sizes; (void)n_in; (void)out_size;

    prep_w<<<NQKV, 256>>>(w_qkv, w_o);                                    // 1
    prep_a<<<MROWS, 256>>>(x);                                            // 2
    nop_k<<<1, 32>>>();                                                   // 3
    gemm_mma<0><<<dim3(NQKV / 128, MROWS / 128), 256>>>(b_qkv, nullptr);  // 4 <- ncu
    route_k<<<P2, 256>>>();                                               // 5
    attn_mma<<<dim3(P2, 8, 2), 128>>>();                                  // 6
    lepe_k<<<IMG * IMG, 256>>>(lepe_w, lepe_b);                           // 7
    gemm_mma<1><<<dim3(KDIM / 128, MROWS / 128), 256>>>(b_o, out);        // 8
}

// round 14
// speedup vs baseline: 5.2551x; 1.0209x over previous
#include <cuda_runtime.h>
#include <cuda_bf16.h>
#include <cuda_fp16.h>
#include <cstdint>

// ---------------------------------------------------------------------------
// BiLevelRoutingAttention, B=1, H=W=112, DIM=QK=256, HEADS=8, NWIN=7, TOPK=4
// gemm0: single-term fp16, A gathered from x in-kernel (no prep_a).
// gemm1: single-term fp16. Attention v7: 4 warps x 32 q-rows, cp.async K/V,
// single-term fp16 QK, ex2.f16x2 softmax, l via ones-mma.
// ---------------------------------------------------------------------------

#define P2     49
#define W2     256
#define MROWS  12544
#define NQKV   768
#define KDIM   256
#define IMG    112
#define QSCALE 0.09016844f   // 256^-0.5 * log2(e)

__device__ float g_qkv [MROWS * 512];              // q (stride 512)
__device__ float g_vimg[MROWS * 256];              // v, image layout
__device__ float g_part2[98][512];                 // per half-window column sums
__device__ int   g_top [P2 * 4];
__device__ float g_y   [MROWS * 256];              // attn out, image layout
__device__ __half g_Yp[MROWS * 512];               // attn+lepe   [hi| - ]
__device__ __half g_Bq[NQKV * 512];                // w_qkv^T     [hi| - ]
__device__ __half g_Bo[KDIM * 512];                // w_o^T       [hi| - ]
// Packed K/V tiles (fp16): per (win,h): 256 rows x 128B; only hi half used.
__device__ unsigned char g_Ktb[P2 * 8 * 32768];
__device__ unsigned char g_Vtb[P2 * 8 * 32768];

__device__ __forceinline__ uint32_t smem_u32(const void* p) {
    uint32_t a;
    asm("{ .reg .u64 t; cvta.to.shared.u64 t, %1; cvt.u32.u64 %0, t; }" : "=r"(a) : "l"(p));
    return a;
}
__device__ __forceinline__ uint32_t pack_h2(__half lo, __half hi) {
    return ((uint32_t)__half_as_ushort(hi) << 16) | __half_as_ushort(lo);
}
__device__ __forceinline__ uint32_t cvt_h2(float lo, float hi) {
    uint32_t d;
    asm("cvt.rn.f16x2.f32 %0, %1, %2;" : "=r"(d) : "f"(hi), "f"(lo));
    return d;
}
__device__ __forceinline__ uint32_t exp2_h2(float hi, float lo) {
    uint32_t d;
    asm("cvt.rn.f16x2.f32 %0, %1, %2;" : "=r"(d) : "f"(hi), "f"(lo));
    asm("sub.f16x2 %0, %0, %1;" : "+r"(d) : "r"(0x46004600u));   // 6.0 | 6.0
    asm("ex2.approx.f16x2 %0, %0;" : "+r"(d));
    return d;
}
__device__ __forceinline__ void ldsm_x4(uint32_t& r0, uint32_t& r1, uint32_t& r2, uint32_t& r3, uint32_t a) {
    asm volatile("ldmatrix.sync.aligned.m8n8.x4.shared.b16 {%0,%1,%2,%3}, [%4];"
                 : "=r"(r0), "=r"(r1), "=r"(r2), "=r"(r3) : "r"(a));
}
__device__ __forceinline__ void ldsm_x4_t(uint32_t& r0, uint32_t& r1, uint32_t& r2, uint32_t& r3, uint32_t a) {
    asm volatile("ldmatrix.sync.aligned.m8n8.x4.trans.shared.b16 {%0,%1,%2,%3}, [%4];"
                 : "=r"(r0), "=r"(r1), "=r"(r2), "=r"(r3) : "r"(a));
}
__device__ __forceinline__ void mma16816h(float* c, const uint32_t* a, const uint32_t* b) {
    asm volatile(
        "mma.sync.aligned.m16n8k16.row.col.f32.f16.f16.f32 "
        "{%0,%1,%2,%3}, {%4,%5,%6,%7}, {%8,%9}, {%0,%1,%2,%3};"
        : "+f"(c[0]), "+f"(c[1]), "+f"(c[2]), "+f"(c[3])
        : "r"(a[0]), "r"(a[1]), "r"(a[2]), "r"(a[3]), "r"(b[0]), "r"(b[1]));
}
#define CP_ASYNC16(sa, gp) asm volatile("cp.async.cg.shared.global [%0], [%1], 16;" :: "r"(sa), "l"(gp) : "memory")
#define CP_COMMIT()        asm volatile("cp.async.commit_group;" ::: "memory")
#define CP_WAIT0()         asm volatile("cp.async.wait_group 0;" ::: "memory")

// ---------------------------------------------------------------------------
// Prep: weight transpose to fp16
// ---------------------------------------------------------------------------
__global__ __launch_bounds__(256) void prep_w(const float* __restrict__ wq,
                                              const float* __restrict__ wo) {
    const int t = blockIdx.x * 256 + threadIdx.x;
    const int n = t >> 8, k = t & 255;
    g_Bq[n * 512 + k] = __float2half_rn(wq[k * NQKV + n]);
    if (t < KDIM * KDIM)
        g_Bo[n * 512 + k] = __float2half_rn(wo[k * KDIM + n]);
}

// ---------------------------------------------------------------------------
// Dense GEMM fp16 single-term, 4 k-tiles.
// MODE 0: A gathered from x (fp32 -> fp16 in the fill phase); epilogue fuses
//         KV pack + v image scatter + window column sums.
// MODE 1: A = g_Yp (fp16); plain output.
// ---------------------------------------------------------------------------
template <int MODE>
__global__ __launch_bounds__(256) void gemm_mma(const float* __restrict__ X,
                                                const float* __restrict__ bias,
                                                float* __restrict__ Cout) {
    __shared__ __align__(128) __half As[128 * 64];
    __shared__ __align__(128) __half Bs[128 * 64];
    __shared__ float sWsum[8][64];

    const __half* B = (MODE == 0) ? g_Bq : g_Bo;

    const int tid  = threadIdx.x;
    const int wid  = tid >> 5;
    const int lane = tid & 31;
    const int m0   = blockIdx.y * 128;
    const int n0   = blockIdx.x * 128;
    const int mw   = (wid >> 1) * 32;
    const int nw   = (wid & 1) * 64;

    const uint32_t sA = smem_u32(As), sB = smem_u32(Bs);

    int grow[4], gchk[4], soff[4];
    const float* Arow[4];
#pragma unroll
    for (int i = 0; i < 4; i++) {
        const int idx = tid + 256 * i;
        grow[i] = idx >> 3;
        gchk[i] = idx & 7;
        soff[i] = grow[i] * 128 + ((gchk[i] ^ (grow[i] & 7)) * 16);
        const int m = m0 + grow[i];
        if (MODE == 0) {
            const int p = m >> 8, pix = m & 255;
            const int gy = (p / 7) * 16 + (pix >> 4);
            const int gx = (p % 7) * 16 + (pix & 15);
            Arow[i] = X + (size_t)(gy * IMG + gx) * KDIM + gchk[i] * 8;
        } else {
            Arow[i] = (const float*)(g_Yp + (size_t)m * 512 + gchk[i] * 8);  // fp16 data
        }
    }

    uint4 pb[4];
#pragma unroll
    for (int i = 0; i < 4; i++)
        pb[i] = *(const uint4*)(B + (size_t)(n0 + grow[i]) * 512 + gchk[i] * 8);

    float acc[2][8][4];
#pragma unroll
    for (int mt = 0; mt < 2; mt++)
#pragma unroll
        for (int nt = 0; nt < 8; nt++)
#pragma unroll
            for (int j = 0; j < 4; j++) acc[mt][nt][j] = 0.f;

    for (int kt = 0; kt < 4; kt++) {
        // fill A
#pragma unroll
        for (int i = 0; i < 4; i++) {
            uint4 hv;
            if (MODE == 0) {
                const float4 f0 = *(const float4*)(Arow[i] + kt * 64);
                const float4 f1 = *(const float4*)(Arow[i] + kt * 64 + 4);
                hv.x = cvt_h2(f0.x, f0.y);
                hv.y = cvt_h2(f0.z, f0.w);
                hv.z = cvt_h2(f1.x, f1.y);
                hv.w = cvt_h2(f1.z, f1.w);
            } else {
                hv = *(const uint4*)((const __half*)Arow[i] + kt * 64);
            }
            *(uint4*)((char*)As + soff[i]) = hv;
            *(uint4*)((char*)Bs + soff[i]) = pb[i];
        }
        __syncthreads();
        if (kt + 1 < 4) {
            const int bo = (kt + 1) * 64;
#pragma unroll
            for (int i = 0; i < 4; i++)
                pb[i] = *(const uint4*)(B + (size_t)(n0 + grow[i]) * 512 + bo + gchk[i] * 8);
        }
#pragma unroll
        for (int ks = 0; ks < 4; ks++) {
            uint32_t aF[2][4];
#pragma unroll
            for (int mt = 0; mt < 2; mt++) {
                const int row = mw + mt * 16 + (lane & 15);
                const int chk = ks * 2 + (lane >> 4);
                ldsm_x4(aF[mt][0], aF[mt][1], aF[mt][2], aF[mt][3],
                        sA + row * 128 + ((chk ^ (row & 7)) * 16));
            }
            uint32_t bF[8][2];
#pragma unroll
            for (int np = 0; np < 4; np++) {
                const int row = nw + np * 16 + (lane & 7) + ((lane >> 4) << 3);
                const int chk = ks * 2 + ((lane >> 3) & 1);
                uint32_t r0, r1, r2, r3;
                ldsm_x4(r0, r1, r2, r3, sB + row * 128 + ((chk ^ (row & 7)) * 16));
                bF[np * 2][0] = r0; bF[np * 2][1] = r1;
                bF[np * 2 + 1][0] = r2; bF[np * 2 + 1][1] = r3;
            }
#pragma unroll
            for (int mt = 0; mt < 2; mt++)
#pragma unroll
                for (int nt = 0; nt < 8; nt++)
                    mma16816h(acc[mt][nt], aF[mt], bF[nt]);
        }
        __syncthreads();
    }

    const int r0 = lane >> 2, c0 = (lane & 3) * 2;
    const int kind = (MODE == 0) ? ((n0 >= 512) ? 2 : ((n0 >= 256) ? 1 : 0)) : 0;

    float cs[8][2];
#pragma unroll
    for (int nt = 0; nt < 8; nt++) { cs[nt][0] = 0.f; cs[nt][1] = 0.f; }

#pragma unroll
    for (int mt = 0; mt < 2; mt++) {
#pragma unroll
        for (int nt = 0; nt < 8; nt++) {
            const int col = n0 + nw + nt * 8 + c0;
            const float bx = bias[col], by = bias[col + 1];
            const int rowa = m0 + mw + mt * 16 + r0;
            const float vx[2] = {acc[mt][nt][0] + bx, acc[mt][nt][2] + bx};
            const float vy[2] = {acc[mt][nt][1] + by, acc[mt][nt][3] + by};
            if (MODE == 1) {
                *(float2*)(Cout + (size_t)rowa * KDIM + col)       = make_float2(vx[0], vy[0]);
                *(float2*)(Cout + (size_t)(rowa + 8) * KDIM + col) = make_float2(vx[1], vy[1]);
            } else {
                cs[nt][0] += vx[0] + vx[1];
                cs[nt][1] += vy[0] + vy[1];
#pragma unroll
                for (int rr = 0; rr < 2; rr++) {
                    const int row = rowa + rr * 8;
                    if (kind == 0)
                        *(float2*)(g_qkv + (size_t)row * 512 + col) = make_float2(vx[rr], vy[rr]);
                    if (kind >= 1) {
                        const int cc = col - ((kind == 1) ? 256 : 512);
                        const int hh = cc >> 5, w = (cc & 31) >> 1;
                        const int p = row >> 8, j = row & 255;
                        unsigned char* tb = ((kind == 1) ? g_Ktb : g_Vtb)
                                          + ((size_t)(p * 8 + hh)) * 32768 + (size_t)j * 128;
                        const int sw = j & 7;
                        const int hib = (((w >> 2) ^ sw) * 16) + (w & 3) * 4;
                        *(uint32_t*)(tb + hib) = pack_h2(__float2half_rn(vx[rr]),
                                                         __float2half_rn(vy[rr]));
                    }
                    if (kind == 2) {
                        const int p = row >> 8, pix = row & 255;
                        const int gy = (p / 7) * 16 + (pix >> 4);
                        const int gx = (p % 7) * 16 + (pix & 15);
                        *(float2*)(g_vimg + ((size_t)(gy * IMG + gx)) * 256 + (col - 512))
                            = make_float2(vx[rr], vy[rr]);
                    }
                }
            }
        }
    }

    if (MODE == 0 && kind < 2) {
#pragma unroll
        for (int nt = 0; nt < 8; nt++) {
            float a = cs[nt][0], b = cs[nt][1];
#pragma unroll
            for (int o = 4; o < 32; o <<= 1) {
                a += __shfl_xor_sync(0xffffffffu, a, o);
                b += __shfl_xor_sync(0xffffffffu, b, o);
            }
            if (lane < 4) {
                sWsum[wid][nt * 8 + c0]     = a;
                sWsum[wid][nt * 8 + c0 + 1] = b;
            }
        }
        __syncthreads();
        if (tid < 128) {
            const int nwsel = tid >> 6, col = tid & 63;
            const float s = sWsum[nwsel][col] + sWsum[2 + nwsel][col]
                          + sWsum[4 + nwsel][col] + sWsum[6 + nwsel][col];
            g_part2[m0 >> 7][n0 + nwsel * 64 + col] = s;
        }
    }
}

// ---------------------------------------------------------------------------
// Routing: block p: q-row sum, logits vs all k-row sums, top-4.
// ---------------------------------------------------------------------------
__global__ __launch_bounds__(256) void route_k() {
    __shared__ float sq[256];
    __shared__ float slog[64];
    const int p = blockIdx.x, tid = threadIdx.x, wrp = tid >> 5, lane = tid & 31;

    sq[tid] = g_part2[2 * p][tid] + g_part2[2 * p + 1][tid];
    __syncthreads();

    const float q0 = sq[lane * 8 + 0], q1 = sq[lane * 8 + 1];
    const float q2 = sq[lane * 8 + 2], q3 = sq[lane * 8 + 3];
    const float q4 = sq[lane * 8 + 4], q5 = sq[lane * 8 + 5];
    const float q6 = sq[lane * 8 + 6], q7 = sq[lane * 8 + 7];
    for (int j = wrp; j < P2; j += 8) {
        const float4 a0 = *(const float4*)&g_part2[2 * j][256 + lane * 8];
        const float4 a1 = *(const float4*)&g_part2[2 * j][256 + lane * 8 + 4];
        const float4 b0 = *(const float4*)&g_part2[2 * j + 1][256 + lane * 8];
        const float4 b1 = *(const float4*)&g_part2[2 * j + 1][256 + lane * 8 + 4];
        float d = q0 * (a0.x + b0.x) + q1 * (a0.y + b0.y)
                + q2 * (a0.z + b0.z) + q3 * (a0.w + b0.w)
                + q4 * (a1.x + b1.x) + q5 * (a1.y + b1.y)
                + q6 * (a1.z + b1.z) + q7 * (a1.w + b1.w);
#pragma unroll
        for (int o = 16; o > 0; o >>= 1) d += __shfl_xor_sync(0xffffffffu, d, o);
        if (lane == 0) slog[j] = d;
    }
    __syncthreads();

    if (tid == 0) {
        float bv0 = -1e30f, bv1 = -1e30f, bv2 = -1e30f, bv3 = -1e30f;
        int   bi0 = 0, bi1 = 0, bi2 = 0, bi3 = 0;
        for (int j = 0; j < P2; j++) {
            const float s = slog[j];
            if (s > bv3) {
                if (s > bv0)      { bv3=bv2;bi3=bi2; bv2=bv1;bi2=bi1; bv1=bv0;bi1=bi0; bv0=s;bi0=j; }
                else if (s > bv1) { bv3=bv2;bi3=bi2; bv2=bv1;bi2=bi1; bv1=s;bi1=j; }
                else if (s > bv2) { bv3=bv2;bi3=bi2; bv2=s;bi2=j; }
                else              { bv3=s;bi3=j; }
            }
        }
        g_top[p * 4 + 0] = bi0; g_top[p * 4 + 1] = bi1;
        g_top[p * 4 + 2] = bi2; g_top[p * 4 + 3] = bi3;
    }
}

// ---------------------------------------------------------------------------
// Attention v7 (validated R13): grid (49, 8, 2); 128 threads, cp.async K/V.
// ---------------------------------------------------------------------------
__global__ __launch_bounds__(128) void attn_mma() {
    __shared__ __align__(128) unsigned char Kt[16384];
    __shared__ __align__(128) unsigned char Vt[16384];
    __shared__ int sidx[4];
    const int p = blockIdx.x, h = blockIdx.y, qz = blockIdx.z;
    const int tid = threadIdx.x, wid = tid >> 5, lane = tid & 31;
    if (tid < 4) sidx[tid] = g_top[p * 4 + tid];

    const uint32_t sK = smem_u32(Kt), sV = smem_u32(Vt);
    const int r  = lane >> 2;
    const int c2 = (lane & 3) * 2;

    int loff[2];
#pragma unroll
    for (int i = 0; i < 2; i++) {
        const int t = tid + i * 128;
        const int lrow = t >> 2, lc = t & 3;
        loff[i] = lrow * 128 + ((lc ^ (lrow & 7)) * 16);
    }

    uint32_t qh[2][2][4];
    {
        const float* qb = g_qkv + ((size_t)p * W2 + qz * 128 + wid * 32) * 512 + h * 32;
#pragma unroll
        for (int mt = 0; mt < 2; mt++)
#pragma unroll
            for (int ks = 0; ks < 2; ks++)
#pragma unroll
                for (int idx = 0; idx < 4; idx++) {
                    const int row = mt * 16 + r + (idx & 1) * 8;
                    const int col = ks * 16 + (idx >> 1) * 8 + c2;
                    const float2 v = *(const float2*)(qb + (size_t)row * 512 + col);
                    qh[mt][ks][idx] = pack_h2(__float2half_rn(v.x * QSCALE),
                                              __float2half_rn(v.y * QSCALE));
                }
    }
    __syncthreads();
    const int s0 = sidx[0], s1 = sidx[1], s2 = sidx[2], s3 = sidx[3];

    float lacc[2][4];
    float outA[2][4][4];
#pragma unroll
    for (int mt = 0; mt < 2; mt++) {
#pragma unroll
        for (int j = 0; j < 4; j++) lacc[mt][j] = 0.f;
#pragma unroll
        for (int ct = 0; ct < 4; ct++)
#pragma unroll
            for (int j = 0; j < 4; j++) outA[mt][ct][j] = 0.f;
    }
    const uint32_t ONE2 = 0x3C003C00u;
    const uint32_t bones[2] = {ONE2, ONE2};

    {
        const size_t b = ((size_t)(s0 * 8 + h)) * 32768;
#pragma unroll
        for (int i = 0; i < 2; i++) {
            CP_ASYNC16(sK + loff[i], g_Ktb + b + loff[i]);
            CP_ASYNC16(sV + loff[i], g_Vtb + b + loff[i]);
        }
        CP_COMMIT();
        CP_WAIT0();
    }
    __syncthreads();

#pragma unroll 1
    for (int ch = 0; ch < 16; ch++) {
        const int cb = (ch & 1) * 8192;
        const bool more = (ch + 1 < 16);
        if (more) {
            const int nc = ch + 1, t = nc >> 2;
            const int sw = (t == 0) ? s0 : (t == 1) ? s1 : (t == 2) ? s2 : s3;
            const size_t b = ((size_t)(sw * 8 + h)) * 32768 + (size_t)(nc & 3) * 8192;
            const int nb = cb ^ 8192;
#pragma unroll
            for (int i = 0; i < 2; i++) {
                CP_ASYNC16(sK + nb + loff[i], g_Ktb + b + loff[i]);
                CP_ASYNC16(sV + nb + loff[i], g_Vtb + b + loff[i]);
            }
            CP_COMMIT();
        }

        float s[2][8][4];
#pragma unroll
        for (int mt = 0; mt < 2; mt++)
#pragma unroll
            for (int nt = 0; nt < 8; nt++)
#pragma unroll
                for (int j = 0; j < 4; j++) s[mt][nt][j] = 0.f;

#pragma unroll
        for (int ks = 0; ks < 2; ks++) {
#pragma unroll
            for (int np = 0; np < 4; np++) {
                const int row = np * 16 + (lane & 7) + ((lane >> 4) << 3);
                const int chk = ks * 2 + ((lane >> 3) & 1);
                uint32_t b0, b1, b2, b3;
                ldsm_x4(b0, b1, b2, b3, sK + cb + row * 128 + ((chk ^ (row & 7)) * 16));
                uint32_t f0[2] = {b0, b1}, f1[2] = {b2, b3};
#pragma unroll
                for (int mt = 0; mt < 2; mt++) {
                    mma16816h(s[mt][np * 2],     qh[mt][ks], f0);
                    mma16816h(s[mt][np * 2 + 1], qh[mt][ks], f1);
                }
            }
        }

        uint32_t pp[2][8][2];
#pragma unroll
        for (int mt = 0; mt < 2; mt++)
#pragma unroll
            for (int nt = 0; nt < 8; nt++) {
                pp[mt][nt][0] = exp2_h2(s[mt][nt][1], s[mt][nt][0]);
                pp[mt][nt][1] = exp2_h2(s[mt][nt][3], s[mt][nt][2]);
            }

#pragma unroll
        for (int ks = 0; ks < 4; ks++) {
            uint32_t bV[4][2];
#pragma unroll
            for (int cp = 0; cp < 2; cp++) {
                const int row = ks * 16 + (lane & 15);
                const int chk = cp * 2 + (lane >> 4);
                uint32_t b0, b1, b2, b3;
                ldsm_x4_t(b0, b1, b2, b3, sV + cb + row * 128 + ((chk ^ (row & 7)) * 16));
                bV[cp * 2][0] = b0; bV[cp * 2][1] = b1;
                bV[cp * 2 + 1][0] = b2; bV[cp * 2 + 1][1] = b3;
            }
#pragma unroll
            for (int mt = 0; mt < 2; mt++) {
                uint32_t aP[4];
                aP[0] = pp[mt][2 * ks][0];
                aP[1] = pp[mt][2 * ks][1];
                aP[2] = pp[mt][2 * ks + 1][0];
                aP[3] = pp[mt][2 * ks + 1][1];
                mma16816h(lacc[mt], aP, bones);
#pragma unroll
                for (int ct = 0; ct < 4; ct++)
                    mma16816h(outA[mt][ct], aP, bV[ct]);
            }
        }

        if (more) CP_WAIT0();
        __syncthreads();
    }

    const int wy = p / 7, wx = p % 7;
#pragma unroll
    for (int mt = 0; mt < 2; mt++)
#pragma unroll
        for (int hf = 0; hf < 2; hf++) {
            const float inv = 1.f / lacc[mt][hf * 2];
            const int q = qz * 128 + wid * 32 + mt * 16 + r + hf * 8;
            const int gy = wy * 16 + (q >> 4), gx = wx * 16 + (q & 15);
            float* o = g_y + ((size_t)(gy * IMG + gx)) * 256 + h * 32;
#pragma unroll
            for (int ct = 0; ct < 4; ct++) {
                float2 v = {outA[mt][ct][hf * 2] * inv, outA[mt][ct][hf * 2 + 1] * inv};
                *(float2*)(o + ct * 8 + c2) = v;
            }
        }
}

// ---------------------------------------------------------------------------
// LePE + add attn; emit fp16 hi rows for out-gemm
// ---------------------------------------------------------------------------
__global__ __launch_bounds__(256) void lepe_k(const float* __restrict__ lw,
                                              const float* __restrict__ lb) {
    const int pix = blockIdx.x;
    const int c   = threadIdx.x;
    const int y = pix / IMG, x = pix % IMG;
    float sum = lb[c];
#pragma unroll
    for (int dy = -1; dy <= 1; dy++) {
        const int yy = y + dy;
        if (yy < 0 || yy >= IMG) continue;
#pragma unroll
        for (int dx = -1; dx <= 1; dx++) {
            const int xx = x + dx;
            if (xx < 0 || xx >= IMG) continue;
            const float v = g_vimg[((size_t)(yy * IMG + xx)) * 256 + c];
            sum += v * lw[((dy + 1) * 3 + (dx + 1)) * 256 + c];
        }
    }
    const float tot = g_y[(size_t)pix * 256 + c] + sum;
    g_Yp[(size_t)pix * 512 + c] = __float2half_rn(tot);
}

// ---------------------------------------------------------------------------
extern "C" void kernel_launch(void* const* d_in, const int* in_sizes, int n_in,
                              void* d_out, int out_size) {
    const float* x      = (const float*)d_in[0];
    const float* w_qkv  = (const float*)d_in[1];
    const float* b_qkv  = (const float*)d_in[2];
    const float* w_o    = (const float*)d_in[3];
    const float* b_o    = (const float*)d_in[4];
    const float* lepe_w = (const float*)d_in[5];
    const float* lepe_b = (const float*)d_in[6];
    float* out = (float*)d_out;
    (void)in_sizes; (void)n_in; (void)out_size;

    prep_w<<<NQKV, 256>>>(w_qkv, w_o);                                       // 1
    gemm_mma<0><<<dim3(NQKV / 128, MROWS / 128), 256>>>(x, b_qkv, nullptr);  // 2
    route_k<<<P2, 256>>>();                                                  // 3
    attn_mma<<<dim3(P2, 8, 2), 128>>>();                                     // 4 <- ncu
    lepe_k<<<IMG * IMG, 256>>>(lepe_w, lepe_b);                              // 5
    gemm_mma<1><<<dim3(KDIM / 128, MROWS / 128), 256>>>(nullptr, b_o, out);  // 6
}